// round 10
// baseline (speedup 1.0000x reference)
#include <cuda_runtime.h>
#include <cuda_bf16.h>
#include <cstdint>

// Problem constants: B=4, S=1024, D=512, H=8, DH=64
#define RQ   4096
#define R3   12288
#define DD   512
#define NPAIR 32
#define SPLITS 4
#define LN_EPS 1e-5f

// ---------------- scratch ----------------
__device__ float         g_f[3 * RQ * DD];        // fp32 f_q|f_k|f_v
__device__ __nv_bfloat16 g_Ahi[R3 * DD];
__device__ __nv_bfloat16 g_Alo[R3 * DD];
__device__ __nv_bfloat16 g_Bhi[2 * DD * DD];      // W_in^T | W_out^T (hi)
__device__ __nv_bfloat16 g_Blo[2 * DD * DD];
__device__ __nv_bfloat16 g_ghi[RQ * DD];
__device__ __nv_bfloat16 g_glo[RQ * DD];
__device__ float g_hmu[2 * NPAIR * 1024];
__device__ float g_hinvn[2 * NPAIR * 1024];
__device__ float g_hvar[2 * NPAIR * 1024];
__device__ float g_Mpart[NPAIR * SPLITS * 2 * 4096];
__device__ float g_rpart[NPAIR * SPLITS * 64];
__device__ float g_M[NPAIR * 2 * 4096];   // G = K^T V | H = K^T (ikn*V)
__device__ float g_r[NPAIR * 64];
__device__ unsigned int g_cnt[NPAIR];     // wraps to 0 each replay via atomicInc

// ---------------- helpers ----------------
__device__ __forceinline__ uint32_t smem_u32(const void* p) {
    uint32_t a;
    asm("{ .reg .u64 t; cvta.to.shared.u64 t, %1; cvt.u32.u64 %0, t; }" : "=r"(a) : "l"(p));
    return a;
}
__device__ __forceinline__ void cp16(uint32_t dst, const void* src) {
    asm volatile("cp.async.cg.shared.global [%0], [%1], 16;" :: "r"(dst), "l"(src));
}
__device__ __forceinline__ void cp_commit() {
    asm volatile("cp.async.commit_group;");
}
__device__ __forceinline__ void ldsm4(uint32_t& r0, uint32_t& r1, uint32_t& r2, uint32_t& r3,
                                      uint32_t addr) {
    asm volatile("ldmatrix.sync.aligned.m8n8.x4.shared.b16 {%0,%1,%2,%3}, [%4];"
                 : "=r"(r0), "=r"(r1), "=r"(r2), "=r"(r3) : "r"(addr));
}
__device__ __forceinline__ void mma16816(float& c0, float& c1, float& c2, float& c3,
                                         uint32_t a0, uint32_t a1, uint32_t a2, uint32_t a3,
                                         uint32_t b0, uint32_t b1) {
    asm volatile(
        "mma.sync.aligned.m16n8k16.row.col.f32.bf16.bf16.f32 "
        "{%0,%1,%2,%3}, {%4,%5,%6,%7}, {%8,%9}, {%0,%1,%2,%3};"
        : "+f"(c0), "+f"(c1), "+f"(c2), "+f"(c3)
        : "r"(a0), "r"(a1), "r"(a2), "r"(a3), "r"(b0), "r"(b1));
}

// ---------------- 1) merged prep: LN+split | W transpose+split ----------------
__global__ void __launch_bounds__(256) prep(
    const float* __restrict__ q, const float* __restrict__ k,
    const float* __restrict__ v, const float* __restrict__ lng,
    const float* __restrict__ lnb, const float* __restrict__ Win,
    const float* __restrict__ Wout)
{
    __shared__ float ts[32][33];
    if (blockIdx.x < 1536) {
        int gw   = blockIdx.x * 8 + (threadIdx.x >> 5);
        int lane = threadIdx.x & 31;
        const float* src = (gw < RQ) ? q : (gw < 2 * RQ ? k : v);
        int row = gw & (RQ - 1);
        const float4* p = (const float4*)(src + (size_t)row * DD);
        float4 x[4];
        float s = 0.f, ss = 0.f;
#pragma unroll
        for (int i = 0; i < 4; i++) {
            x[i] = p[lane + i * 32];
            s  += x[i].x + x[i].y + x[i].z + x[i].w;
            ss += x[i].x * x[i].x + x[i].y * x[i].y + x[i].z * x[i].z + x[i].w * x[i].w;
        }
#pragma unroll
        for (int o = 16; o; o >>= 1) {
            s  += __shfl_xor_sync(0xffffffffu, s, o);
            ss += __shfl_xor_sync(0xffffffffu, ss, o);
        }
        float mu = s * (1.f / 512.f);
        float rs = rsqrtf(ss * (1.f / 512.f) - mu * mu + LN_EPS);
#pragma unroll
        for (int i = 0; i < 4; i++) {
            float4 gg = ((const float4*)lng)[lane + i * 32];
            float4 bb = ((const float4*)lnb)[lane + i * 32];
            float y0 = (x[i].x - mu) * rs * gg.x + bb.x;
            float y1 = (x[i].y - mu) * rs * gg.y + bb.y;
            float y2 = (x[i].z - mu) * rs * gg.z + bb.z;
            float y3 = (x[i].w - mu) * rs * gg.w + bb.w;
            __nv_bfloat162 h01 = __floats2bfloat162_rn(y0, y1);
            __nv_bfloat162 h23 = __floats2bfloat162_rn(y2, y3);
            __nv_bfloat162 l01 = __floats2bfloat162_rn(y0 - __bfloat162float(h01.x),
                                                       y1 - __bfloat162float(h01.y));
            __nv_bfloat162 l23 = __floats2bfloat162_rn(y2 - __bfloat162float(h23.x),
                                                       y3 - __bfloat162float(h23.y));
            size_t off = (size_t)gw * DD + 4 * (lane + 32 * i);
            uint2 hv, lv;
            hv.x = *(uint32_t*)&h01; hv.y = *(uint32_t*)&h23;
            lv.x = *(uint32_t*)&l01; lv.y = *(uint32_t*)&l23;
            *(uint2*)&g_Ahi[off] = hv;
            *(uint2*)&g_Alo[off] = lv;
        }
    } else {
        int bx = blockIdx.x - 1536;
        int bz = bx >> 8; bx &= 255;
        const float* W = bz ? Wout : Win;
        size_t base = (size_t)bz * DD * DD;
        int k0 = (bx >> 4) * 32, n0 = (bx & 15) * 32;
        int tx = threadIdx.x & 31, ty = threadIdx.x >> 5;
#pragma unroll
        for (int i = 0; i < 4; i++)
            ts[ty + 8 * i][tx] = W[(size_t)(k0 + ty + 8 * i) * DD + n0 + tx];
        __syncthreads();
#pragma unroll
        for (int i = 0; i < 4; i++) {
            int n = n0 + ty + 8 * i, kk = k0 + tx;
            float val = ts[tx][ty + 8 * i];
            __nv_bfloat16 h = __float2bfloat16_rn(val);
            __nv_bfloat16 l = __float2bfloat16_rn(val - __bfloat162float(h));
            g_Bhi[base + (size_t)n * DD + kk] = h;
            g_Blo[base + (size_t)n * DD + kk] = l;
        }
    }
}

// ---------------- 2) HMMA GEMM, bf16x3 (R6-best config) ----------------
#define RS 40                      // smem row stride (bf16)
#define TILE_B (128 * RS * 2)      // 10240 bytes per operand tile
#define BUF_B  (4 * TILE_B)        // Ahi|Alo|Bhi|Blo per buffer
#define GEMM_SMEM (2 * BUF_B)      // 81920 bytes

__global__ void __launch_bounds__(256, 2) gemm_bf3(
    const __nv_bfloat16* __restrict__ Ahi, const __nv_bfloat16* __restrict__ Alo,
    const __nv_bfloat16* __restrict__ Bhi, const __nv_bfloat16* __restrict__ Blo,
    float* __restrict__ C, const float* __restrict__ bias, int mode)
{
    extern __shared__ char smem[];
    uint32_t sb = smem_u32(smem);
    int t = threadIdx.x, wid = t >> 5, lane = t & 31;
    int n0 = blockIdx.x * 128, m0 = blockIdx.y * 128;
    int wm = wid >> 2, wn = wid & 3;

    float acc[4][4][4];
#pragma unroll
    for (int i = 0; i < 4; i++)
#pragma unroll
        for (int j = 0; j < 4; j++)
#pragma unroll
            for (int r = 0; r < 4; r++) acc[i][j][r] = 0.f;

    int r0l = t >> 2, seg = t & 3;

    auto issue = [&](int c, int buf) {
        int k0 = c * 32;
        uint32_t d0 = sb + buf * BUF_B;
#pragma unroll
        for (int i = 0; i < 2; i++) {
            int row = r0l + i * 64;
            uint32_t doff = (row * RS + seg * 8) * 2;
            size_t ga = (size_t)(m0 + row) * DD + k0 + seg * 8;
            size_t gb = (size_t)(n0 + row) * DD + k0 + seg * 8;
            cp16(d0 + doff,              Ahi + ga);
            cp16(d0 + TILE_B + doff,     Alo + ga);
            cp16(d0 + 2 * TILE_B + doff, Bhi + gb);
            cp16(d0 + 3 * TILE_B + doff, Blo + gb);
        }
        cp_commit();
    };

    issue(0, 0);
    int g = lane >> 3, rl = lane & 7;

    for (int c = 0; c < 16; c++) {
        int buf = c & 1;
        if (c < 15) issue(c + 1, buf ^ 1);
        if (c < 15) asm volatile("cp.async.wait_group 1;");
        else        asm volatile("cp.async.wait_group 0;");
        __syncthreads();

        uint32_t aBase = sb + buf * BUF_B;
        uint32_t bBase = aBase + 2 * TILE_B;
#pragma unroll
        for (int h = 0; h < 2; h++) {
            uint32_t aH[4][4], aL[4][4];
#pragma unroll
            for (int it = 0; it < 4; it++) {
                int row = wm * 64 + it * 16 + rl + (g & 1) * 8;
                int kc  = h * 16 + (g & 2) * 4;
                uint32_t ad = aBase + (row * RS + kc) * 2;
                ldsm4(aH[it][0], aH[it][1], aH[it][2], aH[it][3], ad);
                ldsm4(aL[it][0], aL[it][1], aL[it][2], aL[it][3], ad + TILE_B);
            }
            uint32_t bH[4][2], bL[4][2];
#pragma unroll
            for (int jp = 0; jp < 2; jp++) {
                int row = wn * 32 + jp * 16 + rl + (g >> 1) * 8;
                int kc  = h * 16 + (g & 1) * 8;
                uint32_t bd = bBase + (row * RS + kc) * 2;
                ldsm4(bH[2 * jp][0], bH[2 * jp][1], bH[2 * jp + 1][0], bH[2 * jp + 1][1], bd);
                ldsm4(bL[2 * jp][0], bL[2 * jp][1], bL[2 * jp + 1][0], bL[2 * jp + 1][1],
                      bd + TILE_B);
            }
#pragma unroll
            for (int it = 0; it < 4; it++)
#pragma unroll
                for (int jt = 0; jt < 4; jt++) {
                    mma16816(acc[it][jt][0], acc[it][jt][1], acc[it][jt][2], acc[it][jt][3],
                             aH[it][0], aH[it][1], aH[it][2], aH[it][3],
                             bH[jt][0], bH[jt][1]);
                    mma16816(acc[it][jt][0], acc[it][jt][1], acc[it][jt][2], acc[it][jt][3],
                             aH[it][0], aH[it][1], aH[it][2], aH[it][3],
                             bL[jt][0], bL[jt][1]);
                    mma16816(acc[it][jt][0], acc[it][jt][1], acc[it][jt][2], acc[it][jt][3],
                             aL[it][0], aL[it][1], aL[it][2], aL[it][3],
                             bH[jt][0], bH[jt][1]);
                }
        }
        __syncthreads();
    }

    // ---------------- epilogue ----------------
    int rr = lane >> 2, cc = 2 * (lane & 3);
#pragma unroll
    for (int it = 0; it < 4; it++) {
        int row = m0 + wm * 64 + it * 16 + rr;
#pragma unroll
        for (int jt = 0; jt < 4; jt++) {
            int col = n0 + wn * 32 + jt * 8 + cc;
            if (mode == 0) {
                *(float2*)&C[(size_t)row * DD + col] =
                    make_float2(acc[it][jt][0], acc[it][jt][1]);
                *(float2*)&C[(size_t)(row + 8) * DD + col] =
                    make_float2(acc[it][jt][2], acc[it][jt][3]);
            } else {
                float2 bb = *(const float2*)&bias[col];
                *(float2*)&C[(size_t)row * DD + col] =
                    make_float2(acc[it][jt][0] + bb.x, acc[it][jt][1] + bb.y);
                *(float2*)&C[(size_t)(row + 8) * DD + col] =
                    make_float2(acc[it][jt][2] + bb.x, acc[it][jt][3] + bb.y);
            }
        }
    }

    // fused per-head row stats (mode 0, fq/fk rows only)
    if (mode == 0 && m0 < 2 * RQ) {
        float* sred = (float*)smem;   // [wn][128 rows][2] = 4KB
#pragma unroll
        for (int it = 0; it < 4; it++) {
#pragma unroll
            for (int sub = 0; sub < 2; sub++) {
                float s = 0.f, ss = 0.f;
#pragma unroll
                for (int jt = 0; jt < 4; jt++) {
                    float v0 = acc[it][jt][2 * sub], v1 = acc[it][jt][2 * sub + 1];
                    s  += v0 + v1;
                    ss += v0 * v0 + v1 * v1;
                }
#pragma unroll
                for (int o = 1; o <= 2; o <<= 1) {
                    s  += __shfl_xor_sync(0xffffffffu, s, o);
                    ss += __shfl_xor_sync(0xffffffffu, ss, o);
                }
                if ((lane & 3) == 0) {
                    int lr = wm * 64 + it * 16 + rr + sub * 8;
                    sred[(wn * 128 + lr) * 2 + 0] = s;
                    sred[(wn * 128 + lr) * 2 + 1] = ss;
                }
            }
        }
        __syncthreads();
        int hp = t >> 7, lr = t & 127;
        float s  = sred[((2 * hp) * 128 + lr) * 2 + 0] +
                   sred[((2 * hp + 1) * 128 + lr) * 2 + 0];
        float ss = sred[((2 * hp) * 128 + lr) * 2 + 1] +
                   sred[((2 * hp + 1) * 128 + lr) * 2 + 1];
        int grow = m0 + lr;
        int tensor = grow >> 12;
        int b = (grow >> 10) & 3, m = grow & 1023;
        int h = (n0 >> 6) + hp;
        int idx = tensor * 32768 + (h * 4 + b) * 1024 + m;
        g_hmu[idx]   = s * (1.f / 64.f);
        g_hinvn[idx] = rsqrtf(ss);
        g_hvar[idx]  = (ss - s * s * (1.f / 64.f)) * (1.f / 63.f);
    }
}

// ---------------- 3) G/H/r partials + fused last-block reduction ----------------
__global__ void __launch_bounds__(256, 4) macc()
{
    __shared__ float Ks[2][32][64];
    __shared__ float Vs[2][32][64];
    __shared__ float sikn[256], skv[256];
    __shared__ unsigned int s_last;
    int t = threadIdx.x;
    int pair  = blockIdx.x >> 2;
    int split = blockIdx.x & 3;
    int h = pair >> 2, b = pair & 3;
    const float* fk = g_f + (size_t)RQ * DD     + (size_t)(b * 1024) * DD + h * 64;
    const float* fv = g_f + (size_t)2 * RQ * DD + (size_t)(b * 1024) * DD + h * 64;
    int tx = t & 15, ty = t >> 4;
    int d0 = ty * 4, e0 = tx * 4;
    float G[4][4] = {}, Hm[4][4] = {}, ra[4] = {};
    int mbase0 = split * 256;
    uint32_t sK = smem_u32(Ks), sV = smem_u32(Vs);

    auto issue = [&](int c) {
        int mbase = mbase0 + c * 32;
        uint32_t bufo = (uint32_t)(c & 1) * (32 * 64 * 4);
#pragma unroll
        for (int i = 0; i < 2; i++) {
            int u = t + i * 256;
            int rr = u >> 4, c4 = (u & 15) * 4;
            uint32_t off = bufo + (rr * 64 + c4) * 4;
            cp16(sK + off, fk + (size_t)(mbase + rr) * DD + c4);
            cp16(sV + off, fv + (size_t)(mbase + rr) * DD + c4);
        }
        cp_commit();
    };

    issue(0);
    {
        int idx = 32768 + pair * 1024 + mbase0 + t;
        sikn[t] = g_hinvn[idx];
        skv[t]  = g_hvar[idx];
    }

    for (int c = 0; c < 8; c++) {
        if (c < 7) issue(c + 1);
        if (c < 7) asm volatile("cp.async.wait_group 1;");
        else       asm volatile("cp.async.wait_group 0;");
        __syncthreads();
        int buf = c & 1;
#pragma unroll 8
        for (int mm = 0; mm < 32; mm++) {
            float ikn = sikn[c * 32 + mm];
            float4 kk4 = *(float4*)&Ks[buf][mm][d0];
            float4 vv4 = *(float4*)&Vs[buf][mm][e0];
            float kk[4] = {kk4.x, kk4.y, kk4.z, kk4.w};
            float vv[4] = {vv4.x, vv4.y, vv4.z, vv4.w};
            float vn[4] = {vv4.x * ikn, vv4.y * ikn, vv4.z * ikn, vv4.w * ikn};
#pragma unroll
            for (int i = 0; i < 4; i++)
#pragma unroll
                for (int j = 0; j < 4; j++) {
                    G[i][j]  += kk[i] * vv[j];
                    Hm[i][j] += kk[i] * vn[j];
                }
        }
        if (ty == 0) {
#pragma unroll 8
            for (int mm = 0; mm < 32; mm++) {
                float kvv = skv[c * 32 + mm];
#pragma unroll
                for (int j = 0; j < 4; j++) ra[j] += kvv * Vs[buf][mm][e0 + j];
            }
        }
        __syncthreads();
    }
    float* mp = g_Mpart + (size_t)blockIdx.x * 8192;
#pragma unroll
    for (int i = 0; i < 4; i++)
#pragma unroll
        for (int j = 0; j < 4; j++) {
            mp[(d0 + i) * 64 + e0 + j]        = G[i][j];
            mp[4096 + (d0 + i) * 64 + e0 + j] = Hm[i][j];
        }
    if (ty == 0)
#pragma unroll
        for (int j = 0; j < 4; j++) g_rpart[blockIdx.x * 64 + e0 + j] = ra[j];

    // last block of this pair performs the cross-split reduction
    __threadfence();
    __syncthreads();
    if (t == 0) s_last = atomicInc(&g_cnt[pair], SPLITS - 1);   // wraps -> self-reset
    __syncthreads();
    if (s_last == SPLITS - 1) {
        const float* p0 = g_Mpart + (size_t)(pair * SPLITS) * 8192;
        for (int idx = t; idx < 8192; idx += 256) {
            float s = 0.f;
#pragma unroll
            for (int sp = 0; sp < SPLITS; sp++) s += __ldcg(p0 + (size_t)sp * 8192 + idx);
            g_M[(size_t)pair * 8192 + idx] = s;
        }
        if (t < 64) {
            float s = 0.f;
#pragma unroll
            for (int sp = 0; sp < SPLITS; sp++)
                s += __ldcg(&g_rpart[(pair * SPLITS + sp) * 64 + t]);
            g_r[pair * 64 + t] = s;
        }
    }
}

// ---------------- 4) apply, emits bf16 hi/lo ----------------
__global__ void __launch_bounds__(256) apply_k(const float* __restrict__ cov_w,
                                               const float* __restrict__ var_w)
{
    __shared__ float Ms[2 * 4096];
    __shared__ float qs[64][34];
    __shared__ float scs1[64], srs[64];
    __shared__ float sbeta[32], sgamma[32], smual[32];
    int t = threadIdx.x;
    int pair  = blockIdx.x >> 5;
    int ntile = blockIdx.x & 31;
    int h = pair >> 2, b = pair & 3;
    float cw = cov_w[0], vw = var_w[0];
    float w3 = 1.f - cw - vw;
    float alpha = cw * (1.f / 64.f);

    const float* msrc = g_M + (size_t)pair * 8192;
#pragma unroll
    for (int i = 0; i < 8; i++) {
        int fi = t + i * 256;
        ((float4*)Ms)[fi] = ((const float4*)msrc)[fi];
    }
    int n0 = ntile * 32;
    const float* fq = g_f + (size_t)(b * 1024 + n0) * DD + h * 64;
#pragma unroll
    for (int i = 0; i < 2; i++) {
        int fi = t + i * 256;
        int rr = fi >> 4, c4 = (fi & 15) * 4;
        float4 x = *(const float4*)(fq + (size_t)rr * DD + c4);
        qs[c4 + 0][rr] = x.x; qs[c4 + 1][rr] = x.y;
        qs[c4 + 2][rr] = x.z; qs[c4 + 3][rr] = x.w;
    }
    if (t < 32) {
        int idx = pair * 1024 + n0 + t;
        float mu = g_hmu[idx], invn = g_hinvn[idx], var = g_hvar[idx];
        sbeta[t]  = w3 * invn;
        sgamma[t] = vw * (1.f / 64.f) * var;
        smual[t]  = alpha * mu;
    }
    if (t < 64) srs[t] = g_r[pair * 64 + t];
    __syncthreads();
    if (t < 64) {
        float s = 0.f;
#pragma unroll
        for (int d = 0; d < 64; d++) s += Ms[d * 64 + t];
        scs1[t] = s;
    }
    __syncthreads();

    int tx = t & 15, ty = t >> 4;
    int e0 = tx * 4, r0 = ty * 2;
    float t1[2][4] = {}, t2[2][4] = {};
#pragma unroll 8
    for (int d = 0; d < 64; d++) {
        float4 m1 = *(float4*)&Ms[d * 64 + e0];
        float4 m2 = *(float4*)&Ms[4096 + d * 64 + e0];
        float q0 = qs[d][r0], q1 = qs[d][r0 + 1];
        t1[0][0] += q0 * m1.x; t1[0][1] += q0 * m1.y; t1[0][2] += q0 * m1.z; t1[0][3] += q0 * m1.w;
        t1[1][0] += q1 * m1.x; t1[1][1] += q1 * m1.y; t1[1][2] += q1 * m1.z; t1[1][3] += q1 * m1.w;
        t2[0][0] += q0 * m2.x; t2[0][1] += q0 * m2.y; t2[0][2] += q0 * m2.z; t2[0][3] += q0 * m2.w;
        t2[1][0] += q1 * m2.x; t2[1][1] += q1 * m2.y; t2[1][2] += q1 * m2.z; t2[1][3] += q1 * m2.w;
    }
#pragma unroll
    for (int i = 0; i < 2; i++) {
        int row = r0 + i;
        int n = n0 + row;
        float beta = sbeta[row], gamma = sgamma[row], mal = smual[row];
        float o0 = alpha * t1[i][0] - mal * scs1[e0 + 0] + beta * t2[i][0] + gamma * srs[e0 + 0];
        float o1 = alpha * t1[i][1] - mal * scs1[e0 + 1] + beta * t2[i][1] + gamma * srs[e0 + 1];
        float o2 = alpha * t1[i][2] - mal * scs1[e0 + 2] + beta * t2[i][2] + gamma * srs[e0 + 2];
        float o3 = alpha * t1[i][3] - mal * scs1[e0 + 3] + beta * t2[i][3] + gamma * srs[e0 + 3];
        __nv_bfloat162 h01 = __floats2bfloat162_rn(o0, o1);
        __nv_bfloat162 h23 = __floats2bfloat162_rn(o2, o3);
        __nv_bfloat162 l01 = __floats2bfloat162_rn(o0 - __bfloat162float(h01.x),
                                                   o1 - __bfloat162float(h01.y));
        __nv_bfloat162 l23 = __floats2bfloat162_rn(o2 - __bfloat162float(h23.x),
                                                   o3 - __bfloat162float(h23.y));
        size_t off = (size_t)(b * 1024 + n) * DD + h * 64 + e0;
        uint2 hv, lv;
        hv.x = *(uint32_t*)&h01; hv.y = *(uint32_t*)&h23;
        lv.x = *(uint32_t*)&l01; lv.y = *(uint32_t*)&l23;
        *(uint2*)&g_ghi[off] = hv;
        *(uint2*)&g_glo[off] = lv;
    }
}

// ---------------- launch ----------------
extern "C" void kernel_launch(void* const* d_in, const int* in_sizes, int n_in,
                              void* d_out, int out_size)
{
    const float* q     = (const float*)d_in[0];
    const float* k     = (const float*)d_in[1];
    const float* v     = (const float*)d_in[2];
    const float* ln_g  = (const float*)d_in[3];
    const float* ln_b  = (const float*)d_in[4];
    const float* W_in  = (const float*)d_in[5];
    const float* W_out = (const float*)d_in[6];
    const float* b_out = (const float*)d_in[7];
    const float* cov_w = (const float*)d_in[8];
    const float* var_w = (const float*)d_in[9];
    float* out = (float*)d_out;

    cudaFuncSetAttribute(gemm_bf3, cudaFuncAttributeMaxDynamicSharedMemorySize, GEMM_SMEM);

    __nv_bfloat16 *Ahi, *Alo, *Bhi, *Blo, *ghi, *glo;
    float* f;
    cudaGetSymbolAddress((void**)&Ahi, g_Ahi);
    cudaGetSymbolAddress((void**)&Alo, g_Alo);
    cudaGetSymbolAddress((void**)&Bhi, g_Bhi);
    cudaGetSymbolAddress((void**)&Blo, g_Blo);
    cudaGetSymbolAddress((void**)&ghi, g_ghi);
    cudaGetSymbolAddress((void**)&glo, g_glo);
    cudaGetSymbolAddress((void**)&f,   g_f);

    prep<<<1536 + 512, 256>>>(q, k, v, ln_g, ln_b, W_in, W_out);
    gemm_bf3<<<dim3(4, 96), 256, GEMM_SMEM>>>(Ahi, Alo, Bhi, Blo, f, nullptr, 0);
    macc<<<NPAIR * SPLITS, 256>>>();
    apply_k<<<NPAIR * 32, 256>>>(cov_w, var_w);
    gemm_bf3<<<dim3(4, 32), 256, GEMM_SMEM>>>(ghi, glo, Bhi + DD * DD, Blo + DD * DD,
                                              out, b_out, 1);
}

// round 11
// speedup vs baseline: 1.0981x; 1.0981x over previous
#include <cuda_runtime.h>
#include <cuda_bf16.h>
#include <cstdint>

// Problem constants: B=4, S=1024, D=512, H=8, DH=64
#define RQ   4096
#define R3   12288
#define DD   512
#define NPAIR 32
#define SPLITS 4
#define LN_EPS 1e-5f

// ---------------- scratch ----------------
__device__ float         g_f[3 * RQ * DD];        // fp32 f_q|f_k|f_v
__device__ __nv_bfloat16 g_Ahi[R3 * DD];
__device__ __nv_bfloat16 g_Alo[R3 * DD];
__device__ __nv_bfloat16 g_Bhi[2 * DD * DD];      // W_in^T | W_out^T (hi)
__device__ __nv_bfloat16 g_Blo[2 * DD * DD];
__device__ __nv_bfloat16 g_ghi[RQ * DD];
__device__ __nv_bfloat16 g_glo[RQ * DD];
__device__ float g_hmu[2 * NPAIR * 1024];
__device__ float g_hinvn[2 * NPAIR * 1024];
__device__ float g_hvar[2 * NPAIR * 1024];
__device__ float g_Mpart[NPAIR * SPLITS * 2 * 4096];
__device__ float g_rpart[NPAIR * SPLITS * 64];
__device__ float g_M[NPAIR * 2 * 4096];   // G = K^T V | H = K^T (ikn*V)
__device__ float g_r[NPAIR * 64];

// ---------------- helpers ----------------
__device__ __forceinline__ uint32_t smem_u32(const void* p) {
    uint32_t a;
    asm("{ .reg .u64 t; cvta.to.shared.u64 t, %1; cvt.u32.u64 %0, t; }" : "=r"(a) : "l"(p));
    return a;
}
__device__ __forceinline__ void cp16(uint32_t dst, const void* src) {
    asm volatile("cp.async.cg.shared.global [%0], [%1], 16;" :: "r"(dst), "l"(src));
}
__device__ __forceinline__ void cp_commit() {
    asm volatile("cp.async.commit_group;");
}
__device__ __forceinline__ void ldsm4(uint32_t& r0, uint32_t& r1, uint32_t& r2, uint32_t& r3,
                                      uint32_t addr) {
    asm volatile("ldmatrix.sync.aligned.m8n8.x4.shared.b16 {%0,%1,%2,%3}, [%4];"
                 : "=r"(r0), "=r"(r1), "=r"(r2), "=r"(r3) : "r"(addr));
}
__device__ __forceinline__ void mma16816(float& c0, float& c1, float& c2, float& c3,
                                         uint32_t a0, uint32_t a1, uint32_t a2, uint32_t a3,
                                         uint32_t b0, uint32_t b1) {
    asm volatile(
        "mma.sync.aligned.m16n8k16.row.col.f32.bf16.bf16.f32 "
        "{%0,%1,%2,%3}, {%4,%5,%6,%7}, {%8,%9}, {%0,%1,%2,%3};"
        : "+f"(c0), "+f"(c1), "+f"(c2), "+f"(c3)
        : "r"(a0), "r"(a1), "r"(a2), "r"(a3), "r"(b0), "r"(b1));
}

// ---------------- 1) merged prep: LN+split | W transpose+split ----------------
__global__ void __launch_bounds__(256) prep(
    const float* __restrict__ q, const float* __restrict__ k,
    const float* __restrict__ v, const float* __restrict__ lng,
    const float* __restrict__ lnb, const float* __restrict__ Win,
    const float* __restrict__ Wout)
{
    __shared__ float ts[32][33];
    if (blockIdx.x < 1536) {
        int gw   = blockIdx.x * 8 + (threadIdx.x >> 5);
        int lane = threadIdx.x & 31;
        const float* src = (gw < RQ) ? q : (gw < 2 * RQ ? k : v);
        int row = gw & (RQ - 1);
        const float4* p = (const float4*)(src + (size_t)row * DD);
        float4 x[4];
        float s = 0.f, ss = 0.f;
#pragma unroll
        for (int i = 0; i < 4; i++) {
            x[i] = p[lane + i * 32];
            s  += x[i].x + x[i].y + x[i].z + x[i].w;
            ss += x[i].x * x[i].x + x[i].y * x[i].y + x[i].z * x[i].z + x[i].w * x[i].w;
        }
#pragma unroll
        for (int o = 16; o; o >>= 1) {
            s  += __shfl_xor_sync(0xffffffffu, s, o);
            ss += __shfl_xor_sync(0xffffffffu, ss, o);
        }
        float mu = s * (1.f / 512.f);
        float rs = rsqrtf(ss * (1.f / 512.f) - mu * mu + LN_EPS);
#pragma unroll
        for (int i = 0; i < 4; i++) {
            float4 gg = ((const float4*)lng)[lane + i * 32];
            float4 bb = ((const float4*)lnb)[lane + i * 32];
            float y0 = (x[i].x - mu) * rs * gg.x + bb.x;
            float y1 = (x[i].y - mu) * rs * gg.y + bb.y;
            float y2 = (x[i].z - mu) * rs * gg.z + bb.z;
            float y3 = (x[i].w - mu) * rs * gg.w + bb.w;
            __nv_bfloat162 h01 = __floats2bfloat162_rn(y0, y1);
            __nv_bfloat162 h23 = __floats2bfloat162_rn(y2, y3);
            __nv_bfloat162 l01 = __floats2bfloat162_rn(y0 - __bfloat162float(h01.x),
                                                       y1 - __bfloat162float(h01.y));
            __nv_bfloat162 l23 = __floats2bfloat162_rn(y2 - __bfloat162float(h23.x),
                                                       y3 - __bfloat162float(h23.y));
            size_t off = (size_t)gw * DD + 4 * (lane + 32 * i);
            uint2 hv, lv;
            hv.x = *(uint32_t*)&h01; hv.y = *(uint32_t*)&h23;
            lv.x = *(uint32_t*)&l01; lv.y = *(uint32_t*)&l23;
            *(uint2*)&g_Ahi[off] = hv;
            *(uint2*)&g_Alo[off] = lv;
        }
    } else {
        int bx = blockIdx.x - 1536;
        int bz = bx >> 8; bx &= 255;
        const float* W = bz ? Wout : Win;
        size_t base = (size_t)bz * DD * DD;
        int k0 = (bx >> 4) * 32, n0 = (bx & 15) * 32;
        int tx = threadIdx.x & 31, ty = threadIdx.x >> 5;
#pragma unroll
        for (int i = 0; i < 4; i++)
            ts[ty + 8 * i][tx] = W[(size_t)(k0 + ty + 8 * i) * DD + n0 + tx];
        __syncthreads();
#pragma unroll
        for (int i = 0; i < 4; i++) {
            int n = n0 + ty + 8 * i, kk = k0 + tx;
            float val = ts[tx][ty + 8 * i];
            __nv_bfloat16 h = __float2bfloat16_rn(val);
            __nv_bfloat16 l = __float2bfloat16_rn(val - __bfloat162float(h));
            g_Bhi[base + (size_t)n * DD + kk] = h;
            g_Blo[base + (size_t)n * DD + kk] = l;
        }
    }
}

// ---------------- 2) HMMA GEMM, bf16x3 (R6-best config) ----------------
#define RS 40                      // smem row stride (bf16)
#define TILE_B (128 * RS * 2)      // 10240 bytes per operand tile
#define BUF_B  (4 * TILE_B)        // Ahi|Alo|Bhi|Blo per buffer
#define GEMM_SMEM (2 * BUF_B)      // 81920 bytes

__global__ void __launch_bounds__(256, 2) gemm_bf3(
    const __nv_bfloat16* __restrict__ Ahi, const __nv_bfloat16* __restrict__ Alo,
    const __nv_bfloat16* __restrict__ Bhi, const __nv_bfloat16* __restrict__ Blo,
    float* __restrict__ C, const float* __restrict__ bias, int mode)
{
    extern __shared__ char smem[];
    uint32_t sb = smem_u32(smem);
    int t = threadIdx.x, wid = t >> 5, lane = t & 31;
    int n0 = blockIdx.x * 128, m0 = blockIdx.y * 128;
    int wm = wid >> 2, wn = wid & 3;

    float acc[4][4][4];
#pragma unroll
    for (int i = 0; i < 4; i++)
#pragma unroll
        for (int j = 0; j < 4; j++)
#pragma unroll
            for (int r = 0; r < 4; r++) acc[i][j][r] = 0.f;

    int r0l = t >> 2, seg = t & 3;

    auto issue = [&](int c, int buf) {
        int k0 = c * 32;
        uint32_t d0 = sb + buf * BUF_B;
#pragma unroll
        for (int i = 0; i < 2; i++) {
            int row = r0l + i * 64;
            uint32_t doff = (row * RS + seg * 8) * 2;
            size_t ga = (size_t)(m0 + row) * DD + k0 + seg * 8;
            size_t gb = (size_t)(n0 + row) * DD + k0 + seg * 8;
            cp16(d0 + doff,              Ahi + ga);
            cp16(d0 + TILE_B + doff,     Alo + ga);
            cp16(d0 + 2 * TILE_B + doff, Bhi + gb);
            cp16(d0 + 3 * TILE_B + doff, Blo + gb);
        }
        cp_commit();
    };

    issue(0, 0);
    int g = lane >> 3, rl = lane & 7;

    for (int c = 0; c < 16; c++) {
        int buf = c & 1;
        if (c < 15) issue(c + 1, buf ^ 1);
        if (c < 15) asm volatile("cp.async.wait_group 1;");
        else        asm volatile("cp.async.wait_group 0;");
        __syncthreads();

        uint32_t aBase = sb + buf * BUF_B;
        uint32_t bBase = aBase + 2 * TILE_B;
#pragma unroll
        for (int h = 0; h < 2; h++) {
            uint32_t aH[4][4], aL[4][4];
#pragma unroll
            for (int it = 0; it < 4; it++) {
                int row = wm * 64 + it * 16 + rl + (g & 1) * 8;
                int kc  = h * 16 + (g & 2) * 4;
                uint32_t ad = aBase + (row * RS + kc) * 2;
                ldsm4(aH[it][0], aH[it][1], aH[it][2], aH[it][3], ad);
                ldsm4(aL[it][0], aL[it][1], aL[it][2], aL[it][3], ad + TILE_B);
            }
            uint32_t bH[4][2], bL[4][2];
#pragma unroll
            for (int jp = 0; jp < 2; jp++) {
                int row = wn * 32 + jp * 16 + rl + (g >> 1) * 8;
                int kc  = h * 16 + (g & 1) * 8;
                uint32_t bd = bBase + (row * RS + kc) * 2;
                ldsm4(bH[2 * jp][0], bH[2 * jp][1], bH[2 * jp + 1][0], bH[2 * jp + 1][1], bd);
                ldsm4(bL[2 * jp][0], bL[2 * jp][1], bL[2 * jp + 1][0], bL[2 * jp + 1][1],
                      bd + TILE_B);
            }
#pragma unroll
            for (int it = 0; it < 4; it++)
#pragma unroll
                for (int jt = 0; jt < 4; jt++) {
                    mma16816(acc[it][jt][0], acc[it][jt][1], acc[it][jt][2], acc[it][jt][3],
                             aH[it][0], aH[it][1], aH[it][2], aH[it][3],
                             bH[jt][0], bH[jt][1]);
                    mma16816(acc[it][jt][0], acc[it][jt][1], acc[it][jt][2], acc[it][jt][3],
                             aH[it][0], aH[it][1], aH[it][2], aH[it][3],
                             bL[jt][0], bL[jt][1]);
                    mma16816(acc[it][jt][0], acc[it][jt][1], acc[it][jt][2], acc[it][jt][3],
                             aL[it][0], aL[it][1], aL[it][2], aL[it][3],
                             bH[jt][0], bH[jt][1]);
                }
        }
        __syncthreads();
    }

    // ---------------- epilogue ----------------
    int rr = lane >> 2, cc = 2 * (lane & 3);
#pragma unroll
    for (int it = 0; it < 4; it++) {
        int row = m0 + wm * 64 + it * 16 + rr;
#pragma unroll
        for (int jt = 0; jt < 4; jt++) {
            int col = n0 + wn * 32 + jt * 8 + cc;
            if (mode == 0) {
                *(float2*)&C[(size_t)row * DD + col] =
                    make_float2(acc[it][jt][0], acc[it][jt][1]);
                *(float2*)&C[(size_t)(row + 8) * DD + col] =
                    make_float2(acc[it][jt][2], acc[it][jt][3]);
            } else {
                float2 bb = *(const float2*)&bias[col];
                *(float2*)&C[(size_t)row * DD + col] =
                    make_float2(acc[it][jt][0] + bb.x, acc[it][jt][1] + bb.y);
                *(float2*)&C[(size_t)(row + 8) * DD + col] =
                    make_float2(acc[it][jt][2] + bb.x, acc[it][jt][3] + bb.y);
            }
        }
    }

    // fused per-head row stats (mode 0, fq/fk rows only)
    if (mode == 0 && m0 < 2 * RQ) {
        float* sred = (float*)smem;   // [wn][128 rows][2] = 4KB
#pragma unroll
        for (int it = 0; it < 4; it++) {
#pragma unroll
            for (int sub = 0; sub < 2; sub++) {
                float s = 0.f, ss = 0.f;
#pragma unroll
                for (int jt = 0; jt < 4; jt++) {
                    float v0 = acc[it][jt][2 * sub], v1 = acc[it][jt][2 * sub + 1];
                    s  += v0 + v1;
                    ss += v0 * v0 + v1 * v1;
                }
#pragma unroll
                for (int o = 1; o <= 2; o <<= 1) {
                    s  += __shfl_xor_sync(0xffffffffu, s, o);
                    ss += __shfl_xor_sync(0xffffffffu, ss, o);
                }
                if ((lane & 3) == 0) {
                    int lr = wm * 64 + it * 16 + rr + sub * 8;
                    sred[(wn * 128 + lr) * 2 + 0] = s;
                    sred[(wn * 128 + lr) * 2 + 1] = ss;
                }
            }
        }
        __syncthreads();
        int hp = t >> 7, lr = t & 127;
        float s  = sred[((2 * hp) * 128 + lr) * 2 + 0] +
                   sred[((2 * hp + 1) * 128 + lr) * 2 + 0];
        float ss = sred[((2 * hp) * 128 + lr) * 2 + 1] +
                   sred[((2 * hp + 1) * 128 + lr) * 2 + 1];
        int grow = m0 + lr;
        int tensor = grow >> 12;
        int b = (grow >> 10) & 3, m = grow & 1023;
        int h = (n0 >> 6) + hp;
        int idx = tensor * 32768 + (h * 4 + b) * 1024 + m;
        g_hmu[idx]   = s * (1.f / 64.f);
        g_hinvn[idx] = rsqrtf(ss);
        g_hvar[idx]  = (ss - s * s * (1.f / 64.f)) * (1.f / 63.f);
    }
}

// ---------------- 3) G/H/r partials: 4 splits x 256 rows, cp.async ring ----------------
__global__ void __launch_bounds__(256, 4) macc()
{
    __shared__ float Ks[2][32][64];
    __shared__ float Vs[2][32][64];
    __shared__ float sikn[256], skv[256];
    int t = threadIdx.x;
    int pair  = blockIdx.x >> 2;
    int split = blockIdx.x & 3;
    int h = pair >> 2, b = pair & 3;
    const float* fk = g_f + (size_t)RQ * DD     + (size_t)(b * 1024) * DD + h * 64;
    const float* fv = g_f + (size_t)2 * RQ * DD + (size_t)(b * 1024) * DD + h * 64;
    int tx = t & 15, ty = t >> 4;
    int d0 = ty * 4, e0 = tx * 4;
    float G[4][4] = {}, Hm[4][4] = {}, ra[4] = {};
    int mbase0 = split * 256;
    uint32_t sK = smem_u32(Ks), sV = smem_u32(Vs);

    auto issue = [&](int c) {
        int mbase = mbase0 + c * 32;
        uint32_t bufo = (uint32_t)(c & 1) * (32 * 64 * 4);
#pragma unroll
        for (int i = 0; i < 2; i++) {
            int u = t + i * 256;
            int rr = u >> 4, c4 = (u & 15) * 4;
            uint32_t off = bufo + (rr * 64 + c4) * 4;
            cp16(sK + off, fk + (size_t)(mbase + rr) * DD + c4);
            cp16(sV + off, fv + (size_t)(mbase + rr) * DD + c4);
        }
        cp_commit();
    };

    issue(0);
    {
        int idx = 32768 + pair * 1024 + mbase0 + t;
        sikn[t] = g_hinvn[idx];
        skv[t]  = g_hvar[idx];
    }

    for (int c = 0; c < 8; c++) {
        if (c < 7) issue(c + 1);
        if (c < 7) asm volatile("cp.async.wait_group 1;");
        else       asm volatile("cp.async.wait_group 0;");
        __syncthreads();
        int buf = c & 1;
#pragma unroll 8
        for (int mm = 0; mm < 32; mm++) {
            float ikn = sikn[c * 32 + mm];
            float4 kk4 = *(float4*)&Ks[buf][mm][d0];
            float4 vv4 = *(float4*)&Vs[buf][mm][e0];
            float kk[4] = {kk4.x, kk4.y, kk4.z, kk4.w};
            float vv[4] = {vv4.x, vv4.y, vv4.z, vv4.w};
            float vn[4] = {vv4.x * ikn, vv4.y * ikn, vv4.z * ikn, vv4.w * ikn};
#pragma unroll
            for (int i = 0; i < 4; i++)
#pragma unroll
                for (int j = 0; j < 4; j++) {
                    G[i][j]  += kk[i] * vv[j];
                    Hm[i][j] += kk[i] * vn[j];
                }
        }
        if (ty == 0) {
#pragma unroll 8
            for (int mm = 0; mm < 32; mm++) {
                float kvv = skv[c * 32 + mm];
#pragma unroll
                for (int j = 0; j < 4; j++) ra[j] += kvv * Vs[buf][mm][e0 + j];
            }
        }
        __syncthreads();
    }
    float* mp = g_Mpart + (size_t)blockIdx.x * 8192;
#pragma unroll
    for (int i = 0; i < 4; i++)
#pragma unroll
        for (int j = 0; j < 4; j++) {
            mp[(d0 + i) * 64 + e0 + j]        = G[i][j];
            mp[4096 + (d0 + i) * 64 + e0 + j] = Hm[i][j];
        }
    if (ty == 0)
#pragma unroll
        for (int j = 0; j < 4; j++) g_rpart[blockIdx.x * 64 + e0 + j] = ra[j];
}

// ---------------- 4) reduce partials (4-way) ----------------
__global__ void mreduce()
{
    int p = blockIdx.x >> 3, seg = blockIdx.x & 7, t = threadIdx.x;
    int base = seg * 1024;
    for (int idx = base + t; idx < base + 1024; idx += 256) {
        float s = 0.f;
#pragma unroll
        for (int sp = 0; sp < SPLITS; sp++)
            s += g_Mpart[(size_t)(p * SPLITS + sp) * 8192 + idx];
        g_M[(size_t)p * 8192 + idx] = s;
    }
    if (seg == 0 && t < 64) {
        float s = 0.f;
#pragma unroll
        for (int sp = 0; sp < SPLITS; sp++) s += g_rpart[(p * SPLITS + sp) * 64 + t];
        g_r[p * 64 + t] = s;
    }
}

// ---------------- 5) apply v2: 64 rows/block, 4 rows/thread ----------------
#define QS_S 65
#define APPLY_SMEM ((8192 + 64 * QS_S + 5 * 64) * 4)

__global__ void __launch_bounds__(256) apply_k(const float* __restrict__ cov_w,
                                               const float* __restrict__ var_w)
{
    extern __shared__ float sm[];
    float* Ms    = sm;                        // 8192: M1 | M2
    float* qs    = sm + 8192;                 // [64 d][QS_S] rows
    float* scs1  = sm + 8192 + 64 * QS_S;     // 64
    float* srs   = scs1 + 64;                 // 64
    float* sbeta = srs + 64;                  // 64
    float* sgam  = sbeta + 64;                // 64
    float* smual = sgam + 64;                 // 64

    int t = threadIdx.x;
    int pair  = blockIdx.x >> 4;
    int ntile = blockIdx.x & 15;
    int h = pair >> 2, b = pair & 3;
    float cw = cov_w[0], vw = var_w[0];
    float w3 = 1.f - cw - vw;
    float alpha = cw * (1.f / 64.f);

    const float* msrc = g_M + (size_t)pair * 8192;
#pragma unroll
    for (int i = 0; i < 8; i++) {
        int fi = t + i * 256;
        ((float4*)Ms)[fi] = ((const float4*)msrc)[fi];
    }
    int n0 = ntile * 64;
    const float* fq = g_f + (size_t)(b * 1024 + n0) * DD + h * 64;
    // load 64 rows x 64 cols transposed: qs[d][row]
#pragma unroll
    for (int i = 0; i < 4; i++) {
        int fi = t + i * 256;
        int rr = fi >> 4, c4 = (fi & 15) * 4;
        float4 x = *(const float4*)(fq + (size_t)rr * DD + c4);
        qs[(c4 + 0) * QS_S + rr] = x.x;
        qs[(c4 + 1) * QS_S + rr] = x.y;
        qs[(c4 + 2) * QS_S + rr] = x.z;
        qs[(c4 + 3) * QS_S + rr] = x.w;
    }
    if (t < 64) {
        int idx = pair * 1024 + n0 + t;
        float mu = g_hmu[idx], invn = g_hinvn[idx], var = g_hvar[idx];
        sbeta[t] = w3 * invn;
        sgam[t]  = vw * (1.f / 64.f) * var;
        smual[t] = alpha * mu;
        srs[t]   = g_r[pair * 64 + t];
    }
    __syncthreads();
    if (t < 64) {
        float s = 0.f;
#pragma unroll
        for (int d = 0; d < 64; d++) s += Ms[d * 64 + t];
        scs1[t] = s;
    }
    __syncthreads();

    int tx = t & 15, ty = t >> 4;
    int e0 = tx * 4, r0 = ty * 4;
    float t1[4][4] = {}, t2[4][4] = {};
#pragma unroll 4
    for (int d = 0; d < 64; d++) {
        float4 m1 = *(float4*)&Ms[d * 64 + e0];
        float4 m2 = *(float4*)&Ms[4096 + d * 64 + e0];
        float qv[4];
#pragma unroll
        for (int i = 0; i < 4; i++) qv[i] = qs[d * QS_S + r0 + i];
#pragma unroll
        for (int i = 0; i < 4; i++) {
            t1[i][0] += qv[i] * m1.x; t1[i][1] += qv[i] * m1.y;
            t1[i][2] += qv[i] * m1.z; t1[i][3] += qv[i] * m1.w;
            t2[i][0] += qv[i] * m2.x; t2[i][1] += qv[i] * m2.y;
            t2[i][2] += qv[i] * m2.z; t2[i][3] += qv[i] * m2.w;
        }
    }
#pragma unroll
    for (int i = 0; i < 4; i++) {
        int row = r0 + i;
        int n = n0 + row;
        float beta = sbeta[row], gamma = sgam[row], mal = smual[row];
        float o0 = alpha * t1[i][0] - mal * scs1[e0 + 0] + beta * t2[i][0] + gamma * srs[e0 + 0];
        float o1 = alpha * t1[i][1] - mal * scs1[e0 + 1] + beta * t2[i][1] + gamma * srs[e0 + 1];
        float o2 = alpha * t1[i][2] - mal * scs1[e0 + 2] + beta * t2[i][2] + gamma * srs[e0 + 2];
        float o3 = alpha * t1[i][3] - mal * scs1[e0 + 3] + beta * t2[i][3] + gamma * srs[e0 + 3];
        __nv_bfloat162 h01 = __floats2bfloat162_rn(o0, o1);
        __nv_bfloat162 h23 = __floats2bfloat162_rn(o2, o3);
        __nv_bfloat162 l01 = __floats2bfloat162_rn(o0 - __bfloat162float(h01.x),
                                                   o1 - __bfloat162float(h01.y));
        __nv_bfloat162 l23 = __floats2bfloat162_rn(o2 - __bfloat162float(h23.x),
                                                   o3 - __bfloat162float(h23.y));
        size_t off = (size_t)(b * 1024 + n) * DD + h * 64 + e0;
        uint2 hv, lv;
        hv.x = *(uint32_t*)&h01; hv.y = *(uint32_t*)&h23;
        lv.x = *(uint32_t*)&l01; lv.y = *(uint32_t*)&l23;
        *(uint2*)&g_ghi[off] = hv;
        *(uint2*)&g_glo[off] = lv;
    }
}

// ---------------- launch ----------------
extern "C" void kernel_launch(void* const* d_in, const int* in_sizes, int n_in,
                              void* d_out, int out_size)
{
    const float* q     = (const float*)d_in[0];
    const float* k     = (const float*)d_in[1];
    const float* v     = (const float*)d_in[2];
    const float* ln_g  = (const float*)d_in[3];
    const float* ln_b  = (const float*)d_in[4];
    const float* W_in  = (const float*)d_in[5];
    const float* W_out = (const float*)d_in[6];
    const float* b_out = (const float*)d_in[7];
    const float* cov_w = (const float*)d_in[8];
    const float* var_w = (const float*)d_in[9];
    float* out = (float*)d_out;

    cudaFuncSetAttribute(gemm_bf3, cudaFuncAttributeMaxDynamicSharedMemorySize, GEMM_SMEM);
    cudaFuncSetAttribute(apply_k, cudaFuncAttributeMaxDynamicSharedMemorySize, APPLY_SMEM);

    __nv_bfloat16 *Ahi, *Alo, *Bhi, *Blo, *ghi, *glo;
    float* f;
    cudaGetSymbolAddress((void**)&Ahi, g_Ahi);
    cudaGetSymbolAddress((void**)&Alo, g_Alo);
    cudaGetSymbolAddress((void**)&Bhi, g_Bhi);
    cudaGetSymbolAddress((void**)&Blo, g_Blo);
    cudaGetSymbolAddress((void**)&ghi, g_ghi);
    cudaGetSymbolAddress((void**)&glo, g_glo);
    cudaGetSymbolAddress((void**)&f,   g_f);

    prep<<<1536 + 512, 256>>>(q, k, v, ln_g, ln_b, W_in, W_out);
    gemm_bf3<<<dim3(4, 96), 256, GEMM_SMEM>>>(Ahi, Alo, Bhi, Blo, f, nullptr, 0);
    macc<<<NPAIR * SPLITS, 256>>>();
    mreduce<<<NPAIR * 8, 256>>>();
    apply_k<<<NPAIR * 16, 256, APPLY_SMEM>>>(cov_w, var_w);
    gemm_bf3<<<dim3(4, 32), 256, GEMM_SMEM>>>(ghi, glo, Bhi + DD * DD, Blo + DD * DD,
                                              out, b_out, 1);
}

// round 12
// speedup vs baseline: 1.1132x; 1.0138x over previous
#include <cuda_runtime.h>
#include <cuda_bf16.h>
#include <cstdint>

// Problem constants: B=4, S=1024, D=512, H=8, DH=64
#define RQ   4096
#define R3   12288
#define DD   512
#define NPAIR 32
#define SPLITS 4
#define LN_EPS 1e-5f

// ---------------- scratch ----------------
__device__ float         g_f[3 * RQ * DD];        // fp32 f_q|f_k|f_v
__device__ __nv_bfloat16 g_Ahi[R3 * DD];
__device__ __nv_bfloat16 g_Alo[R3 * DD];
__device__ __nv_bfloat16 g_Bhi[2 * DD * DD];      // W_in^T | W_out^T (hi)
__device__ __nv_bfloat16 g_Blo[2 * DD * DD];
__device__ __nv_bfloat16 g_ghi[RQ * DD];
__device__ __nv_bfloat16 g_glo[RQ * DD];
__device__ float g_hmu[2 * NPAIR * 1024];
__device__ float g_hinvn[2 * NPAIR * 1024];
__device__ float g_hvar[2 * NPAIR * 1024];
__device__ float g_Mpart[NPAIR * SPLITS * 2 * 4096];
__device__ float g_rpart[NPAIR * SPLITS * 64];
__device__ float g_M[NPAIR * 2 * 4096];   // G = K^T V | H = K^T (ikn*V)
__device__ float g_r[NPAIR * 64];

// ---------------- helpers ----------------
__device__ __forceinline__ uint32_t smem_u32(const void* p) {
    uint32_t a;
    asm("{ .reg .u64 t; cvta.to.shared.u64 t, %1; cvt.u32.u64 %0, t; }" : "=r"(a) : "l"(p));
    return a;
}
__device__ __forceinline__ void cp16(uint32_t dst, const void* src) {
    asm volatile("cp.async.cg.shared.global [%0], [%1], 16;" :: "r"(dst), "l"(src));
}
__device__ __forceinline__ void cp_commit() {
    asm volatile("cp.async.commit_group;");
}
__device__ __forceinline__ void ldsm4(uint32_t& r0, uint32_t& r1, uint32_t& r2, uint32_t& r3,
                                      uint32_t addr) {
    asm volatile("ldmatrix.sync.aligned.m8n8.x4.shared.b16 {%0,%1,%2,%3}, [%4];"
                 : "=r"(r0), "=r"(r1), "=r"(r2), "=r"(r3) : "r"(addr));
}
__device__ __forceinline__ void mma16816(float& c0, float& c1, float& c2, float& c3,
                                         uint32_t a0, uint32_t a1, uint32_t a2, uint32_t a3,
                                         uint32_t b0, uint32_t b1) {
    asm volatile(
        "mma.sync.aligned.m16n8k16.row.col.f32.bf16.bf16.f32 "
        "{%0,%1,%2,%3}, {%4,%5,%6,%7}, {%8,%9}, {%0,%1,%2,%3};"
        : "+f"(c0), "+f"(c1), "+f"(c2), "+f"(c3)
        : "r"(a0), "r"(a1), "r"(a2), "r"(a3), "r"(b0), "r"(b1));
}

// ---------------- 1) merged prep: LN+split | W transpose+split ----------------
__global__ void __launch_bounds__(256) prep(
    const float* __restrict__ q, const float* __restrict__ k,
    const float* __restrict__ v, const float* __restrict__ lng,
    const float* __restrict__ lnb, const float* __restrict__ Win,
    const float* __restrict__ Wout)
{
    __shared__ float ts[32][33];
    if (blockIdx.x < 1536) {
        int gw   = blockIdx.x * 8 + (threadIdx.x >> 5);
        int lane = threadIdx.x & 31;
        const float* src = (gw < RQ) ? q : (gw < 2 * RQ ? k : v);
        int row = gw & (RQ - 1);
        const float4* p = (const float4*)(src + (size_t)row * DD);
        float4 x[4];
        float s = 0.f, ss = 0.f;
#pragma unroll
        for (int i = 0; i < 4; i++) {
            x[i] = p[lane + i * 32];
            s  += x[i].x + x[i].y + x[i].z + x[i].w;
            ss += x[i].x * x[i].x + x[i].y * x[i].y + x[i].z * x[i].z + x[i].w * x[i].w;
        }
#pragma unroll
        for (int o = 16; o; o >>= 1) {
            s  += __shfl_xor_sync(0xffffffffu, s, o);
            ss += __shfl_xor_sync(0xffffffffu, ss, o);
        }
        float mu = s * (1.f / 512.f);
        float rs = rsqrtf(ss * (1.f / 512.f) - mu * mu + LN_EPS);
#pragma unroll
        for (int i = 0; i < 4; i++) {
            float4 gg = ((const float4*)lng)[lane + i * 32];
            float4 bb = ((const float4*)lnb)[lane + i * 32];
            float y0 = (x[i].x - mu) * rs * gg.x + bb.x;
            float y1 = (x[i].y - mu) * rs * gg.y + bb.y;
            float y2 = (x[i].z - mu) * rs * gg.z + bb.z;
            float y3 = (x[i].w - mu) * rs * gg.w + bb.w;
            __nv_bfloat162 h01 = __floats2bfloat162_rn(y0, y1);
            __nv_bfloat162 h23 = __floats2bfloat162_rn(y2, y3);
            __nv_bfloat162 l01 = __floats2bfloat162_rn(y0 - __bfloat162float(h01.x),
                                                       y1 - __bfloat162float(h01.y));
            __nv_bfloat162 l23 = __floats2bfloat162_rn(y2 - __bfloat162float(h23.x),
                                                       y3 - __bfloat162float(h23.y));
            size_t off = (size_t)gw * DD + 4 * (lane + 32 * i);
            uint2 hv, lv;
            hv.x = *(uint32_t*)&h01; hv.y = *(uint32_t*)&h23;
            lv.x = *(uint32_t*)&l01; lv.y = *(uint32_t*)&l23;
            *(uint2*)&g_Ahi[off] = hv;
            *(uint2*)&g_Alo[off] = lv;
        }
    } else {
        int bx = blockIdx.x - 1536;
        int bz = bx >> 8; bx &= 255;
        const float* W = bz ? Wout : Win;
        size_t base = (size_t)bz * DD * DD;
        int k0 = (bx >> 4) * 32, n0 = (bx & 15) * 32;
        int tx = threadIdx.x & 31, ty = threadIdx.x >> 5;
#pragma unroll
        for (int i = 0; i < 4; i++)
            ts[ty + 8 * i][tx] = W[(size_t)(k0 + ty + 8 * i) * DD + n0 + tx];
        __syncthreads();
#pragma unroll
        for (int i = 0; i < 4; i++) {
            int n = n0 + ty + 8 * i, kk = k0 + tx;
            float val = ts[tx][ty + 8 * i];
            __nv_bfloat16 h = __float2bfloat16_rn(val);
            __nv_bfloat16 l = __float2bfloat16_rn(val - __bfloat162float(h));
            g_Bhi[base + (size_t)n * DD + kk] = h;
            g_Blo[base + (size_t)n * DD + kk] = l;
        }
    }
}

// ---------------- 2) HMMA GEMM, bf16x3 (R6-best config), GEMM1 ----------------
#define RS 40                      // smem row stride (bf16)
#define TILE_B (128 * RS * 2)      // 10240 bytes per operand tile
#define BUF_B  (4 * TILE_B)        // Ahi|Alo|Bhi|Blo per buffer
#define GEMM_SMEM (2 * BUF_B)      // 81920 bytes

__global__ void __launch_bounds__(256, 2) gemm_bf3(
    const __nv_bfloat16* __restrict__ Ahi, const __nv_bfloat16* __restrict__ Alo,
    const __nv_bfloat16* __restrict__ Bhi, const __nv_bfloat16* __restrict__ Blo,
    float* __restrict__ C, const float* __restrict__ bias, int mode)
{
    extern __shared__ char smem[];
    uint32_t sb = smem_u32(smem);
    int t = threadIdx.x, wid = t >> 5, lane = t & 31;
    int n0 = blockIdx.x * 128, m0 = blockIdx.y * 128;
    int wm = wid >> 2, wn = wid & 3;

    float acc[4][4][4];
#pragma unroll
    for (int i = 0; i < 4; i++)
#pragma unroll
        for (int j = 0; j < 4; j++)
#pragma unroll
            for (int r = 0; r < 4; r++) acc[i][j][r] = 0.f;

    int r0l = t >> 2, seg = t & 3;

    auto issue = [&](int c, int buf) {
        int k0 = c * 32;
        uint32_t d0 = sb + buf * BUF_B;
#pragma unroll
        for (int i = 0; i < 2; i++) {
            int row = r0l + i * 64;
            uint32_t doff = (row * RS + seg * 8) * 2;
            size_t ga = (size_t)(m0 + row) * DD + k0 + seg * 8;
            size_t gb = (size_t)(n0 + row) * DD + k0 + seg * 8;
            cp16(d0 + doff,              Ahi + ga);
            cp16(d0 + TILE_B + doff,     Alo + ga);
            cp16(d0 + 2 * TILE_B + doff, Bhi + gb);
            cp16(d0 + 3 * TILE_B + doff, Blo + gb);
        }
        cp_commit();
    };

    issue(0, 0);
    int g = lane >> 3, rl = lane & 7;

    for (int c = 0; c < 16; c++) {
        int buf = c & 1;
        if (c < 15) issue(c + 1, buf ^ 1);
        if (c < 15) asm volatile("cp.async.wait_group 1;");
        else        asm volatile("cp.async.wait_group 0;");
        __syncthreads();

        uint32_t aBase = sb + buf * BUF_B;
        uint32_t bBase = aBase + 2 * TILE_B;
#pragma unroll
        for (int h = 0; h < 2; h++) {
            uint32_t aH[4][4], aL[4][4];
#pragma unroll
            for (int it = 0; it < 4; it++) {
                int row = wm * 64 + it * 16 + rl + (g & 1) * 8;
                int kc  = h * 16 + (g & 2) * 4;
                uint32_t ad = aBase + (row * RS + kc) * 2;
                ldsm4(aH[it][0], aH[it][1], aH[it][2], aH[it][3], ad);
                ldsm4(aL[it][0], aL[it][1], aL[it][2], aL[it][3], ad + TILE_B);
            }
            uint32_t bH[4][2], bL[4][2];
#pragma unroll
            for (int jp = 0; jp < 2; jp++) {
                int row = wn * 32 + jp * 16 + rl + (g >> 1) * 8;
                int kc  = h * 16 + (g & 1) * 8;
                uint32_t bd = bBase + (row * RS + kc) * 2;
                ldsm4(bH[2 * jp][0], bH[2 * jp][1], bH[2 * jp + 1][0], bH[2 * jp + 1][1], bd);
                ldsm4(bL[2 * jp][0], bL[2 * jp][1], bL[2 * jp + 1][0], bL[2 * jp + 1][1],
                      bd + TILE_B);
            }
#pragma unroll
            for (int it = 0; it < 4; it++)
#pragma unroll
                for (int jt = 0; jt < 4; jt++) {
                    mma16816(acc[it][jt][0], acc[it][jt][1], acc[it][jt][2], acc[it][jt][3],
                             aH[it][0], aH[it][1], aH[it][2], aH[it][3],
                             bH[jt][0], bH[jt][1]);
                    mma16816(acc[it][jt][0], acc[it][jt][1], acc[it][jt][2], acc[it][jt][3],
                             aH[it][0], aH[it][1], aH[it][2], aH[it][3],
                             bL[jt][0], bL[jt][1]);
                    mma16816(acc[it][jt][0], acc[it][jt][1], acc[it][jt][2], acc[it][jt][3],
                             aL[it][0], aL[it][1], aL[it][2], aL[it][3],
                             bH[jt][0], bH[jt][1]);
                }
        }
        __syncthreads();
    }

    // ---------------- epilogue ----------------
    int rr = lane >> 2, cc = 2 * (lane & 3);
#pragma unroll
    for (int it = 0; it < 4; it++) {
        int row = m0 + wm * 64 + it * 16 + rr;
#pragma unroll
        for (int jt = 0; jt < 4; jt++) {
            int col = n0 + wn * 32 + jt * 8 + cc;
            *(float2*)&C[(size_t)row * DD + col] =
                make_float2(acc[it][jt][0], acc[it][jt][1]);
            *(float2*)&C[(size_t)(row + 8) * DD + col] =
                make_float2(acc[it][jt][2], acc[it][jt][3]);
        }
    }

    // fused per-head row stats (fq/fk rows only)
    if (m0 < 2 * RQ) {
        float* sred = (float*)smem;   // [wn][128 rows][2] = 4KB
#pragma unroll
        for (int it = 0; it < 4; it++) {
#pragma unroll
            for (int sub = 0; sub < 2; sub++) {
                float s = 0.f, ss = 0.f;
#pragma unroll
                for (int jt = 0; jt < 4; jt++) {
                    float v0 = acc[it][jt][2 * sub], v1 = acc[it][jt][2 * sub + 1];
                    s  += v0 + v1;
                    ss += v0 * v0 + v1 * v1;
                }
#pragma unroll
                for (int o = 1; o <= 2; o <<= 1) {
                    s  += __shfl_xor_sync(0xffffffffu, s, o);
                    ss += __shfl_xor_sync(0xffffffffu, ss, o);
                }
                if ((lane & 3) == 0) {
                    int lr = wm * 64 + it * 16 + rr + sub * 8;
                    sred[(wn * 128 + lr) * 2 + 0] = s;
                    sred[(wn * 128 + lr) * 2 + 1] = ss;
                }
            }
        }
        __syncthreads();
        int hp = t >> 7, lr = t & 127;
        float s  = sred[((2 * hp) * 128 + lr) * 2 + 0] +
                   sred[((2 * hp + 1) * 128 + lr) * 2 + 0];
        float ss = sred[((2 * hp) * 128 + lr) * 2 + 1] +
                   sred[((2 * hp + 1) * 128 + lr) * 2 + 1];
        int grow = m0 + lr;
        int tensor = grow >> 12;
        int b = (grow >> 10) & 3, m = grow & 1023;
        int h = (n0 >> 6) + hp;
        int idx = tensor * 32768 + (h * 4 + b) * 1024 + m;
        g_hmu[idx]   = s * (1.f / 64.f);
        g_hinvn[idx] = rsqrtf(ss);
        g_hvar[idx]  = (ss - s * s * (1.f / 64.f)) * (1.f / 63.f);
    }
}

// ---------------- 2b) GEMM2: CTA tile 64x128 (256 CTAs -> full chip) ----------------
#define A64_B (64 * RS * 2)          // 5120 B per A part
#define BUF64 (2 * A64_B + 2 * TILE_B)   // Ahi|Alo|Bhi|Blo = 30720
#define GEMM64_SMEM (2 * BUF64)      // 61440

__global__ void __launch_bounds__(256, 2) gemm_bf3_m64(
    const __nv_bfloat16* __restrict__ Ahi, const __nv_bfloat16* __restrict__ Alo,
    const __nv_bfloat16* __restrict__ Bhi, const __nv_bfloat16* __restrict__ Blo,
    float* __restrict__ C, const float* __restrict__ bias)
{
    extern __shared__ char smem[];
    uint32_t sb = smem_u32(smem);
    int t = threadIdx.x, wid = t >> 5, lane = t & 31;
    int n0 = blockIdx.x * 128, m0 = blockIdx.y * 64;
    int wm = wid >> 2, wn = wid & 3;   // warp tile 32x32

    float acc[2][4][4];
#pragma unroll
    for (int i = 0; i < 2; i++)
#pragma unroll
        for (int j = 0; j < 4; j++)
#pragma unroll
            for (int r = 0; r < 4; r++) acc[i][j][r] = 0.f;

    auto issue = [&](int c, int buf) {
        int k0 = c * 32;
        uint32_t d0 = sb + buf * BUF64;
        // A: 64 rows x 4 units, 1 unit/thread per part
        {
            int row = t >> 2, seg = t & 3;
            uint32_t doff = (row * RS + seg * 8) * 2;
            size_t ga = (size_t)(m0 + row) * DD + k0 + seg * 8;
            cp16(d0 + doff,         Ahi + ga);
            cp16(d0 + A64_B + doff, Alo + ga);
        }
        // B: 128 rows x 4 units, 2 units/thread per part
#pragma unroll
        for (int i = 0; i < 2; i++) {
            int u = t + i * 256;
            int row = u >> 2, seg = u & 3;
            uint32_t doff = (row * RS + seg * 8) * 2;
            size_t gb = (size_t)(n0 + row) * DD + k0 + seg * 8;
            cp16(d0 + 2 * A64_B + doff,          Bhi + gb);
            cp16(d0 + 2 * A64_B + TILE_B + doff, Blo + gb);
        }
        cp_commit();
    };

    issue(0, 0);
    int g = lane >> 3, rl = lane & 7;

    for (int c = 0; c < 16; c++) {
        int buf = c & 1;
        if (c < 15) issue(c + 1, buf ^ 1);
        if (c < 15) asm volatile("cp.async.wait_group 1;");
        else        asm volatile("cp.async.wait_group 0;");
        __syncthreads();

        uint32_t aBase = sb + buf * BUF64;
        uint32_t bBase = aBase + 2 * A64_B;
#pragma unroll
        for (int h = 0; h < 2; h++) {
            uint32_t aH[2][4], aL[2][4];
#pragma unroll
            for (int it = 0; it < 2; it++) {
                int row = wm * 32 + it * 16 + rl + (g & 1) * 8;
                int kc  = h * 16 + (g & 2) * 4;
                uint32_t ad = aBase + (row * RS + kc) * 2;
                ldsm4(aH[it][0], aH[it][1], aH[it][2], aH[it][3], ad);
                ldsm4(aL[it][0], aL[it][1], aL[it][2], aL[it][3], ad + A64_B);
            }
            uint32_t bH[4][2], bL[4][2];
#pragma unroll
            for (int jp = 0; jp < 2; jp++) {
                int row = wn * 32 + jp * 16 + rl + (g >> 1) * 8;
                int kc  = h * 16 + (g & 1) * 8;
                uint32_t bd = bBase + (row * RS + kc) * 2;
                ldsm4(bH[2 * jp][0], bH[2 * jp][1], bH[2 * jp + 1][0], bH[2 * jp + 1][1], bd);
                ldsm4(bL[2 * jp][0], bL[2 * jp][1], bL[2 * jp + 1][0], bL[2 * jp + 1][1],
                      bd + TILE_B);
            }
#pragma unroll
            for (int it = 0; it < 2; it++)
#pragma unroll
                for (int jt = 0; jt < 4; jt++) {
                    mma16816(acc[it][jt][0], acc[it][jt][1], acc[it][jt][2], acc[it][jt][3],
                             aH[it][0], aH[it][1], aH[it][2], aH[it][3],
                             bH[jt][0], bH[jt][1]);
                    mma16816(acc[it][jt][0], acc[it][jt][1], acc[it][jt][2], acc[it][jt][3],
                             aH[it][0], aH[it][1], aH[it][2], aH[it][3],
                             bL[jt][0], bL[jt][1]);
                    mma16816(acc[it][jt][0], acc[it][jt][1], acc[it][jt][2], acc[it][jt][3],
                             aL[it][0], aL[it][1], aL[it][2], aL[it][3],
                             bH[jt][0], bH[jt][1]);
                }
        }
        __syncthreads();
    }

    int rr = lane >> 2, cc = 2 * (lane & 3);
#pragma unroll
    for (int it = 0; it < 2; it++) {
        int row = m0 + wm * 32 + it * 16 + rr;
#pragma unroll
        for (int jt = 0; jt < 4; jt++) {
            int col = n0 + wn * 32 + jt * 8 + cc;
            float2 bb = *(const float2*)&bias[col];
            *(float2*)&C[(size_t)row * DD + col] =
                make_float2(acc[it][jt][0] + bb.x, acc[it][jt][1] + bb.y);
            *(float2*)&C[(size_t)(row + 8) * DD + col] =
                make_float2(acc[it][jt][2] + bb.x, acc[it][jt][3] + bb.y);
        }
    }
}

// ---------------- 3) G/H/r partials: 4 splits x 256 rows, cp.async ring ----------------
__global__ void __launch_bounds__(256, 4) macc()
{
    __shared__ float Ks[2][32][64];
    __shared__ float Vs[2][32][64];
    __shared__ float sikn[256], skv[256];
    int t = threadIdx.x;
    int pair  = blockIdx.x >> 2;
    int split = blockIdx.x & 3;
    int h = pair >> 2, b = pair & 3;
    const float* fk = g_f + (size_t)RQ * DD     + (size_t)(b * 1024) * DD + h * 64;
    const float* fv = g_f + (size_t)2 * RQ * DD + (size_t)(b * 1024) * DD + h * 64;
    int tx = t & 15, ty = t >> 4;
    int d0 = ty * 4, e0 = tx * 4;
    float G[4][4] = {}, Hm[4][4] = {}, ra[4] = {};
    int mbase0 = split * 256;
    uint32_t sK = smem_u32(Ks), sV = smem_u32(Vs);

    auto issue = [&](int c) {
        int mbase = mbase0 + c * 32;
        uint32_t bufo = (uint32_t)(c & 1) * (32 * 64 * 4);
#pragma unroll
        for (int i = 0; i < 2; i++) {
            int u = t + i * 256;
            int rr = u >> 4, c4 = (u & 15) * 4;
            uint32_t off = bufo + (rr * 64 + c4) * 4;
            cp16(sK + off, fk + (size_t)(mbase + rr) * DD + c4);
            cp16(sV + off, fv + (size_t)(mbase + rr) * DD + c4);
        }
        cp_commit();
    };

    issue(0);
    {
        int idx = 32768 + pair * 1024 + mbase0 + t;
        sikn[t] = g_hinvn[idx];
        skv[t]  = g_hvar[idx];
    }

    for (int c = 0; c < 8; c++) {
        if (c < 7) issue(c + 1);
        if (c < 7) asm volatile("cp.async.wait_group 1;");
        else       asm volatile("cp.async.wait_group 0;");
        __syncthreads();
        int buf = c & 1;
#pragma unroll 8
        for (int mm = 0; mm < 32; mm++) {
            float ikn = sikn[c * 32 + mm];
            float4 kk4 = *(float4*)&Ks[buf][mm][d0];
            float4 vv4 = *(float4*)&Vs[buf][mm][e0];
            float kk[4] = {kk4.x, kk4.y, kk4.z, kk4.w};
            float vv[4] = {vv4.x, vv4.y, vv4.z, vv4.w};
            float vn[4] = {vv4.x * ikn, vv4.y * ikn, vv4.z * ikn, vv4.w * ikn};
#pragma unroll
            for (int i = 0; i < 4; i++)
#pragma unroll
                for (int j = 0; j < 4; j++) {
                    G[i][j]  += kk[i] * vv[j];
                    Hm[i][j] += kk[i] * vn[j];
                }
        }
        if (ty == 0) {
#pragma unroll 8
            for (int mm = 0; mm < 32; mm++) {
                float kvv = skv[c * 32 + mm];
#pragma unroll
                for (int j = 0; j < 4; j++) ra[j] += kvv * Vs[buf][mm][e0 + j];
            }
        }
        __syncthreads();
    }
    float* mp = g_Mpart + (size_t)blockIdx.x * 8192;
#pragma unroll
    for (int i = 0; i < 4; i++)
#pragma unroll
        for (int j = 0; j < 4; j++) {
            mp[(d0 + i) * 64 + e0 + j]        = G[i][j];
            mp[4096 + (d0 + i) * 64 + e0 + j] = Hm[i][j];
        }
    if (ty == 0)
#pragma unroll
        for (int j = 0; j < 4; j++) g_rpart[blockIdx.x * 64 + e0 + j] = ra[j];
}

// ---------------- 4) reduce partials (1 elem/thread, 1024 blocks) ----------------
__global__ void mreduce()
{
    int p = blockIdx.x >> 5, seg = blockIdx.x & 31, t = threadIdx.x;
    int idx = seg * 256 + t;
    const float* p0 = g_Mpart + (size_t)(p * SPLITS) * 8192;
    float s = 0.f;
#pragma unroll
    for (int sp = 0; sp < SPLITS; sp++) s += __ldcg(p0 + (size_t)sp * 8192 + idx);
    g_M[(size_t)p * 8192 + idx] = s;
    if (seg == 0 && t < 64) {
        float r = 0.f;
#pragma unroll
        for (int sp = 0; sp < SPLITS; sp++)
            r += __ldcg(&g_rpart[(p * SPLITS + sp) * 64 + t]);
        g_r[p * 64 + t] = r;
    }
}

// ---------------- 5) apply v2: 64 rows/block, 4 rows/thread ----------------
#define QS_S 65
#define APPLY_SMEM ((8192 + 64 * QS_S + 5 * 64) * 4)

__global__ void __launch_bounds__(256) apply_k(const float* __restrict__ cov_w,
                                               const float* __restrict__ var_w)
{
    extern __shared__ float sm[];
    float* Ms    = sm;
    float* qs    = sm + 8192;
    float* scs1  = sm + 8192 + 64 * QS_S;
    float* srs   = scs1 + 64;
    float* sbeta = srs + 64;
    float* sgam  = sbeta + 64;
    float* smual = sgam + 64;

    int t = threadIdx.x;
    int pair  = blockIdx.x >> 4;
    int ntile = blockIdx.x & 15;
    int h = pair >> 2, b = pair & 3;
    float cw = cov_w[0], vw = var_w[0];
    float w3 = 1.f - cw - vw;
    float alpha = cw * (1.f / 64.f);

    const float* msrc = g_M + (size_t)pair * 8192;
#pragma unroll
    for (int i = 0; i < 8; i++) {
        int fi = t + i * 256;
        ((float4*)Ms)[fi] = ((const float4*)msrc)[fi];
    }
    int n0 = ntile * 64;
    const float* fq = g_f + (size_t)(b * 1024 + n0) * DD + h * 64;
#pragma unroll
    for (int i = 0; i < 4; i++) {
        int fi = t + i * 256;
        int rr = fi >> 4, c4 = (fi & 15) * 4;
        float4 x = *(const float4*)(fq + (size_t)rr * DD + c4);
        qs[(c4 + 0) * QS_S + rr] = x.x;
        qs[(c4 + 1) * QS_S + rr] = x.y;
        qs[(c4 + 2) * QS_S + rr] = x.z;
        qs[(c4 + 3) * QS_S + rr] = x.w;
    }
    if (t < 64) {
        int idx = pair * 1024 + n0 + t;
        float mu = g_hmu[idx], invn = g_hinvn[idx], var = g_hvar[idx];
        sbeta[t] = w3 * invn;
        sgam[t]  = vw * (1.f / 64.f) * var;
        smual[t] = alpha * mu;
        srs[t]   = g_r[pair * 64 + t];
    }
    __syncthreads();
    if (t < 64) {
        float s = 0.f;
#pragma unroll
        for (int d = 0; d < 64; d++) s += Ms[d * 64 + t];
        scs1[t] = s;
    }
    __syncthreads();

    int tx = t & 15, ty = t >> 4;
    int e0 = tx * 4, r0 = ty * 4;
    float t1[4][4] = {}, t2[4][4] = {};
#pragma unroll 4
    for (int d = 0; d < 64; d++) {
        float4 m1 = *(float4*)&Ms[d * 64 + e0];
        float4 m2 = *(float4*)&Ms[4096 + d * 64 + e0];
        float qv[4];
#pragma unroll
        for (int i = 0; i < 4; i++) qv[i] = qs[d * QS_S + r0 + i];
#pragma unroll
        for (int i = 0; i < 4; i++) {
            t1[i][0] += qv[i] * m1.x; t1[i][1] += qv[i] * m1.y;
            t1[i][2] += qv[i] * m1.z; t1[i][3] += qv[i] * m1.w;
            t2[i][0] += qv[i] * m2.x; t2[i][1] += qv[i] * m2.y;
            t2[i][2] += qv[i] * m2.z; t2[i][3] += qv[i] * m2.w;
        }
    }
#pragma unroll
    for (int i = 0; i < 4; i++) {
        int row = r0 + i;
        int n = n0 + row;
        float beta = sbeta[row], gamma = sgam[row], mal = smual[row];
        float o0 = alpha * t1[i][0] - mal * scs1[e0 + 0] + beta * t2[i][0] + gamma * srs[e0 + 0];
        float o1 = alpha * t1[i][1] - mal * scs1[e0 + 1] + beta * t2[i][1] + gamma * srs[e0 + 1];
        float o2 = alpha * t1[i][2] - mal * scs1[e0 + 2] + beta * t2[i][2] + gamma * srs[e0 + 2];
        float o3 = alpha * t1[i][3] - mal * scs1[e0 + 3] + beta * t2[i][3] + gamma * srs[e0 + 3];
        __nv_bfloat162 h01 = __floats2bfloat162_rn(o0, o1);
        __nv_bfloat162 h23 = __floats2bfloat162_rn(o2, o3);
        __nv_bfloat162 l01 = __floats2bfloat162_rn(o0 - __bfloat162float(h01.x),
                                                   o1 - __bfloat162float(h01.y));
        __nv_bfloat162 l23 = __floats2bfloat162_rn(o2 - __bfloat162float(h23.x),
                                                   o3 - __bfloat162float(h23.y));
        size_t off = (size_t)(b * 1024 + n) * DD + h * 64 + e0;
        uint2 hv, lv;
        hv.x = *(uint32_t*)&h01; hv.y = *(uint32_t*)&h23;
        lv.x = *(uint32_t*)&l01; lv.y = *(uint32_t*)&l23;
        *(uint2*)&g_ghi[off] = hv;
        *(uint2*)&g_glo[off] = lv;
    }
}

// ---------------- launch ----------------
extern "C" void kernel_launch(void* const* d_in, const int* in_sizes, int n_in,
                              void* d_out, int out_size)
{
    const float* q     = (const float*)d_in[0];
    const float* k     = (const float*)d_in[1];
    const float* v     = (const float*)d_in[2];
    const float* ln_g  = (const float*)d_in[3];
    const float* ln_b  = (const float*)d_in[4];
    const float* W_in  = (const float*)d_in[5];
    const float* W_out = (const float*)d_in[6];
    const float* b_out = (const float*)d_in[7];
    const float* cov_w = (const float*)d_in[8];
    const float* var_w = (const float*)d_in[9];
    float* out = (float*)d_out;

    cudaFuncSetAttribute(gemm_bf3, cudaFuncAttributeMaxDynamicSharedMemorySize, GEMM_SMEM);
    cudaFuncSetAttribute(gemm_bf3_m64, cudaFuncAttributeMaxDynamicSharedMemorySize, GEMM64_SMEM);
    cudaFuncSetAttribute(apply_k, cudaFuncAttributeMaxDynamicSharedMemorySize, APPLY_SMEM);

    __nv_bfloat16 *Ahi, *Alo, *Bhi, *Blo, *ghi, *glo;
    float* f;
    cudaGetSymbolAddress((void**)&Ahi, g_Ahi);
    cudaGetSymbolAddress((void**)&Alo, g_Alo);
    cudaGetSymbolAddress((void**)&Bhi, g_Bhi);
    cudaGetSymbolAddress((void**)&Blo, g_Blo);
    cudaGetSymbolAddress((void**)&ghi, g_ghi);
    cudaGetSymbolAddress((void**)&glo, g_glo);
    cudaGetSymbolAddress((void**)&f,   g_f);

    prep<<<1536 + 512, 256>>>(q, k, v, ln_g, ln_b, W_in, W_out);
    gemm_bf3<<<dim3(4, 96), 256, GEMM_SMEM>>>(Ahi, Alo, Bhi, Blo, f, nullptr, 0);
    macc<<<NPAIR * SPLITS, 256>>>();
    mreduce<<<NPAIR * 32, 256>>>();
    apply_k<<<NPAIR * 16, 256, APPLY_SMEM>>>(cov_w, var_w);
    gemm_bf3_m64<<<dim3(4, 64), 256, GEMM64_SMEM>>>(ghi, glo, Bhi + DD * DD, Blo + DD * DD,
                                                    out, b_out);
}

// round 13
// speedup vs baseline: 1.1152x; 1.0018x over previous
#include <cuda_runtime.h>
#include <cuda_bf16.h>
#include <cstdint>

// Problem constants: B=4, S=1024, D=512, H=8, DH=64
#define RQ   4096
#define R3   12288
#define DD   512
#define NPAIR 32
#define SPLITS 4
#define LN_EPS 1e-5f

// ---------------- scratch ----------------
__device__ float         g_f[3 * RQ * DD];        // fp32 f_q|f_k|f_v
__device__ __nv_bfloat16 g_Ahi[R3 * DD];
__device__ __nv_bfloat16 g_Alo[R3 * DD];
__device__ __nv_bfloat16 g_Bhi[2 * DD * DD];      // W_in^T | W_out^T (hi)
__device__ __nv_bfloat16 g_Blo[2 * DD * DD];
__device__ __nv_bfloat16 g_ghi[RQ * DD];
__device__ __nv_bfloat16 g_glo[RQ * DD];
__device__ float g_hmu[2 * NPAIR * 1024];
__device__ float g_hinvn[2 * NPAIR * 1024];
__device__ float g_hvar[2 * NPAIR * 1024];
__device__ float g_Mpart[NPAIR * SPLITS * 2 * 4096];
__device__ float g_rpart[NPAIR * SPLITS * 64];

// ---------------- helpers ----------------
__device__ __forceinline__ uint32_t smem_u32(const void* p) {
    uint32_t a;
    asm("{ .reg .u64 t; cvta.to.shared.u64 t, %1; cvt.u32.u64 %0, t; }" : "=r"(a) : "l"(p));
    return a;
}
__device__ __forceinline__ void cp16(uint32_t dst, const void* src) {
    asm volatile("cp.async.cg.shared.global [%0], [%1], 16;" :: "r"(dst), "l"(src));
}
__device__ __forceinline__ void cp_commit() {
    asm volatile("cp.async.commit_group;");
}
__device__ __forceinline__ void ldsm4(uint32_t& r0, uint32_t& r1, uint32_t& r2, uint32_t& r3,
                                      uint32_t addr) {
    asm volatile("ldmatrix.sync.aligned.m8n8.x4.shared.b16 {%0,%1,%2,%3}, [%4];"
                 : "=r"(r0), "=r"(r1), "=r"(r2), "=r"(r3) : "r"(addr));
}
__device__ __forceinline__ void mma16816(float& c0, float& c1, float& c2, float& c3,
                                         uint32_t a0, uint32_t a1, uint32_t a2, uint32_t a3,
                                         uint32_t b0, uint32_t b1) {
    asm volatile(
        "mma.sync.aligned.m16n8k16.row.col.f32.bf16.bf16.f32 "
        "{%0,%1,%2,%3}, {%4,%5,%6,%7}, {%8,%9}, {%0,%1,%2,%3};"
        : "+f"(c0), "+f"(c1), "+f"(c2), "+f"(c3)
        : "r"(a0), "r"(a1), "r"(a2), "r"(a3), "r"(b0), "r"(b1));
}

// ---------------- 1) merged prep: LN+split | W transpose+split ----------------
__global__ void __launch_bounds__(256) prep(
    const float* __restrict__ q, const float* __restrict__ k,
    const float* __restrict__ v, const float* __restrict__ lng,
    const float* __restrict__ lnb, const float* __restrict__ Win,
    const float* __restrict__ Wout)
{
    __shared__ float ts[32][33];
    if (blockIdx.x < 1536) {
        int gw   = blockIdx.x * 8 + (threadIdx.x >> 5);
        int lane = threadIdx.x & 31;
        const float* src = (gw < RQ) ? q : (gw < 2 * RQ ? k : v);
        int row = gw & (RQ - 1);
        const float4* p = (const float4*)(src + (size_t)row * DD);
        float4 x[4];
        float s = 0.f, ss = 0.f;
#pragma unroll
        for (int i = 0; i < 4; i++) {
            x[i] = p[lane + i * 32];
            s  += x[i].x + x[i].y + x[i].z + x[i].w;
            ss += x[i].x * x[i].x + x[i].y * x[i].y + x[i].z * x[i].z + x[i].w * x[i].w;
        }
#pragma unroll
        for (int o = 16; o; o >>= 1) {
            s  += __shfl_xor_sync(0xffffffffu, s, o);
            ss += __shfl_xor_sync(0xffffffffu, ss, o);
        }
        float mu = s * (1.f / 512.f);
        float rs = rsqrtf(ss * (1.f / 512.f) - mu * mu + LN_EPS);
#pragma unroll
        for (int i = 0; i < 4; i++) {
            float4 gg = ((const float4*)lng)[lane + i * 32];
            float4 bb = ((const float4*)lnb)[lane + i * 32];
            float y0 = (x[i].x - mu) * rs * gg.x + bb.x;
            float y1 = (x[i].y - mu) * rs * gg.y + bb.y;
            float y2 = (x[i].z - mu) * rs * gg.z + bb.z;
            float y3 = (x[i].w - mu) * rs * gg.w + bb.w;
            __nv_bfloat162 h01 = __floats2bfloat162_rn(y0, y1);
            __nv_bfloat162 h23 = __floats2bfloat162_rn(y2, y3);
            __nv_bfloat162 l01 = __floats2bfloat162_rn(y0 - __bfloat162float(h01.x),
                                                       y1 - __bfloat162float(h01.y));
            __nv_bfloat162 l23 = __floats2bfloat162_rn(y2 - __bfloat162float(h23.x),
                                                       y3 - __bfloat162float(h23.y));
            size_t off = (size_t)gw * DD + 4 * (lane + 32 * i);
            uint2 hv, lv;
            hv.x = *(uint32_t*)&h01; hv.y = *(uint32_t*)&h23;
            lv.x = *(uint32_t*)&l01; lv.y = *(uint32_t*)&l23;
            *(uint2*)&g_Ahi[off] = hv;
            *(uint2*)&g_Alo[off] = lv;
        }
    } else {
        int bx = blockIdx.x - 1536;
        int bz = bx >> 8; bx &= 255;
        const float* W = bz ? Wout : Win;
        size_t base = (size_t)bz * DD * DD;
        int k0 = (bx >> 4) * 32, n0 = (bx & 15) * 32;
        int tx = threadIdx.x & 31, ty = threadIdx.x >> 5;
#pragma unroll
        for (int i = 0; i < 4; i++)
            ts[ty + 8 * i][tx] = W[(size_t)(k0 + ty + 8 * i) * DD + n0 + tx];
        __syncthreads();
#pragma unroll
        for (int i = 0; i < 4; i++) {
            int n = n0 + ty + 8 * i, kk = k0 + tx;
            float val = ts[tx][ty + 8 * i];
            __nv_bfloat16 h = __float2bfloat16_rn(val);
            __nv_bfloat16 l = __float2bfloat16_rn(val - __bfloat162float(h));
            g_Bhi[base + (size_t)n * DD + kk] = h;
            g_Blo[base + (size_t)n * DD + kk] = l;
        }
    }
}

// ---------------- 2) HMMA GEMM, bf16x3 (GEMM1) ----------------
#define RS 40                      // smem row stride (bf16)
#define TILE_B (128 * RS * 2)      // 10240 bytes per operand tile
#define BUF_B  (4 * TILE_B)        // Ahi|Alo|Bhi|Blo per buffer
#define GEMM_SMEM (2 * BUF_B)      // 81920 bytes

__global__ void __launch_bounds__(256, 2) gemm_bf3(
    const __nv_bfloat16* __restrict__ Ahi, const __nv_bfloat16* __restrict__ Alo,
    const __nv_bfloat16* __restrict__ Bhi, const __nv_bfloat16* __restrict__ Blo,
    float* __restrict__ C)
{
    extern __shared__ char smem[];
    uint32_t sb = smem_u32(smem);
    int t = threadIdx.x, wid = t >> 5, lane = t & 31;
    int n0 = blockIdx.x * 128, m0 = blockIdx.y * 128;
    int wm = wid >> 2, wn = wid & 3;

    float acc[4][4][4];
#pragma unroll
    for (int i = 0; i < 4; i++)
#pragma unroll
        for (int j = 0; j < 4; j++)
#pragma unroll
            for (int r = 0; r < 4; r++) acc[i][j][r] = 0.f;

    int r0l = t >> 2, seg = t & 3;

    auto issue = [&](int c, int buf) {
        int k0 = c * 32;
        uint32_t d0 = sb + buf * BUF_B;
#pragma unroll
        for (int i = 0; i < 2; i++) {
            int row = r0l + i * 64;
            uint32_t doff = (row * RS + seg * 8) * 2;
            size_t ga = (size_t)(m0 + row) * DD + k0 + seg * 8;
            size_t gb = (size_t)(n0 + row) * DD + k0 + seg * 8;
            cp16(d0 + doff,              Ahi + ga);
            cp16(d0 + TILE_B + doff,     Alo + ga);
            cp16(d0 + 2 * TILE_B + doff, Bhi + gb);
            cp16(d0 + 3 * TILE_B + doff, Blo + gb);
        }
        cp_commit();
    };

    issue(0, 0);
    int g = lane >> 3, rl = lane & 7;

    for (int c = 0; c < 16; c++) {
        int buf = c & 1;
        if (c < 15) issue(c + 1, buf ^ 1);
        if (c < 15) asm volatile("cp.async.wait_group 1;");
        else        asm volatile("cp.async.wait_group 0;");
        __syncthreads();

        uint32_t aBase = sb + buf * BUF_B;
        uint32_t bBase = aBase + 2 * TILE_B;
#pragma unroll
        for (int h = 0; h < 2; h++) {
            uint32_t aH[4][4], aL[4][4];
#pragma unroll
            for (int it = 0; it < 4; it++) {
                int row = wm * 64 + it * 16 + rl + (g & 1) * 8;
                int kc  = h * 16 + (g & 2) * 4;
                uint32_t ad = aBase + (row * RS + kc) * 2;
                ldsm4(aH[it][0], aH[it][1], aH[it][2], aH[it][3], ad);
                ldsm4(aL[it][0], aL[it][1], aL[it][2], aL[it][3], ad + TILE_B);
            }
            uint32_t bH[4][2], bL[4][2];
#pragma unroll
            for (int jp = 0; jp < 2; jp++) {
                int row = wn * 32 + jp * 16 + rl + (g >> 1) * 8;
                int kc  = h * 16 + (g & 1) * 8;
                uint32_t bd = bBase + (row * RS + kc) * 2;
                ldsm4(bH[2 * jp][0], bH[2 * jp][1], bH[2 * jp + 1][0], bH[2 * jp + 1][1], bd);
                ldsm4(bL[2 * jp][0], bL[2 * jp][1], bL[2 * jp + 1][0], bL[2 * jp + 1][1],
                      bd + TILE_B);
            }
#pragma unroll
            for (int it = 0; it < 4; it++)
#pragma unroll
                for (int jt = 0; jt < 4; jt++) {
                    mma16816(acc[it][jt][0], acc[it][jt][1], acc[it][jt][2], acc[it][jt][3],
                             aH[it][0], aH[it][1], aH[it][2], aH[it][3],
                             bH[jt][0], bH[jt][1]);
                    mma16816(acc[it][jt][0], acc[it][jt][1], acc[it][jt][2], acc[it][jt][3],
                             aH[it][0], aH[it][1], aH[it][2], aH[it][3],
                             bL[jt][0], bL[jt][1]);
                    mma16816(acc[it][jt][0], acc[it][jt][1], acc[it][jt][2], acc[it][jt][3],
                             aL[it][0], aL[it][1], aL[it][2], aL[it][3],
                             bH[jt][0], bH[jt][1]);
                }
        }
        __syncthreads();
    }

    // ---------------- epilogue ----------------
    int rr = lane >> 2, cc = 2 * (lane & 3);
#pragma unroll
    for (int it = 0; it < 4; it++) {
        int row = m0 + wm * 64 + it * 16 + rr;
#pragma unroll
        for (int jt = 0; jt < 4; jt++) {
            int col = n0 + wn * 32 + jt * 8 + cc;
            *(float2*)&C[(size_t)row * DD + col] =
                make_float2(acc[it][jt][0], acc[it][jt][1]);
            *(float2*)&C[(size_t)(row + 8) * DD + col] =
                make_float2(acc[it][jt][2], acc[it][jt][3]);
        }
    }

    // fused per-head row stats (fq/fk rows only)
    if (m0 < 2 * RQ) {
        float* sred = (float*)smem;   // [wn][128 rows][2] = 4KB
#pragma unroll
        for (int it = 0; it < 4; it++) {
#pragma unroll
            for (int sub = 0; sub < 2; sub++) {
                float s = 0.f, ss = 0.f;
#pragma unroll
                for (int jt = 0; jt < 4; jt++) {
                    float v0 = acc[it][jt][2 * sub], v1 = acc[it][jt][2 * sub + 1];
                    s  += v0 + v1;
                    ss += v0 * v0 + v1 * v1;
                }
#pragma unroll
                for (int o = 1; o <= 2; o <<= 1) {
                    s  += __shfl_xor_sync(0xffffffffu, s, o);
                    ss += __shfl_xor_sync(0xffffffffu, ss, o);
                }
                if ((lane & 3) == 0) {
                    int lr = wm * 64 + it * 16 + rr + sub * 8;
                    sred[(wn * 128 + lr) * 2 + 0] = s;
                    sred[(wn * 128 + lr) * 2 + 1] = ss;
                }
            }
        }
        __syncthreads();
        int hp = t >> 7, lr = t & 127;
        float s  = sred[((2 * hp) * 128 + lr) * 2 + 0] +
                   sred[((2 * hp + 1) * 128 + lr) * 2 + 0];
        float ss = sred[((2 * hp) * 128 + lr) * 2 + 1] +
                   sred[((2 * hp + 1) * 128 + lr) * 2 + 1];
        int grow = m0 + lr;
        int tensor = grow >> 12;
        int b = (grow >> 10) & 3, m = grow & 1023;
        int h = (n0 >> 6) + hp;
        int idx = tensor * 32768 + (h * 4 + b) * 1024 + m;
        g_hmu[idx]   = s * (1.f / 64.f);
        g_hinvn[idx] = rsqrtf(ss);
        g_hvar[idx]  = (ss - s * s * (1.f / 64.f)) * (1.f / 63.f);
    }
}

// ---------------- 2b) GEMM2: CTA tile 64x128 ----------------
#define A64_B (64 * RS * 2)
#define BUF64 (2 * A64_B + 2 * TILE_B)
#define GEMM64_SMEM (2 * BUF64)

__global__ void __launch_bounds__(256, 2) gemm_bf3_m64(
    const __nv_bfloat16* __restrict__ Ahi, const __nv_bfloat16* __restrict__ Alo,
    const __nv_bfloat16* __restrict__ Bhi, const __nv_bfloat16* __restrict__ Blo,
    float* __restrict__ C, const float* __restrict__ bias)
{
    extern __shared__ char smem[];
    uint32_t sb = smem_u32(smem);
    int t = threadIdx.x, wid = t >> 5, lane = t & 31;
    int n0 = blockIdx.x * 128, m0 = blockIdx.y * 64;
    int wm = wid >> 2, wn = wid & 3;

    float acc[2][4][4];
#pragma unroll
    for (int i = 0; i < 2; i++)
#pragma unroll
        for (int j = 0; j < 4; j++)
#pragma unroll
            for (int r = 0; r < 4; r++) acc[i][j][r] = 0.f;

    auto issue = [&](int c, int buf) {
        int k0 = c * 32;
        uint32_t d0 = sb + buf * BUF64;
        {
            int row = t >> 2, seg = t & 3;
            uint32_t doff = (row * RS + seg * 8) * 2;
            size_t ga = (size_t)(m0 + row) * DD + k0 + seg * 8;
            cp16(d0 + doff,         Ahi + ga);
            cp16(d0 + A64_B + doff, Alo + ga);
        }
#pragma unroll
        for (int i = 0; i < 2; i++) {
            int u = t + i * 256;
            int row = u >> 2, seg = u & 3;
            uint32_t doff = (row * RS + seg * 8) * 2;
            size_t gb = (size_t)(n0 + row) * DD + k0 + seg * 8;
            cp16(d0 + 2 * A64_B + doff,          Bhi + gb);
            cp16(d0 + 2 * A64_B + TILE_B + doff, Blo + gb);
        }
        cp_commit();
    };

    issue(0, 0);
    int g = lane >> 3, rl = lane & 7;

    for (int c = 0; c < 16; c++) {
        int buf = c & 1;
        if (c < 15) issue(c + 1, buf ^ 1);
        if (c < 15) asm volatile("cp.async.wait_group 1;");
        else        asm volatile("cp.async.wait_group 0;");
        __syncthreads();

        uint32_t aBase = sb + buf * BUF64;
        uint32_t bBase = aBase + 2 * A64_B;
#pragma unroll
        for (int h = 0; h < 2; h++) {
            uint32_t aH[2][4], aL[2][4];
#pragma unroll
            for (int it = 0; it < 2; it++) {
                int row = wm * 32 + it * 16 + rl + (g & 1) * 8;
                int kc  = h * 16 + (g & 2) * 4;
                uint32_t ad = aBase + (row * RS + kc) * 2;
                ldsm4(aH[it][0], aH[it][1], aH[it][2], aH[it][3], ad);
                ldsm4(aL[it][0], aL[it][1], aL[it][2], aL[it][3], ad + A64_B);
            }
            uint32_t bH[4][2], bL[4][2];
#pragma unroll
            for (int jp = 0; jp < 2; jp++) {
                int row = wn * 32 + jp * 16 + rl + (g >> 1) * 8;
                int kc  = h * 16 + (g & 1) * 8;
                uint32_t bd = bBase + (row * RS + kc) * 2;
                ldsm4(bH[2 * jp][0], bH[2 * jp][1], bH[2 * jp + 1][0], bH[2 * jp + 1][1], bd);
                ldsm4(bL[2 * jp][0], bL[2 * jp][1], bL[2 * jp + 1][0], bL[2 * jp + 1][1],
                      bd + TILE_B);
            }
#pragma unroll
            for (int it = 0; it < 2; it++)
#pragma unroll
                for (int jt = 0; jt < 4; jt++) {
                    mma16816(acc[it][jt][0], acc[it][jt][1], acc[it][jt][2], acc[it][jt][3],
                             aH[it][0], aH[it][1], aH[it][2], aH[it][3],
                             bH[jt][0], bH[jt][1]);
                    mma16816(acc[it][jt][0], acc[it][jt][1], acc[it][jt][2], acc[it][jt][3],
                             aH[it][0], aH[it][1], aH[it][2], aH[it][3],
                             bL[jt][0], bL[jt][1]);
                    mma16816(acc[it][jt][0], acc[it][jt][1], acc[it][jt][2], acc[it][jt][3],
                             aL[it][0], aL[it][1], aL[it][2], aL[it][3],
                             bH[jt][0], bH[jt][1]);
                }
        }
        __syncthreads();
    }

    int rr = lane >> 2, cc = 2 * (lane & 3);
#pragma unroll
    for (int it = 0; it < 2; it++) {
        int row = m0 + wm * 32 + it * 16 + rr;
#pragma unroll
        for (int jt = 0; jt < 4; jt++) {
            int col = n0 + wn * 32 + jt * 8 + cc;
            float2 bb = *(const float2*)&bias[col];
            *(float2*)&C[(size_t)row * DD + col] =
                make_float2(acc[it][jt][0] + bb.x, acc[it][jt][1] + bb.y);
            *(float2*)&C[(size_t)(row + 8) * DD + col] =
                make_float2(acc[it][jt][2] + bb.x, acc[it][jt][3] + bb.y);
        }
    }
}

// ---------------- 3) G/H/r partials: 4 splits x 256 rows, cp.async ring ----------------
__global__ void __launch_bounds__(256, 4) macc()
{
    __shared__ float Ks[2][32][64];
    __shared__ float Vs[2][32][64];
    __shared__ float sikn[256], skv[256];
    int t = threadIdx.x;
    int pair  = blockIdx.x >> 2;
    int split = blockIdx.x & 3;
    int h = pair >> 2, b = pair & 3;
    const float* fk = g_f + (size_t)RQ * DD     + (size_t)(b * 1024) * DD + h * 64;
    const float* fv = g_f + (size_t)2 * RQ * DD + (size_t)(b * 1024) * DD + h * 64;
    int tx = t & 15, ty = t >> 4;
    int d0 = ty * 4, e0 = tx * 4;
    float G[4][4] = {}, Hm[4][4] = {}, ra[4] = {};
    int mbase0 = split * 256;
    uint32_t sK = smem_u32(Ks), sV = smem_u32(Vs);

    auto issue = [&](int c) {
        int mbase = mbase0 + c * 32;
        uint32_t bufo = (uint32_t)(c & 1) * (32 * 64 * 4);
#pragma unroll
        for (int i = 0; i < 2; i++) {
            int u = t + i * 256;
            int rr = u >> 4, c4 = (u & 15) * 4;
            uint32_t off = bufo + (rr * 64 + c4) * 4;
            cp16(sK + off, fk + (size_t)(mbase + rr) * DD + c4);
            cp16(sV + off, fv + (size_t)(mbase + rr) * DD + c4);
        }
        cp_commit();
    };

    issue(0);
    {
        int idx = 32768 + pair * 1024 + mbase0 + t;
        sikn[t] = g_hinvn[idx];
        skv[t]  = g_hvar[idx];
    }

    for (int c = 0; c < 8; c++) {
        if (c < 7) issue(c + 1);
        if (c < 7) asm volatile("cp.async.wait_group 1;");
        else       asm volatile("cp.async.wait_group 0;");
        __syncthreads();
        int buf = c & 1;
#pragma unroll 8
        for (int mm = 0; mm < 32; mm++) {
            float ikn = sikn[c * 32 + mm];
            float4 kk4 = *(float4*)&Ks[buf][mm][d0];
            float4 vv4 = *(float4*)&Vs[buf][mm][e0];
            float kk[4] = {kk4.x, kk4.y, kk4.z, kk4.w};
            float vv[4] = {vv4.x, vv4.y, vv4.z, vv4.w};
            float vn[4] = {vv4.x * ikn, vv4.y * ikn, vv4.z * ikn, vv4.w * ikn};
#pragma unroll
            for (int i = 0; i < 4; i++)
#pragma unroll
                for (int j = 0; j < 4; j++) {
                    G[i][j]  += kk[i] * vv[j];
                    Hm[i][j] += kk[i] * vn[j];
                }
        }
        if (ty == 0) {
#pragma unroll 8
            for (int mm = 0; mm < 32; mm++) {
                float kvv = skv[c * 32 + mm];
#pragma unroll
                for (int j = 0; j < 4; j++) ra[j] += kvv * Vs[buf][mm][e0 + j];
            }
        }
        __syncthreads();
    }
    float* mp = g_Mpart + (size_t)blockIdx.x * 8192;
#pragma unroll
    for (int i = 0; i < 4; i++)
#pragma unroll
        for (int j = 0; j < 4; j++) {
            mp[(d0 + i) * 64 + e0 + j]        = G[i][j];
            mp[4096 + (d0 + i) * 64 + e0 + j] = Hm[i][j];
        }
    if (ty == 0)
#pragma unroll
        for (int j = 0; j < 4; j++) g_rpart[blockIdx.x * 64 + e0 + j] = ra[j];
}

// ---------------- 4) apply v3: fused partial reduction, 64 rows/block ----------------
#define QS_S 65
#define APPLY_SMEM ((8192 + 64 * QS_S + 5 * 64) * 4)

__global__ void __launch_bounds__(256) apply_k(const float* __restrict__ cov_w,
                                               const float* __restrict__ var_w)
{
    extern __shared__ float sm[];
    float* Ms    = sm;
    float* qs    = sm + 8192;
    float* scs1  = sm + 8192 + 64 * QS_S;
    float* srs   = scs1 + 64;
    float* sbeta = srs + 64;
    float* sgam  = sbeta + 64;
    float* smual = sgam + 64;

    int t = threadIdx.x;
    int pair  = blockIdx.x >> 4;
    int ntile = blockIdx.x & 15;
    int h = pair >> 2, b = pair & 3;
    float cw = cov_w[0], vw = var_w[0];
    float w3 = 1.f - cw - vw;
    float alpha = cw * (1.f / 64.f);

    // fused reduction of 4 split partials (L2-resident) -> Ms
    const float4* mp0 = (const float4*)(g_Mpart + (size_t)(pair * SPLITS) * 8192);
#pragma unroll
    for (int i = 0; i < 8; i++) {
        int fi = t + i * 256;
        float4 a0 = __ldcg(mp0 + fi);
        float4 a1 = __ldcg(mp0 + 2048 + fi);
        float4 a2 = __ldcg(mp0 + 4096 + fi);
        float4 a3 = __ldcg(mp0 + 6144 + fi);
        float4 o;
        o.x = ((a0.x + a1.x) + a2.x) + a3.x;
        o.y = ((a0.y + a1.y) + a2.y) + a3.y;
        o.z = ((a0.z + a1.z) + a2.z) + a3.z;
        o.w = ((a0.w + a1.w) + a2.w) + a3.w;
        ((float4*)Ms)[fi] = o;
    }
    int n0 = ntile * 64;
    const float* fq = g_f + (size_t)(b * 1024 + n0) * DD + h * 64;
#pragma unroll
    for (int i = 0; i < 4; i++) {
        int fi = t + i * 256;
        int rr = fi >> 4, c4 = (fi & 15) * 4;
        float4 x = *(const float4*)(fq + (size_t)rr * DD + c4);
        qs[(c4 + 0) * QS_S + rr] = x.x;
        qs[(c4 + 1) * QS_S + rr] = x.y;
        qs[(c4 + 2) * QS_S + rr] = x.z;
        qs[(c4 + 3) * QS_S + rr] = x.w;
    }
    if (t < 64) {
        int idx = pair * 1024 + n0 + t;
        float mu = g_hmu[idx], invn = g_hinvn[idx], var = g_hvar[idx];
        sbeta[t] = w3 * invn;
        sgam[t]  = vw * (1.f / 64.f) * var;
        smual[t] = alpha * mu;
        float r = 0.f;
#pragma unroll
        for (int sp = 0; sp < SPLITS; sp++)
            r += __ldcg(&g_rpart[(pair * SPLITS + sp) * 64 + t]);
        srs[t] = r;
    }
    __syncthreads();
    if (t < 64) {
        float s = 0.f;
#pragma unroll
        for (int d = 0; d < 64; d++) s += Ms[d * 64 + t];
        scs1[t] = s;
    }
    __syncthreads();

    int tx = t & 15, ty = t >> 4;
    int e0 = tx * 4, r0 = ty * 4;
    float t1[4][4] = {}, t2[4][4] = {};
#pragma unroll 4
    for (int d = 0; d < 64; d++) {
        float4 m1 = *(float4*)&Ms[d * 64 + e0];
        float4 m2 = *(float4*)&Ms[4096 + d * 64 + e0];
        float qv[4];
#pragma unroll
        for (int i = 0; i < 4; i++) qv[i] = qs[d * QS_S + r0 + i];
#pragma unroll
        for (int i = 0; i < 4; i++) {
            t1[i][0] += qv[i] * m1.x; t1[i][1] += qv[i] * m1.y;
            t1[i][2] += qv[i] * m1.z; t1[i][3] += qv[i] * m1.w;
            t2[i][0] += qv[i] * m2.x; t2[i][1] += qv[i] * m2.y;
            t2[i][2] += qv[i] * m2.z; t2[i][3] += qv[i] * m2.w;
        }
    }
#pragma unroll
    for (int i = 0; i < 4; i++) {
        int row = r0 + i;
        int n = n0 + row;
        float beta = sbeta[row], gamma = sgam[row], mal = smual[row];
        float o0 = alpha * t1[i][0] - mal * scs1[e0 + 0] + beta * t2[i][0] + gamma * srs[e0 + 0];
        float o1 = alpha * t1[i][1] - mal * scs1[e0 + 1] + beta * t2[i][1] + gamma * srs[e0 + 1];
        float o2 = alpha * t1[i][2] - mal * scs1[e0 + 2] + beta * t2[i][2] + gamma * srs[e0 + 2];
        float o3 = alpha * t1[i][3] - mal * scs1[e0 + 3] + beta * t2[i][3] + gamma * srs[e0 + 3];
        __nv_bfloat162 h01 = __floats2bfloat162_rn(o0, o1);
        __nv_bfloat162 h23 = __floats2bfloat162_rn(o2, o3);
        __nv_bfloat162 l01 = __floats2bfloat162_rn(o0 - __bfloat162float(h01.x),
                                                   o1 - __bfloat162float(h01.y));
        __nv_bfloat162 l23 = __floats2bfloat162_rn(o2 - __bfloat162float(h23.x),
                                                   o3 - __bfloat162float(h23.y));
        size_t off = (size_t)(b * 1024 + n) * DD + h * 64 + e0;
        uint2 hv, lv;
        hv.x = *(uint32_t*)&h01; hv.y = *(uint32_t*)&h23;
        lv.x = *(uint32_t*)&l01; lv.y = *(uint32_t*)&l23;
        *(uint2*)&g_ghi[off] = hv;
        *(uint2*)&g_glo[off] = lv;
    }
}

// ---------------- launch ----------------
extern "C" void kernel_launch(void* const* d_in, const int* in_sizes, int n_in,
                              void* d_out, int out_size)
{
    const float* q     = (const float*)d_in[0];
    const float* k     = (const float*)d_in[1];
    const float* v     = (const float*)d_in[2];
    const float* ln_g  = (const float*)d_in[3];
    const float* ln_b  = (const float*)d_in[4];
    const float* W_in  = (const float*)d_in[5];
    const float* W_out = (const float*)d_in[6];
    const float* b_out = (const float*)d_in[7];
    const float* cov_w = (const float*)d_in[8];
    const float* var_w = (const float*)d_in[9];
    float* out = (float*)d_out;

    cudaFuncSetAttribute(gemm_bf3, cudaFuncAttributeMaxDynamicSharedMemorySize, GEMM_SMEM);
    cudaFuncSetAttribute(gemm_bf3_m64, cudaFuncAttributeMaxDynamicSharedMemorySize, GEMM64_SMEM);
    cudaFuncSetAttribute(apply_k, cudaFuncAttributeMaxDynamicSharedMemorySize, APPLY_SMEM);

    __nv_bfloat16 *Ahi, *Alo, *Bhi, *Blo, *ghi, *glo;
    float* f;
    cudaGetSymbolAddress((void**)&Ahi, g_Ahi);
    cudaGetSymbolAddress((void**)&Alo, g_Alo);
    cudaGetSymbolAddress((void**)&Bhi, g_Bhi);
    cudaGetSymbolAddress((void**)&Blo, g_Blo);
    cudaGetSymbolAddress((void**)&ghi, g_ghi);
    cudaGetSymbolAddress((void**)&glo, g_glo);
    cudaGetSymbolAddress((void**)&f,   g_f);

    prep<<<1536 + 512, 256>>>(q, k, v, ln_g, ln_b, W_in, W_out);
    gemm_bf3<<<dim3(4, 96), 256, GEMM_SMEM>>>(Ahi, Alo, Bhi, Blo, f);
    macc<<<NPAIR * SPLITS, 256>>>();
    apply_k<<<NPAIR * 16, 256, APPLY_SMEM>>>(cov_w, var_w);
    gemm_bf3_m64<<<dim3(4, 64), 256, GEMM64_SMEM>>>(ghi, glo, Bhi + DD * DD, Blo + DD * DD,
                                                    out, b_out);
}

// round 14
// speedup vs baseline: 1.1461x; 1.0277x over previous
#include <cuda_runtime.h>
#include <cuda_bf16.h>
#include <cstdint>

// Problem constants: B=4, S=1024, D=512, H=8, DH=64
#define RQ   4096
#define R3   12288
#define DD   512
#define NPAIR 32
#define SPLITS 4
#define LN_EPS 1e-5f

// ---------------- scratch ----------------
__device__ float         g_f[3 * RQ * DD];        // fp32 f_q|f_k|f_v
__device__ __nv_bfloat16 g_Ahi[R3 * DD];
__device__ __nv_bfloat16 g_Alo[R3 * DD];
__device__ __nv_bfloat16 g_Bhi[2 * DD * DD];      // W_in^T | W_out^T (hi)
__device__ __nv_bfloat16 g_Blo[2 * DD * DD];
__device__ __nv_bfloat16 g_ghi[RQ * DD];
__device__ __nv_bfloat16 g_glo[RQ * DD];
__device__ float g_hmu[2 * NPAIR * 1024];
__device__ float g_hinvn[2 * NPAIR * 1024];
__device__ float g_hvar[2 * NPAIR * 1024];
__device__ float g_Mpart[NPAIR * SPLITS * 2 * 4096];
__device__ float g_rpart[NPAIR * SPLITS * 64];

// ---------------- helpers ----------------
__device__ __forceinline__ uint32_t smem_u32(const void* p) {
    uint32_t a;
    asm("{ .reg .u64 t; cvta.to.shared.u64 t, %1; cvt.u32.u64 %0, t; }" : "=r"(a) : "l"(p));
    return a;
}
__device__ __forceinline__ void cp16(uint32_t dst, const void* src) {
    asm volatile("cp.async.cg.shared.global [%0], [%1], 16;" :: "r"(dst), "l"(src));
}
__device__ __forceinline__ void cp_commit() {
    asm volatile("cp.async.commit_group;");
}
__device__ __forceinline__ void ldsm4(uint32_t& r0, uint32_t& r1, uint32_t& r2, uint32_t& r3,
                                      uint32_t addr) {
    asm volatile("ldmatrix.sync.aligned.m8n8.x4.shared.b16 {%0,%1,%2,%3}, [%4];"
                 : "=r"(r0), "=r"(r1), "=r"(r2), "=r"(r3) : "r"(addr));
}
__device__ __forceinline__ void mma16816(float& c0, float& c1, float& c2, float& c3,
                                         uint32_t a0, uint32_t a1, uint32_t a2, uint32_t a3,
                                         uint32_t b0, uint32_t b1) {
    asm volatile(
        "mma.sync.aligned.m16n8k16.row.col.f32.bf16.bf16.f32 "
        "{%0,%1,%2,%3}, {%4,%5,%6,%7}, {%8,%9}, {%0,%1,%2,%3};"
        : "+f"(c0), "+f"(c1), "+f"(c2), "+f"(c3)
        : "r"(a0), "r"(a1), "r"(a2), "r"(a3), "r"(b0), "r"(b1));
}

// ---------------- 1) merged prep: LN+split | W transpose+split ----------------
__global__ void __launch_bounds__(256) prep(
    const float* __restrict__ q, const float* __restrict__ k,
    const float* __restrict__ v, const float* __restrict__ lng,
    const float* __restrict__ lnb, const float* __restrict__ Win,
    const float* __restrict__ Wout)
{
    __shared__ float ts[32][33];
    if (blockIdx.x < 1536) {
        int gw   = blockIdx.x * 8 + (threadIdx.x >> 5);
        int lane = threadIdx.x & 31;
        const float* src = (gw < RQ) ? q : (gw < 2 * RQ ? k : v);
        int row = gw & (RQ - 1);
        const float4* p = (const float4*)(src + (size_t)row * DD);
        float4 x[4];
        float s = 0.f, ss = 0.f;
#pragma unroll
        for (int i = 0; i < 4; i++) {
            x[i] = p[lane + i * 32];
            s  += x[i].x + x[i].y + x[i].z + x[i].w;
            ss += x[i].x * x[i].x + x[i].y * x[i].y + x[i].z * x[i].z + x[i].w * x[i].w;
        }
#pragma unroll
        for (int o = 16; o; o >>= 1) {
            s  += __shfl_xor_sync(0xffffffffu, s, o);
            ss += __shfl_xor_sync(0xffffffffu, ss, o);
        }
        float mu = s * (1.f / 512.f);
        float rs = rsqrtf(ss * (1.f / 512.f) - mu * mu + LN_EPS);
#pragma unroll
        for (int i = 0; i < 4; i++) {
            float4 gg = ((const float4*)lng)[lane + i * 32];
            float4 bb = ((const float4*)lnb)[lane + i * 32];
            float y0 = (x[i].x - mu) * rs * gg.x + bb.x;
            float y1 = (x[i].y - mu) * rs * gg.y + bb.y;
            float y2 = (x[i].z - mu) * rs * gg.z + bb.z;
            float y3 = (x[i].w - mu) * rs * gg.w + bb.w;
            __nv_bfloat162 h01 = __floats2bfloat162_rn(y0, y1);
            __nv_bfloat162 h23 = __floats2bfloat162_rn(y2, y3);
            __nv_bfloat162 l01 = __floats2bfloat162_rn(y0 - __bfloat162float(h01.x),
                                                       y1 - __bfloat162float(h01.y));
            __nv_bfloat162 l23 = __floats2bfloat162_rn(y2 - __bfloat162float(h23.x),
                                                       y3 - __bfloat162float(h23.y));
            size_t off = (size_t)gw * DD + 4 * (lane + 32 * i);
            uint2 hv, lv;
            hv.x = *(uint32_t*)&h01; hv.y = *(uint32_t*)&h23;
            lv.x = *(uint32_t*)&l01; lv.y = *(uint32_t*)&l23;
            *(uint2*)&g_Ahi[off] = hv;
            *(uint2*)&g_Alo[off] = lv;
        }
    } else {
        int bx = blockIdx.x - 1536;
        int bz = bx >> 8; bx &= 255;
        const float* W = bz ? Wout : Win;
        size_t base = (size_t)bz * DD * DD;
        int k0 = (bx >> 4) * 32, n0 = (bx & 15) * 32;
        int tx = threadIdx.x & 31, ty = threadIdx.x >> 5;
#pragma unroll
        for (int i = 0; i < 4; i++)
            ts[ty + 8 * i][tx] = W[(size_t)(k0 + ty + 8 * i) * DD + n0 + tx];
        __syncthreads();
#pragma unroll
        for (int i = 0; i < 4; i++) {
            int n = n0 + ty + 8 * i, kk = k0 + tx;
            float val = ts[tx][ty + 8 * i];
            __nv_bfloat16 h = __float2bfloat16_rn(val);
            __nv_bfloat16 l = __float2bfloat16_rn(val - __bfloat162float(h));
            g_Bhi[base + (size_t)n * DD + kk] = h;
            g_Blo[base + (size_t)n * DD + kk] = l;
        }
    }
}

// ---------------- 2) HMMA GEMM, bf16x3 (GEMM1) ----------------
#define RS 40                      // smem row stride (bf16)
#define TILE_B (128 * RS * 2)      // 10240 bytes per operand tile
#define BUF_B  (4 * TILE_B)        // Ahi|Alo|Bhi|Blo per buffer
#define GEMM_SMEM (2 * BUF_B)      // 81920 bytes

__global__ void __launch_bounds__(256, 2) gemm_bf3(
    const __nv_bfloat16* __restrict__ Ahi, const __nv_bfloat16* __restrict__ Alo,
    const __nv_bfloat16* __restrict__ Bhi, const __nv_bfloat16* __restrict__ Blo,
    float* __restrict__ C)
{
    extern __shared__ char smem[];
    uint32_t sb = smem_u32(smem);
    int t = threadIdx.x, wid = t >> 5, lane = t & 31;
    int n0 = blockIdx.x * 128, m0 = blockIdx.y * 128;
    int wm = wid >> 2, wn = wid & 3;

    float acc[4][4][4];
#pragma unroll
    for (int i = 0; i < 4; i++)
#pragma unroll
        for (int j = 0; j < 4; j++)
#pragma unroll
            for (int r = 0; r < 4; r++) acc[i][j][r] = 0.f;

    int r0l = t >> 2, seg = t & 3;

    auto issue = [&](int c, int buf) {
        int k0 = c * 32;
        uint32_t d0 = sb + buf * BUF_B;
#pragma unroll
        for (int i = 0; i < 2; i++) {
            int row = r0l + i * 64;
            uint32_t doff = (row * RS + seg * 8) * 2;
            size_t ga = (size_t)(m0 + row) * DD + k0 + seg * 8;
            size_t gb = (size_t)(n0 + row) * DD + k0 + seg * 8;
            cp16(d0 + doff,              Ahi + ga);
            cp16(d0 + TILE_B + doff,     Alo + ga);
            cp16(d0 + 2 * TILE_B + doff, Bhi + gb);
            cp16(d0 + 3 * TILE_B + doff, Blo + gb);
        }
        cp_commit();
    };

    issue(0, 0);
    int g = lane >> 3, rl = lane & 7;

    for (int c = 0; c < 16; c++) {
        int buf = c & 1;
        if (c < 15) issue(c + 1, buf ^ 1);
        if (c < 15) asm volatile("cp.async.wait_group 1;");
        else        asm volatile("cp.async.wait_group 0;");
        __syncthreads();

        uint32_t aBase = sb + buf * BUF_B;
        uint32_t bBase = aBase + 2 * TILE_B;
#pragma unroll
        for (int h = 0; h < 2; h++) {
            uint32_t aH[4][4], aL[4][4];
#pragma unroll
            for (int it = 0; it < 4; it++) {
                int row = wm * 64 + it * 16 + rl + (g & 1) * 8;
                int kc  = h * 16 + (g & 2) * 4;
                uint32_t ad = aBase + (row * RS + kc) * 2;
                ldsm4(aH[it][0], aH[it][1], aH[it][2], aH[it][3], ad);
                ldsm4(aL[it][0], aL[it][1], aL[it][2], aL[it][3], ad + TILE_B);
            }
            uint32_t bH[4][2], bL[4][2];
#pragma unroll
            for (int jp = 0; jp < 2; jp++) {
                int row = wn * 32 + jp * 16 + rl + (g >> 1) * 8;
                int kc  = h * 16 + (g & 1) * 8;
                uint32_t bd = bBase + (row * RS + kc) * 2;
                ldsm4(bH[2 * jp][0], bH[2 * jp][1], bH[2 * jp + 1][0], bH[2 * jp + 1][1], bd);
                ldsm4(bL[2 * jp][0], bL[2 * jp][1], bL[2 * jp + 1][0], bL[2 * jp + 1][1],
                      bd + TILE_B);
            }
#pragma unroll
            for (int it = 0; it < 4; it++)
#pragma unroll
                for (int jt = 0; jt < 4; jt++) {
                    mma16816(acc[it][jt][0], acc[it][jt][1], acc[it][jt][2], acc[it][jt][3],
                             aH[it][0], aH[it][1], aH[it][2], aH[it][3],
                             bH[jt][0], bH[jt][1]);
                    mma16816(acc[it][jt][0], acc[it][jt][1], acc[it][jt][2], acc[it][jt][3],
                             aH[it][0], aH[it][1], aH[it][2], aH[it][3],
                             bL[jt][0], bL[jt][1]);
                    mma16816(acc[it][jt][0], acc[it][jt][1], acc[it][jt][2], acc[it][jt][3],
                             aL[it][0], aL[it][1], aL[it][2], aL[it][3],
                             bH[jt][0], bH[jt][1]);
                }
        }
        __syncthreads();
    }

    // ---------------- epilogue ----------------
    int rr = lane >> 2, cc = 2 * (lane & 3);
#pragma unroll
    for (int it = 0; it < 4; it++) {
        int row = m0 + wm * 64 + it * 16 + rr;
#pragma unroll
        for (int jt = 0; jt < 4; jt++) {
            int col = n0 + wn * 32 + jt * 8 + cc;
            *(float2*)&C[(size_t)row * DD + col] =
                make_float2(acc[it][jt][0], acc[it][jt][1]);
            *(float2*)&C[(size_t)(row + 8) * DD + col] =
                make_float2(acc[it][jt][2], acc[it][jt][3]);
        }
    }

    // fused per-head row stats (fq/fk rows only)
    if (m0 < 2 * RQ) {
        float* sred = (float*)smem;
#pragma unroll
        for (int it = 0; it < 4; it++) {
#pragma unroll
            for (int sub = 0; sub < 2; sub++) {
                float s = 0.f, ss = 0.f;
#pragma unroll
                for (int jt = 0; jt < 4; jt++) {
                    float v0 = acc[it][jt][2 * sub], v1 = acc[it][jt][2 * sub + 1];
                    s  += v0 + v1;
                    ss += v0 * v0 + v1 * v1;
                }
#pragma unroll
                for (int o = 1; o <= 2; o <<= 1) {
                    s  += __shfl_xor_sync(0xffffffffu, s, o);
                    ss += __shfl_xor_sync(0xffffffffu, ss, o);
                }
                if ((lane & 3) == 0) {
                    int lr = wm * 64 + it * 16 + rr + sub * 8;
                    sred[(wn * 128 + lr) * 2 + 0] = s;
                    sred[(wn * 128 + lr) * 2 + 1] = ss;
                }
            }
        }
        __syncthreads();
        int hp = t >> 7, lr = t & 127;
        float s  = sred[((2 * hp) * 128 + lr) * 2 + 0] +
                   sred[((2 * hp + 1) * 128 + lr) * 2 + 0];
        float ss = sred[((2 * hp) * 128 + lr) * 2 + 1] +
                   sred[((2 * hp + 1) * 128 + lr) * 2 + 1];
        int grow = m0 + lr;
        int tensor = grow >> 12;
        int b = (grow >> 10) & 3, m = grow & 1023;
        int h = (n0 >> 6) + hp;
        int idx = tensor * 32768 + (h * 4 + b) * 1024 + m;
        g_hmu[idx]   = s * (1.f / 64.f);
        g_hinvn[idx] = rsqrtf(ss);
        g_hvar[idx]  = (ss - s * s * (1.f / 64.f)) * (1.f / 63.f);
    }
}

// ---------------- 2b) GEMM2: CTA tile 64x128 ----------------
#define A64_B (64 * RS * 2)
#define BUF64 (2 * A64_B + 2 * TILE_B)
#define GEMM64_SMEM (2 * BUF64)

__global__ void __launch_bounds__(256, 2) gemm_bf3_m64(
    const __nv_bfloat16* __restrict__ Ahi, const __nv_bfloat16* __restrict__ Alo,
    const __nv_bfloat16* __restrict__ Bhi, const __nv_bfloat16* __restrict__ Blo,
    float* __restrict__ C, const float* __restrict__ bias)
{
    extern __shared__ char smem[];
    uint32_t sb = smem_u32(smem);
    int t = threadIdx.x, wid = t >> 5, lane = t & 31;
    int n0 = blockIdx.x * 128, m0 = blockIdx.y * 64;
    int wm = wid >> 2, wn = wid & 3;

    float acc[2][4][4];
#pragma unroll
    for (int i = 0; i < 2; i++)
#pragma unroll
        for (int j = 0; j < 4; j++)
#pragma unroll
            for (int r = 0; r < 4; r++) acc[i][j][r] = 0.f;

    auto issue = [&](int c, int buf) {
        int k0 = c * 32;
        uint32_t d0 = sb + buf * BUF64;
        {
            int row = t >> 2, seg = t & 3;
            uint32_t doff = (row * RS + seg * 8) * 2;
            size_t ga = (size_t)(m0 + row) * DD + k0 + seg * 8;
            cp16(d0 + doff,         Ahi + ga);
            cp16(d0 + A64_B + doff, Alo + ga);
        }
#pragma unroll
        for (int i = 0; i < 2; i++) {
            int u = t + i * 256;
            int row = u >> 2, seg = u & 3;
            uint32_t doff = (row * RS + seg * 8) * 2;
            size_t gb = (size_t)(n0 + row) * DD + k0 + seg * 8;
            cp16(d0 + 2 * A64_B + doff,          Bhi + gb);
            cp16(d0 + 2 * A64_B + TILE_B + doff, Blo + gb);
        }
        cp_commit();
    };

    issue(0, 0);
    int g = lane >> 3, rl = lane & 7;

    for (int c = 0; c < 16; c++) {
        int buf = c & 1;
        if (c < 15) issue(c + 1, buf ^ 1);
        if (c < 15) asm volatile("cp.async.wait_group 1;");
        else        asm volatile("cp.async.wait_group 0;");
        __syncthreads();

        uint32_t aBase = sb + buf * BUF64;
        uint32_t bBase = aBase + 2 * A64_B;
#pragma unroll
        for (int h = 0; h < 2; h++) {
            uint32_t aH[2][4], aL[2][4];
#pragma unroll
            for (int it = 0; it < 2; it++) {
                int row = wm * 32 + it * 16 + rl + (g & 1) * 8;
                int kc  = h * 16 + (g & 2) * 4;
                uint32_t ad = aBase + (row * RS + kc) * 2;
                ldsm4(aH[it][0], aH[it][1], aH[it][2], aH[it][3], ad);
                ldsm4(aL[it][0], aL[it][1], aL[it][2], aL[it][3], ad + A64_B);
            }
            uint32_t bH[4][2], bL[4][2];
#pragma unroll
            for (int jp = 0; jp < 2; jp++) {
                int row = wn * 32 + jp * 16 + rl + (g >> 1) * 8;
                int kc  = h * 16 + (g & 1) * 8;
                uint32_t bd = bBase + (row * RS + kc) * 2;
                ldsm4(bH[2 * jp][0], bH[2 * jp][1], bH[2 * jp + 1][0], bH[2 * jp + 1][1], bd);
                ldsm4(bL[2 * jp][0], bL[2 * jp][1], bL[2 * jp + 1][0], bL[2 * jp + 1][1],
                      bd + TILE_B);
            }
#pragma unroll
            for (int it = 0; it < 2; it++)
#pragma unroll
                for (int jt = 0; jt < 4; jt++) {
                    mma16816(acc[it][jt][0], acc[it][jt][1], acc[it][jt][2], acc[it][jt][3],
                             aH[it][0], aH[it][1], aH[it][2], aH[it][3],
                             bH[jt][0], bH[jt][1]);
                    mma16816(acc[it][jt][0], acc[it][jt][1], acc[it][jt][2], acc[it][jt][3],
                             aH[it][0], aH[it][1], aH[it][2], aH[it][3],
                             bL[jt][0], bL[jt][1]);
                    mma16816(acc[it][jt][0], acc[it][jt][1], acc[it][jt][2], acc[it][jt][3],
                             aL[it][0], aL[it][1], aL[it][2], aL[it][3],
                             bH[jt][0], bH[jt][1]);
                }
        }
        __syncthreads();
    }

    int rr = lane >> 2, cc = 2 * (lane & 3);
#pragma unroll
    for (int it = 0; it < 2; it++) {
        int row = m0 + wm * 32 + it * 16 + rr;
#pragma unroll
        for (int jt = 0; jt < 4; jt++) {
            int col = n0 + wn * 32 + jt * 8 + cc;
            float2 bb = *(const float2*)&bias[col];
            *(float2*)&C[(size_t)row * DD + col] =
                make_float2(acc[it][jt][0] + bb.x, acc[it][jt][1] + bb.y);
            *(float2*)&C[(size_t)(row + 8) * DD + col] =
                make_float2(acc[it][jt][2] + bb.x, acc[it][jt][3] + bb.y);
        }
    }
}

// ---------------- 3) G/H/r partials: 4 splits x 256 rows, cp.async ring ----------------
__global__ void __launch_bounds__(256, 4) macc()
{
    __shared__ float Ks[2][32][64];
    __shared__ float Vs[2][32][64];
    __shared__ float sikn[256], skv[256];
    int t = threadIdx.x;
    int pair  = blockIdx.x >> 2;
    int split = blockIdx.x & 3;
    int h = pair >> 2, b = pair & 3;
    const float* fk = g_f + (size_t)RQ * DD     + (size_t)(b * 1024) * DD + h * 64;
    const float* fv = g_f + (size_t)2 * RQ * DD + (size_t)(b * 1024) * DD + h * 64;
    int tx = t & 15, ty = t >> 4;
    int d0 = ty * 4, e0 = tx * 4;
    float G[4][4] = {}, Hm[4][4] = {}, ra[4] = {};
    int mbase0 = split * 256;
    uint32_t sK = smem_u32(Ks), sV = smem_u32(Vs);

    auto issue = [&](int c) {
        int mbase = mbase0 + c * 32;
        uint32_t bufo = (uint32_t)(c & 1) * (32 * 64 * 4);
#pragma unroll
        for (int i = 0; i < 2; i++) {
            int u = t + i * 256;
            int rr = u >> 4, c4 = (u & 15) * 4;
            uint32_t off = bufo + (rr * 64 + c4) * 4;
            cp16(sK + off, fk + (size_t)(mbase + rr) * DD + c4);
            cp16(sV + off, fv + (size_t)(mbase + rr) * DD + c4);
        }
        cp_commit();
    };

    issue(0);
    {
        int idx = 32768 + pair * 1024 + mbase0 + t;
        sikn[t] = g_hinvn[idx];
        skv[t]  = g_hvar[idx];
    }

    for (int c = 0; c < 8; c++) {
        if (c < 7) issue(c + 1);
        if (c < 7) asm volatile("cp.async.wait_group 1;");
        else       asm volatile("cp.async.wait_group 0;");
        __syncthreads();
        int buf = c & 1;
#pragma unroll 8
        for (int mm = 0; mm < 32; mm++) {
            float ikn = sikn[c * 32 + mm];
            float4 kk4 = *(float4*)&Ks[buf][mm][d0];
            float4 vv4 = *(float4*)&Vs[buf][mm][e0];
            float kk[4] = {kk4.x, kk4.y, kk4.z, kk4.w};
            float vv[4] = {vv4.x, vv4.y, vv4.z, vv4.w};
            float vn[4] = {vv4.x * ikn, vv4.y * ikn, vv4.z * ikn, vv4.w * ikn};
#pragma unroll
            for (int i = 0; i < 4; i++)
#pragma unroll
                for (int j = 0; j < 4; j++) {
                    G[i][j]  += kk[i] * vv[j];
                    Hm[i][j] += kk[i] * vn[j];
                }
        }
        if (ty == 0) {
#pragma unroll 8
            for (int mm = 0; mm < 32; mm++) {
                float kvv = skv[c * 32 + mm];
#pragma unroll
                for (int j = 0; j < 4; j++) ra[j] += kvv * Vs[buf][mm][e0 + j];
            }
        }
        __syncthreads();
    }
    float* mp = g_Mpart + (size_t)blockIdx.x * 8192;
#pragma unroll
    for (int i = 0; i < 4; i++)
#pragma unroll
        for (int j = 0; j < 4; j++) {
            mp[(d0 + i) * 64 + e0 + j]        = G[i][j];
            mp[4096 + (d0 + i) * 64 + e0 + j] = Hm[i][j];
        }
    if (ty == 0)
#pragma unroll
        for (int j = 0; j < 4; j++) g_rpart[blockIdx.x * 64 + e0 + j] = ra[j];
}

// ---------------- 4) apply v4: fused reduce, 128 rows/block, 8 rows/thread ----------------
#define QS2 129
#define APPLY_SMEM ((8192 + 64 * QS2 + 64 + 64 + 3 * 128 + 256) * 4)

__global__ void __launch_bounds__(256) apply_k(const float* __restrict__ cov_w,
                                               const float* __restrict__ var_w)
{
    extern __shared__ float sm[];
    float* Ms    = sm;                       // 8192
    float* qs    = sm + 8192;                // 64 x QS2
    float* scs1  = qs + 64 * QS2;            // 64
    float* srs   = scs1 + 64;                // 64
    float* sbeta = srs + 64;                 // 128
    float* sgam  = sbeta + 128;              // 128
    float* smual = sgam + 128;               // 128
    float* spart = smual + 128;              // 256

    int t = threadIdx.x;
    int pair  = blockIdx.x >> 3;
    int ntile = blockIdx.x & 7;
    int h = pair >> 2, b = pair & 3;
    float cw = cov_w[0], vw = var_w[0];
    float w3 = 1.f - cw - vw;
    float alpha = cw * (1.f / 64.f);

    // fused reduction of 4 split partials (L2-resident) -> Ms
    const float4* mp0 = (const float4*)(g_Mpart + (size_t)(pair * SPLITS) * 8192);
#pragma unroll
    for (int i = 0; i < 8; i++) {
        int fi = t + i * 256;
        float4 a0 = __ldcg(mp0 + fi);
        float4 a1 = __ldcg(mp0 + 2048 + fi);
        float4 a2 = __ldcg(mp0 + 4096 + fi);
        float4 a3 = __ldcg(mp0 + 6144 + fi);
        float4 o;
        o.x = ((a0.x + a1.x) + a2.x) + a3.x;
        o.y = ((a0.y + a1.y) + a2.y) + a3.y;
        o.z = ((a0.z + a1.z) + a2.z) + a3.z;
        o.w = ((a0.w + a1.w) + a2.w) + a3.w;
        ((float4*)Ms)[fi] = o;
    }
    int n0 = ntile * 128;
    const float* fq = g_f + (size_t)(b * 1024 + n0) * DD + h * 64;
    // load 128 rows x 64 cols transposed: qs[d][row]
#pragma unroll
    for (int i = 0; i < 8; i++) {
        int fi = t + i * 256;
        int rr = fi >> 4, c4 = (fi & 15) * 4;
        float4 x = *(const float4*)(fq + (size_t)rr * DD + c4);
        qs[(c4 + 0) * QS2 + rr] = x.x;
        qs[(c4 + 1) * QS2 + rr] = x.y;
        qs[(c4 + 2) * QS2 + rr] = x.z;
        qs[(c4 + 3) * QS2 + rr] = x.w;
    }
    if (t < 128) {
        int idx = pair * 1024 + n0 + t;
        float mu = g_hmu[idx], invn = g_hinvn[idx], var = g_hvar[idx];
        sbeta[t] = w3 * invn;
        sgam[t]  = vw * (1.f / 64.f) * var;
        smual[t] = alpha * mu;
    }
    if (t < 64) {
        float r = 0.f;
#pragma unroll
        for (int sp = 0; sp < SPLITS; sp++)
            r += __ldcg(&g_rpart[(pair * SPLITS + sp) * 64 + t]);
        srs[t] = r;
    }
    __syncthreads();
    // parallel column-sum of M1 (4 partials x 16 d each)
    {
        int col = t & 63, grp = t >> 6;
        float s = 0.f;
#pragma unroll
        for (int d = 0; d < 16; d++) s += Ms[(grp * 16 + d) * 64 + col];
        spart[t] = s;
    }
    __syncthreads();
    if (t < 64)
        scs1[t] = ((spart[t] + spart[64 + t]) + spart[128 + t]) + spart[192 + t];
    __syncthreads();

    int tx = t & 15, ty = t >> 4;
    int e0 = tx * 4, r0 = ty * 8;
    float t1[8][4] = {}, t2[8][4] = {};
#pragma unroll 4
    for (int d = 0; d < 64; d++) {
        float4 m1 = *(float4*)&Ms[d * 64 + e0];
        float4 m2 = *(float4*)&Ms[4096 + d * 64 + e0];
        float qv[8];
#pragma unroll
        for (int i = 0; i < 8; i++) qv[i] = qs[d * QS2 + r0 + i];
#pragma unroll
        for (int i = 0; i < 8; i++) {
            t1[i][0] += qv[i] * m1.x; t1[i][1] += qv[i] * m1.y;
            t1[i][2] += qv[i] * m1.z; t1[i][3] += qv[i] * m1.w;
            t2[i][0] += qv[i] * m2.x; t2[i][1] += qv[i] * m2.y;
            t2[i][2] += qv[i] * m2.z; t2[i][3] += qv[i] * m2.w;
        }
    }
#pragma unroll
    for (int i = 0; i < 8; i++) {
        int row = r0 + i;
        int n = n0 + row;
        float beta = sbeta[row], gamma = sgam[row], mal = smual[row];
        float o0 = alpha * t1[i][0] - mal * scs1[e0 + 0] + beta * t2[i][0] + gamma * srs[e0 + 0];
        float o1 = alpha * t1[i][1] - mal * scs1[e0 + 1] + beta * t2[i][1] + gamma * srs[e0 + 1];
        float o2 = alpha * t1[i][2] - mal * scs1[e0 + 2] + beta * t2[i][2] + gamma * srs[e0 + 2];
        float o3 = alpha * t1[i][3] - mal * scs1[e0 + 3] + beta * t2[i][3] + gamma * srs[e0 + 3];
        __nv_bfloat162 h01 = __floats2bfloat162_rn(o0, o1);
        __nv_bfloat162 h23 = __floats2bfloat162_rn(o2, o3);
        __nv_bfloat162 l01 = __floats2bfloat162_rn(o0 - __bfloat162float(h01.x),
                                                   o1 - __bfloat162float(h01.y));
        __nv_bfloat162 l23 = __floats2bfloat162_rn(o2 - __bfloat162float(h23.x),
                                                   o3 - __bfloat162float(h23.y));
        size_t off = (size_t)(b * 1024 + n) * DD + h * 64 + e0;
        uint2 hv, lv;
        hv.x = *(uint32_t*)&h01; hv.y = *(uint32_t*)&h23;
        lv.x = *(uint32_t*)&l01; lv.y = *(uint32_t*)&l23;
        *(uint2*)&g_ghi[off] = hv;
        *(uint2*)&g_glo[off] = lv;
    }
}

// ---------------- launch ----------------
extern "C" void kernel_launch(void* const* d_in, const int* in_sizes, int n_in,
                              void* d_out, int out_size)
{
    const float* q     = (const float*)d_in[0];
    const float* k     = (const float*)d_in[1];
    const float* v     = (const float*)d_in[2];
    const float* ln_g  = (const float*)d_in[3];
    const float* ln_b  = (const float*)d_in[4];
    const float* W_in  = (const float*)d_in[5];
    const float* W_out = (const float*)d_in[6];
    const float* b_out = (const float*)d_in[7];
    const float* cov_w = (const float*)d_in[8];
    const float* var_w = (const float*)d_in[9];
    float* out = (float*)d_out;

    cudaFuncSetAttribute(gemm_bf3, cudaFuncAttributeMaxDynamicSharedMemorySize, GEMM_SMEM);
    cudaFuncSetAttribute(gemm_bf3_m64, cudaFuncAttributeMaxDynamicSharedMemorySize, GEMM64_SMEM);
    cudaFuncSetAttribute(apply_k, cudaFuncAttributeMaxDynamicSharedMemorySize, APPLY_SMEM);

    __nv_bfloat16 *Ahi, *Alo, *Bhi, *Blo, *ghi, *glo;
    float* f;
    cudaGetSymbolAddress((void**)&Ahi, g_Ahi);
    cudaGetSymbolAddress((void**)&Alo, g_Alo);
    cudaGetSymbolAddress((void**)&Bhi, g_Bhi);
    cudaGetSymbolAddress((void**)&Blo, g_Blo);
    cudaGetSymbolAddress((void**)&ghi, g_ghi);
    cudaGetSymbolAddress((void**)&glo, g_glo);
    cudaGetSymbolAddress((void**)&f,   g_f);

    prep<<<1536 + 512, 256>>>(q, k, v, ln_g, ln_b, W_in, W_out);
    gemm_bf3<<<dim3(4, 96), 256, GEMM_SMEM>>>(Ahi, Alo, Bhi, Blo, f);
    macc<<<NPAIR * SPLITS, 256>>>();
    apply_k<<<NPAIR * 8, 256, APPLY_SMEM>>>(cov_w, var_w);
    gemm_bf3_m64<<<dim3(4, 64), 256, GEMM64_SMEM>>>(ghi, glo, Bhi + DD * DD, Blo + DD * DD,
                                                    out, b_out);
}

// round 15
// speedup vs baseline: 1.1482x; 1.0018x over previous
#include <cuda_runtime.h>
#include <cuda_bf16.h>
#include <cstdint>

// Problem constants: B=4, S=1024, D=512, H=8, DH=64
#define RQ   4096
#define R3   12288
#define DD   512
#define NPAIR 32
#define SPLITS 4
#define LN_EPS 1e-5f

// ---------------- scratch ----------------
__device__ float         g_f[3 * RQ * DD];        // fp32 f_q|f_k|f_v
__device__ __nv_bfloat16 g_Ahi[R3 * DD];
__device__ __nv_bfloat16 g_Alo[R3 * DD];
__device__ __nv_bfloat16 g_Bhi[2 * DD * DD];      // W_in^T | W_out^T (hi)
__device__ __nv_bfloat16 g_Blo[2 * DD * DD];
__device__ __nv_bfloat16 g_ghi[RQ * DD];
__device__ __nv_bfloat16 g_glo[RQ * DD];
__device__ float g_hmu[2 * NPAIR * 1024];
__device__ float g_hinvn[2 * NPAIR * 1024];
__device__ float g_hvar[2 * NPAIR * 1024];
__device__ float g_Mpart[NPAIR * SPLITS * 2 * 4096];
__device__ float g_rpart[NPAIR * SPLITS * 64];

// ---------------- helpers ----------------
__device__ __forceinline__ uint32_t smem_u32(const void* p) {
    uint32_t a;
    asm("{ .reg .u64 t; cvta.to.shared.u64 t, %1; cvt.u32.u64 %0, t; }" : "=r"(a) : "l"(p));
    return a;
}
__device__ __forceinline__ void cp16(uint32_t dst, const void* src) {
    asm volatile("cp.async.cg.shared.global [%0], [%1], 16;" :: "r"(dst), "l"(src));
}
__device__ __forceinline__ void cp_commit() {
    asm volatile("cp.async.commit_group;");
}
__device__ __forceinline__ void ldsm4(uint32_t& r0, uint32_t& r1, uint32_t& r2, uint32_t& r3,
                                      uint32_t addr) {
    asm volatile("ldmatrix.sync.aligned.m8n8.x4.shared.b16 {%0,%1,%2,%3}, [%4];"
                 : "=r"(r0), "=r"(r1), "=r"(r2), "=r"(r3) : "r"(addr));
}
__device__ __forceinline__ void mma16816(float& c0, float& c1, float& c2, float& c3,
                                         uint32_t a0, uint32_t a1, uint32_t a2, uint32_t a3,
                                         uint32_t b0, uint32_t b1) {
    asm volatile(
        "mma.sync.aligned.m16n8k16.row.col.f32.bf16.bf16.f32 "
        "{%0,%1,%2,%3}, {%4,%5,%6,%7}, {%8,%9}, {%0,%1,%2,%3};"
        : "+f"(c0), "+f"(c1), "+f"(c2), "+f"(c3)
        : "r"(a0), "r"(a1), "r"(a2), "r"(a3), "r"(b0), "r"(b1));
}
__device__ __forceinline__ uint32_t pack_hi2(float x, float y) {
    __nv_bfloat162 t = __floats2bfloat162_rn(x, y);
    return *(uint32_t*)&t;
}
__device__ __forceinline__ uint32_t pack_lo2(float x, float y, uint32_t hi) {
    __nv_bfloat162 h = *(__nv_bfloat162*)&hi;
    __nv_bfloat162 t = __floats2bfloat162_rn(x - __bfloat162float(h.x),
                                             y - __bfloat162float(h.y));
    return *(uint32_t*)&t;
}

// ---------------- 1) merged prep: LN+split | W transpose+split ----------------
__global__ void __launch_bounds__(256) prep(
    const float* __restrict__ q, const float* __restrict__ k,
    const float* __restrict__ v, const float* __restrict__ lng,
    const float* __restrict__ lnb, const float* __restrict__ Win,
    const float* __restrict__ Wout)
{
    __shared__ float ts[32][33];
    if (blockIdx.x < 1536) {
        int gw   = blockIdx.x * 8 + (threadIdx.x >> 5);
        int lane = threadIdx.x & 31;
        const float* src = (gw < RQ) ? q : (gw < 2 * RQ ? k : v);
        int row = gw & (RQ - 1);
        const float4* p = (const float4*)(src + (size_t)row * DD);
        float4 x[4];
        float s = 0.f, ss = 0.f;
#pragma unroll
        for (int i = 0; i < 4; i++) {
            x[i] = p[lane + i * 32];
            s  += x[i].x + x[i].y + x[i].z + x[i].w;
            ss += x[i].x * x[i].x + x[i].y * x[i].y + x[i].z * x[i].z + x[i].w * x[i].w;
        }
#pragma unroll
        for (int o = 16; o; o >>= 1) {
            s  += __shfl_xor_sync(0xffffffffu, s, o);
            ss += __shfl_xor_sync(0xffffffffu, ss, o);
        }
        float mu = s * (1.f / 512.f);
        float rs = rsqrtf(ss * (1.f / 512.f) - mu * mu + LN_EPS);
#pragma unroll
        for (int i = 0; i < 4; i++) {
            float4 gg = ((const float4*)lng)[lane + i * 32];
            float4 bb = ((const float4*)lnb)[lane + i * 32];
            float y0 = (x[i].x - mu) * rs * gg.x + bb.x;
            float y1 = (x[i].y - mu) * rs * gg.y + bb.y;
            float y2 = (x[i].z - mu) * rs * gg.z + bb.z;
            float y3 = (x[i].w - mu) * rs * gg.w + bb.w;
            uint32_t h01 = pack_hi2(y0, y1);
            uint32_t h23 = pack_hi2(y2, y3);
            uint32_t l01 = pack_lo2(y0, y1, h01);
            uint32_t l23 = pack_lo2(y2, y3, h23);
            size_t off = (size_t)gw * DD + 4 * (lane + 32 * i);
            *(uint2*)&g_Ahi[off] = make_uint2(h01, h23);
            *(uint2*)&g_Alo[off] = make_uint2(l01, l23);
        }
    } else {
        int bx = blockIdx.x - 1536;
        int bz = bx >> 8; bx &= 255;
        const float* W = bz ? Wout : Win;
        size_t base = (size_t)bz * DD * DD;
        int k0 = (bx >> 4) * 32, n0 = (bx & 15) * 32;
        int tx = threadIdx.x & 31, ty = threadIdx.x >> 5;
#pragma unroll
        for (int i = 0; i < 4; i++)
            ts[ty + 8 * i][tx] = W[(size_t)(k0 + ty + 8 * i) * DD + n0 + tx];
        __syncthreads();
#pragma unroll
        for (int i = 0; i < 4; i++) {
            int n = n0 + ty + 8 * i, kk = k0 + tx;
            float val = ts[tx][ty + 8 * i];
            __nv_bfloat16 h = __float2bfloat16_rn(val);
            __nv_bfloat16 l = __float2bfloat16_rn(val - __bfloat162float(h));
            g_Bhi[base + (size_t)n * DD + kk] = h;
            g_Blo[base + (size_t)n * DD + kk] = l;
        }
    }
}

// ---------------- 2) HMMA GEMM, bf16x3 (GEMM1) ----------------
#define RS 40
#define TILE_B (128 * RS * 2)
#define BUF_B  (4 * TILE_B)
#define GEMM_SMEM (2 * BUF_B)

__global__ void __launch_bounds__(256, 2) gemm_bf3(
    const __nv_bfloat16* __restrict__ Ahi, const __nv_bfloat16* __restrict__ Alo,
    const __nv_bfloat16* __restrict__ Bhi, const __nv_bfloat16* __restrict__ Blo,
    float* __restrict__ C)
{
    extern __shared__ char smem[];
    uint32_t sb = smem_u32(smem);
    int t = threadIdx.x, wid = t >> 5, lane = t & 31;
    int n0 = blockIdx.x * 128, m0 = blockIdx.y * 128;
    int wm = wid >> 2, wn = wid & 3;

    float acc[4][4][4];
#pragma unroll
    for (int i = 0; i < 4; i++)
#pragma unroll
        for (int j = 0; j < 4; j++)
#pragma unroll
            for (int r = 0; r < 4; r++) acc[i][j][r] = 0.f;

    int r0l = t >> 2, seg = t & 3;

    auto issue = [&](int c, int buf) {
        int k0 = c * 32;
        uint32_t d0 = sb + buf * BUF_B;
#pragma unroll
        for (int i = 0; i < 2; i++) {
            int row = r0l + i * 64;
            uint32_t doff = (row * RS + seg * 8) * 2;
            size_t ga = (size_t)(m0 + row) * DD + k0 + seg * 8;
            size_t gb = (size_t)(n0 + row) * DD + k0 + seg * 8;
            cp16(d0 + doff,              Ahi + ga);
            cp16(d0 + TILE_B + doff,     Alo + ga);
            cp16(d0 + 2 * TILE_B + doff, Bhi + gb);
            cp16(d0 + 3 * TILE_B + doff, Blo + gb);
        }
        cp_commit();
    };

    issue(0, 0);
    int g = lane >> 3, rl = lane & 7;

    for (int c = 0; c < 16; c++) {
        int buf = c & 1;
        if (c < 15) issue(c + 1, buf ^ 1);
        if (c < 15) asm volatile("cp.async.wait_group 1;");
        else        asm volatile("cp.async.wait_group 0;");
        __syncthreads();

        uint32_t aBase = sb + buf * BUF_B;
        uint32_t bBase = aBase + 2 * TILE_B;
#pragma unroll
        for (int h = 0; h < 2; h++) {
            uint32_t aH[4][4], aL[4][4];
#pragma unroll
            for (int it = 0; it < 4; it++) {
                int row = wm * 64 + it * 16 + rl + (g & 1) * 8;
                int kc  = h * 16 + (g & 2) * 4;
                uint32_t ad = aBase + (row * RS + kc) * 2;
                ldsm4(aH[it][0], aH[it][1], aH[it][2], aH[it][3], ad);
                ldsm4(aL[it][0], aL[it][1], aL[it][2], aL[it][3], ad + TILE_B);
            }
            uint32_t bH[4][2], bL[4][2];
#pragma unroll
            for (int jp = 0; jp < 2; jp++) {
                int row = wn * 32 + jp * 16 + rl + (g >> 1) * 8;
                int kc  = h * 16 + (g & 1) * 8;
                uint32_t bd = bBase + (row * RS + kc) * 2;
                ldsm4(bH[2 * jp][0], bH[2 * jp][1], bH[2 * jp + 1][0], bH[2 * jp + 1][1], bd);
                ldsm4(bL[2 * jp][0], bL[2 * jp][1], bL[2 * jp + 1][0], bL[2 * jp + 1][1],
                      bd + TILE_B);
            }
#pragma unroll
            for (int it = 0; it < 4; it++)
#pragma unroll
                for (int jt = 0; jt < 4; jt++) {
                    mma16816(acc[it][jt][0], acc[it][jt][1], acc[it][jt][2], acc[it][jt][3],
                             aH[it][0], aH[it][1], aH[it][2], aH[it][3],
                             bH[jt][0], bH[jt][1]);
                    mma16816(acc[it][jt][0], acc[it][jt][1], acc[it][jt][2], acc[it][jt][3],
                             aH[it][0], aH[it][1], aH[it][2], aH[it][3],
                             bL[jt][0], bL[jt][1]);
                    mma16816(acc[it][jt][0], acc[it][jt][1], acc[it][jt][2], acc[it][jt][3],
                             aL[it][0], aL[it][1], aL[it][2], aL[it][3],
                             bH[jt][0], bH[jt][1]);
                }
        }
        __syncthreads();
    }

    int rr = lane >> 2, cc = 2 * (lane & 3);
#pragma unroll
    for (int it = 0; it < 4; it++) {
        int row = m0 + wm * 64 + it * 16 + rr;
#pragma unroll
        for (int jt = 0; jt < 4; jt++) {
            int col = n0 + wn * 32 + jt * 8 + cc;
            *(float2*)&C[(size_t)row * DD + col] =
                make_float2(acc[it][jt][0], acc[it][jt][1]);
            *(float2*)&C[(size_t)(row + 8) * DD + col] =
                make_float2(acc[it][jt][2], acc[it][jt][3]);
        }
    }

    if (m0 < 2 * RQ) {
        float* sred = (float*)smem;
#pragma unroll
        for (int it = 0; it < 4; it++) {
#pragma unroll
            for (int sub = 0; sub < 2; sub++) {
                float s = 0.f, ss = 0.f;
#pragma unroll
                for (int jt = 0; jt < 4; jt++) {
                    float v0 = acc[it][jt][2 * sub], v1 = acc[it][jt][2 * sub + 1];
                    s  += v0 + v1;
                    ss += v0 * v0 + v1 * v1;
                }
#pragma unroll
                for (int o = 1; o <= 2; o <<= 1) {
                    s  += __shfl_xor_sync(0xffffffffu, s, o);
                    ss += __shfl_xor_sync(0xffffffffu, ss, o);
                }
                if ((lane & 3) == 0) {
                    int lr = wm * 64 + it * 16 + rr + sub * 8;
                    sred[(wn * 128 + lr) * 2 + 0] = s;
                    sred[(wn * 128 + lr) * 2 + 1] = ss;
                }
            }
        }
        __syncthreads();
        int hp = t >> 7, lr = t & 127;
        float s  = sred[((2 * hp) * 128 + lr) * 2 + 0] +
                   sred[((2 * hp + 1) * 128 + lr) * 2 + 0];
        float ss = sred[((2 * hp) * 128 + lr) * 2 + 1] +
                   sred[((2 * hp + 1) * 128 + lr) * 2 + 1];
        int grow = m0 + lr;
        int tensor = grow >> 12;
        int b = (grow >> 10) & 3, m = grow & 1023;
        int h = (n0 >> 6) + hp;
        int idx = tensor * 32768 + (h * 4 + b) * 1024 + m;
        g_hmu[idx]   = s * (1.f / 64.f);
        g_hinvn[idx] = rsqrtf(ss);
        g_hvar[idx]  = (ss - s * s * (1.f / 64.f)) * (1.f / 63.f);
    }
}

// ---------------- 2b) GEMM2: CTA tile 64x128 ----------------
#define A64_B (64 * RS * 2)
#define BUF64 (2 * A64_B + 2 * TILE_B)
#define GEMM64_SMEM (2 * BUF64)

__global__ void __launch_bounds__(256, 2) gemm_bf3_m64(
    const __nv_bfloat16* __restrict__ Ahi, const __nv_bfloat16* __restrict__ Alo,
    const __nv_bfloat16* __restrict__ Bhi, const __nv_bfloat16* __restrict__ Blo,
    float* __restrict__ C, const float* __restrict__ bias)
{
    extern __shared__ char smem[];
    uint32_t sb = smem_u32(smem);
    int t = threadIdx.x, wid = t >> 5, lane = t & 31;
    int n0 = blockIdx.x * 128, m0 = blockIdx.y * 64;
    int wm = wid >> 2, wn = wid & 3;

    float acc[2][4][4];
#pragma unroll
    for (int i = 0; i < 2; i++)
#pragma unroll
        for (int j = 0; j < 4; j++)
#pragma unroll
            for (int r = 0; r < 4; r++) acc[i][j][r] = 0.f;

    auto issue = [&](int c, int buf) {
        int k0 = c * 32;
        uint32_t d0 = sb + buf * BUF64;
        {
            int row = t >> 2, seg = t & 3;
            uint32_t doff = (row * RS + seg * 8) * 2;
            size_t ga = (size_t)(m0 + row) * DD + k0 + seg * 8;
            cp16(d0 + doff,         Ahi + ga);
            cp16(d0 + A64_B + doff, Alo + ga);
        }
#pragma unroll
        for (int i = 0; i < 2; i++) {
            int u = t + i * 256;
            int row = u >> 2, seg = u & 3;
            uint32_t doff = (row * RS + seg * 8) * 2;
            size_t gb = (size_t)(n0 + row) * DD + k0 + seg * 8;
            cp16(d0 + 2 * A64_B + doff,          Bhi + gb);
            cp16(d0 + 2 * A64_B + TILE_B + doff, Blo + gb);
        }
        cp_commit();
    };

    issue(0, 0);
    int g = lane >> 3, rl = lane & 7;

    for (int c = 0; c < 16; c++) {
        int buf = c & 1;
        if (c < 15) issue(c + 1, buf ^ 1);
        if (c < 15) asm volatile("cp.async.wait_group 1;");
        else        asm volatile("cp.async.wait_group 0;");
        __syncthreads();

        uint32_t aBase = sb + buf * BUF64;
        uint32_t bBase = aBase + 2 * A64_B;
#pragma unroll
        for (int h = 0; h < 2; h++) {
            uint32_t aH[2][4], aL[2][4];
#pragma unroll
            for (int it = 0; it < 2; it++) {
                int row = wm * 32 + it * 16 + rl + (g & 1) * 8;
                int kc  = h * 16 + (g & 2) * 4;
                uint32_t ad = aBase + (row * RS + kc) * 2;
                ldsm4(aH[it][0], aH[it][1], aH[it][2], aH[it][3], ad);
                ldsm4(aL[it][0], aL[it][1], aL[it][2], aL[it][3], ad + A64_B);
            }
            uint32_t bH[4][2], bL[4][2];
#pragma unroll
            for (int jp = 0; jp < 2; jp++) {
                int row = wn * 32 + jp * 16 + rl + (g >> 1) * 8;
                int kc  = h * 16 + (g & 1) * 8;
                uint32_t bd = bBase + (row * RS + kc) * 2;
                ldsm4(bH[2 * jp][0], bH[2 * jp][1], bH[2 * jp + 1][0], bH[2 * jp + 1][1], bd);
                ldsm4(bL[2 * jp][0], bL[2 * jp][1], bL[2 * jp + 1][0], bL[2 * jp + 1][1],
                      bd + TILE_B);
            }
#pragma unroll
            for (int it = 0; it < 2; it++)
#pragma unroll
                for (int jt = 0; jt < 4; jt++) {
                    mma16816(acc[it][jt][0], acc[it][jt][1], acc[it][jt][2], acc[it][jt][3],
                             aH[it][0], aH[it][1], aH[it][2], aH[it][3],
                             bH[jt][0], bH[jt][1]);
                    mma16816(acc[it][jt][0], acc[it][jt][1], acc[it][jt][2], acc[it][jt][3],
                             aH[it][0], aH[it][1], aH[it][2], aH[it][3],
                             bL[jt][0], bL[jt][1]);
                    mma16816(acc[it][jt][0], acc[it][jt][1], acc[it][jt][2], acc[it][jt][3],
                             aL[it][0], aL[it][1], aL[it][2], aL[it][3],
                             bH[jt][0], bH[jt][1]);
                }
        }
        __syncthreads();
    }

    int rr = lane >> 2, cc = 2 * (lane & 3);
#pragma unroll
    for (int it = 0; it < 2; it++) {
        int row = m0 + wm * 32 + it * 16 + rr;
#pragma unroll
        for (int jt = 0; jt < 4; jt++) {
            int col = n0 + wn * 32 + jt * 8 + cc;
            float2 bb = *(const float2*)&bias[col];
            *(float2*)&C[(size_t)row * DD + col] =
                make_float2(acc[it][jt][0] + bb.x, acc[it][jt][1] + bb.y);
            *(float2*)&C[(size_t)(row + 8) * DD + col] =
                make_float2(acc[it][jt][2] + bb.x, acc[it][jt][3] + bb.y);
        }
    }
}

// ---------------- 3) G/H/r partials: 4 splits x 256 rows, cp.async ring ----------------
__global__ void __launch_bounds__(256, 4) macc()
{
    __shared__ float Ks[2][32][64];
    __shared__ float Vs[2][32][64];
    __shared__ float sikn[256], skv[256];
    int t = threadIdx.x;
    int pair  = blockIdx.x >> 2;
    int split = blockIdx.x & 3;
    int h = pair >> 2, b = pair & 3;
    const float* fk = g_f + (size_t)RQ * DD     + (size_t)(b * 1024) * DD + h * 64;
    const float* fv = g_f + (size_t)2 * RQ * DD + (size_t)(b * 1024) * DD + h * 64;
    int tx = t & 15, ty = t >> 4;
    int d0 = ty * 4, e0 = tx * 4;
    float G[4][4] = {}, Hm[4][4] = {}, ra[4] = {};
    int mbase0 = split * 256;
    uint32_t sK = smem_u32(Ks), sV = smem_u32(Vs);

    auto issue = [&](int c) {
        int mbase = mbase0 + c * 32;
        uint32_t bufo = (uint32_t)(c & 1) * (32 * 64 * 4);
#pragma unroll
        for (int i = 0; i < 2; i++) {
            int u = t + i * 256;
            int rr = u >> 4, c4 = (u & 15) * 4;
            uint32_t off = bufo + (rr * 64 + c4) * 4;
            cp16(sK + off, fk + (size_t)(mbase + rr) * DD + c4);
            cp16(sV + off, fv + (size_t)(mbase + rr) * DD + c4);
        }
        cp_commit();
    };

    issue(0);
    {
        int idx = 32768 + pair * 1024 + mbase0 + t;
        sikn[t] = g_hinvn[idx];
        skv[t]  = g_hvar[idx];
    }

    for (int c = 0; c < 8; c++) {
        if (c < 7) issue(c + 1);
        if (c < 7) asm volatile("cp.async.wait_group 1;");
        else       asm volatile("cp.async.wait_group 0;");
        __syncthreads();
        int buf = c & 1;
#pragma unroll 8
        for (int mm = 0; mm < 32; mm++) {
            float ikn = sikn[c * 32 + mm];
            float4 kk4 = *(float4*)&Ks[buf][mm][d0];
            float4 vv4 = *(float4*)&Vs[buf][mm][e0];
            float kk[4] = {kk4.x, kk4.y, kk4.z, kk4.w};
            float vv[4] = {vv4.x, vv4.y, vv4.z, vv4.w};
            float vn[4] = {vv4.x * ikn, vv4.y * ikn, vv4.z * ikn, vv4.w * ikn};
#pragma unroll
            for (int i = 0; i < 4; i++)
#pragma unroll
                for (int j = 0; j < 4; j++) {
                    G[i][j]  += kk[i] * vv[j];
                    Hm[i][j] += kk[i] * vn[j];
                }
        }
        if (ty == 0) {
#pragma unroll 8
            for (int mm = 0; mm < 32; mm++) {
                float kvv = skv[c * 32 + mm];
#pragma unroll
                for (int j = 0; j < 4; j++) ra[j] += kvv * Vs[buf][mm][e0 + j];
            }
        }
        __syncthreads();
    }
    float* mp = g_Mpart + (size_t)blockIdx.x * 8192;
#pragma unroll
    for (int i = 0; i < 4; i++)
#pragma unroll
        for (int j = 0; j < 4; j++) {
            mp[(d0 + i) * 64 + e0 + j]        = G[i][j];
            mp[4096 + (d0 + i) * 64 + e0 + j] = Hm[i][j];
        }
    if (ty == 0)
#pragma unroll
        for (int j = 0; j < 4; j++) g_rpart[blockIdx.x * 64 + e0 + j] = ra[j];
}

// ---------------- 4) apply v5: HMMA bf16x3, 128 rows/block ----------------
#define MB_S 72
#define APPLY_SMEM (32768 + 2 * 128 * MB_S * 2 + 4096)

__global__ void __launch_bounds__(256) apply_k(const float* __restrict__ cov_w,
                                               const float* __restrict__ var_w)
{
    extern __shared__ float sm[];
    float* Ms = sm;                                      // 8192 fp32: G | H
    __nv_bfloat16* Mbh = (__nv_bfloat16*)(sm + 8192);    // [128 e'][MB_S] (G:0-63,H:64-127)
    __nv_bfloat16* Mbl = Mbh + 128 * MB_S;
    float* sbeta = (float*)(Mbl + 128 * MB_S);           // 128
    float* sgam  = sbeta + 128;                          // 128
    float* smual = sgam + 128;                           // 128
    float* srs   = smual + 128;                          // 64
    float* scs1  = srs + 64;                             // 64
    float* spart = scs1 + 64;                            // 256

    int t = threadIdx.x, wid = t >> 5, lane = t & 31;
    int pair  = blockIdx.x >> 3;
    int ntile = blockIdx.x & 7;
    int h = pair >> 2, b = pair & 3;
    float cw = cov_w[0], vw = var_w[0];
    float w3 = 1.f - cw - vw;
    float alpha = cw * (1.f / 64.f);
    int n0 = ntile * 128;

    // 1) fused reduction of 4 split partials -> Ms
    const float4* mp0 = (const float4*)(g_Mpart + (size_t)(pair * SPLITS) * 8192);
#pragma unroll
    for (int i = 0; i < 8; i++) {
        int fi = t + i * 256;
        float4 a0 = __ldcg(mp0 + fi);
        float4 a1 = __ldcg(mp0 + 2048 + fi);
        float4 a2 = __ldcg(mp0 + 4096 + fi);
        float4 a3 = __ldcg(mp0 + 6144 + fi);
        float4 o;
        o.x = ((a0.x + a1.x) + a2.x) + a3.x;
        o.y = ((a0.y + a1.y) + a2.y) + a3.y;
        o.z = ((a0.z + a1.z) + a2.z) + a3.z;
        o.w = ((a0.w + a1.w) + a2.w) + a3.w;
        ((float4*)Ms)[fi] = o;
    }
    if (t < 128) {
        int idx = pair * 1024 + n0 + t;
        float mu = g_hmu[idx], invn = g_hinvn[idx], var = g_hvar[idx];
        sbeta[t] = w3 * invn;
        sgam[t]  = vw * (1.f / 64.f) * var;
        smual[t] = alpha * mu;
    }
    if (t < 64) {
        float r = 0.f;
#pragma unroll
        for (int sp = 0; sp < SPLITS; sp++)
            r += __ldcg(&g_rpart[(pair * SPLITS + sp) * 64 + t]);
        srs[t] = r;
    }
    __syncthreads();

    // 2) convert Ms -> Mb (transposed [e'][d]) + G column partials
#pragma unroll
    for (int i = 0; i < 8; i++) {
        int fi = t + i * 256;                    // float4 index over Ms
        int half = fi >> 10;                     // 0:G 1:H
        int d = (fi & 1023) >> 4;
        int e4 = (fi & 15) * 4;
        float4 vvv = ((float4*)Ms)[fi];
        float vals[4] = {vvv.x, vvv.y, vvv.z, vvv.w};
#pragma unroll
        for (int j = 0; j < 4; j++) {
            int ep = half * 64 + e4 + j;
            __nv_bfloat16 hh = __float2bfloat16_rn(vals[j]);
            Mbh[ep * MB_S + d] = hh;
            Mbl[ep * MB_S + d] = __float2bfloat16_rn(vals[j] - __bfloat162float(hh));
        }
    }
    {
        int col = t & 63, grp = t >> 6;
        float s = 0.f;
#pragma unroll
        for (int d = 0; d < 16; d++) s += Ms[(grp * 16 + d) * 64 + col];
        spart[t] = s;
    }
    __syncthreads();
    if (t < 64)
        scs1[t] = ((spart[t] + spart[64 + t]) + spart[128 + t]) + spart[192 + t];

    // 3) A-fragment preload from gmem fp32 (warp owns 16 rows)
    int r = lane >> 2, c0b = (lane & 3) * 2;
    const float* qrow0 = g_f + (size_t)(b * 1024 + n0 + wid * 16 + r) * DD + h * 64;
    const float* qrow8 = qrow0 + 8 * DD;
    uint32_t aH[4][4], aL[4][4];
#pragma unroll
    for (int ch = 0; ch < 4; ch++) {
        int c0 = c0b + ch * 16;
#pragma unroll
        for (int p = 0; p < 4; p++) {
            const float* src = ((p & 1) ? qrow8 : qrow0) + c0 + (p >> 1) * 8;
            float2 v = *(const float2*)src;
            aH[ch][p] = pack_hi2(v.x, v.y);
            aL[ch][p] = pack_lo2(v.x, v.y, aH[ch][p]);
        }
    }

    // 4) mainloop: warp tile 16 rows x 128 cols, K=64
    float acc[16][4];
#pragma unroll
    for (int j = 0; j < 16; j++)
#pragma unroll
        for (int x = 0; x < 4; x++) acc[j][x] = 0.f;

    int g = lane >> 3, rl = lane & 7;
    uint32_t mbh = smem_u32(Mbh), mbl = smem_u32(Mbl);
#pragma unroll
    for (int ch = 0; ch < 4; ch++) {
        int kc = ch * 16 + (g & 1) * 8;
#pragma unroll
        for (int jp = 0; jp < 8; jp++) {
            int brow = jp * 16 + rl + (g >> 1) * 8;
            uint32_t boff = (brow * MB_S + kc) * 2;
            uint32_t bH[2][2], bL[2][2];
            ldsm4(bH[0][0], bH[0][1], bH[1][0], bH[1][1], mbh + boff);
            ldsm4(bL[0][0], bL[0][1], bL[1][0], bL[1][1], mbl + boff);
#pragma unroll
            for (int j2 = 0; j2 < 2; j2++) {
                int jt = jp * 2 + j2;
                mma16816(acc[jt][0], acc[jt][1], acc[jt][2], acc[jt][3],
                         aH[ch][0], aH[ch][1], aH[ch][2], aH[ch][3],
                         bH[j2][0], bH[j2][1]);
                mma16816(acc[jt][0], acc[jt][1], acc[jt][2], acc[jt][3],
                         aH[ch][0], aH[ch][1], aH[ch][2], aH[ch][3],
                         bL[j2][0], bL[j2][1]);
                mma16816(acc[jt][0], acc[jt][1], acc[jt][2], acc[jt][3],
                         aL[ch][0], aL[ch][1], aL[ch][2], aL[ch][3],
                         bH[j2][0], bH[j2][1]);
            }
        }
    }
    __syncthreads();   // scs1 visibility

    // 5) epilogue: combine T1 (jt 0-7) and T2 (jt 8-15), emit bf16 hi/lo
#pragma unroll
    for (int jt = 0; jt < 8; jt++) {
        int e0v = jt * 8 + c0b;
        float cs0 = scs1[e0v], cs1v = scs1[e0v + 1];
        float rr0 = srs[e0v],  rr1 = srs[e0v + 1];
#pragma unroll
        for (int rr2 = 0; rr2 < 2; rr2++) {
            int lrow = wid * 16 + r + rr2 * 8;
            float T1a = acc[jt][rr2 * 2],     T1b = acc[jt][rr2 * 2 + 1];
            float T2a = acc[jt + 8][rr2 * 2], T2b = acc[jt + 8][rr2 * 2 + 1];
            float beta = sbeta[lrow], gamma = sgam[lrow], mal = smual[lrow];
            float o0 = alpha * T1a - mal * cs0 + beta * T2a + gamma * rr0;
            float o1 = alpha * T1b - mal * cs1v + beta * T2b + gamma * rr1;
            uint32_t hv = pack_hi2(o0, o1);
            uint32_t lv = pack_lo2(o0, o1, hv);
            size_t off = (size_t)(b * 1024 + n0 + lrow) * DD + h * 64 + e0v;
            *(uint32_t*)&g_ghi[off] = hv;
            *(uint32_t*)&g_glo[off] = lv;
        }
    }
}

// ---------------- launch ----------------
extern "C" void kernel_launch(void* const* d_in, const int* in_sizes, int n_in,
                              void* d_out, int out_size)
{
    const float* q     = (const float*)d_in[0];
    const float* k     = (const float*)d_in[1];
    const float* v     = (const float*)d_in[2];
    const float* ln_g  = (const float*)d_in[3];
    const float* ln_b  = (const float*)d_in[4];
    const float* W_in  = (const float*)d_in[5];
    const float* W_out = (const float*)d_in[6];
    const float* b_out = (const float*)d_in[7];
    const float* cov_w = (const float*)d_in[8];
    const float* var_w = (const float*)d_in[9];
    float* out = (float*)d_out;

    cudaFuncSetAttribute(gemm_bf3, cudaFuncAttributeMaxDynamicSharedMemorySize, GEMM_SMEM);
    cudaFuncSetAttribute(gemm_bf3_m64, cudaFuncAttributeMaxDynamicSharedMemorySize, GEMM64_SMEM);
    cudaFuncSetAttribute(apply_k, cudaFuncAttributeMaxDynamicSharedMemorySize, APPLY_SMEM);

    __nv_bfloat16 *Ahi, *Alo, *Bhi, *Blo, *ghi, *glo;
    float* f;
    cudaGetSymbolAddress((void**)&Ahi, g_Ahi);
    cudaGetSymbolAddress((void**)&Alo, g_Alo);
    cudaGetSymbolAddress((void**)&Bhi, g_Bhi);
    cudaGetSymbolAddress((void**)&Blo, g_Blo);
    cudaGetSymbolAddress((void**)&ghi, g_ghi);
    cudaGetSymbolAddress((void**)&glo, g_glo);
    cudaGetSymbolAddress((void**)&f,   g_f);

    prep<<<1536 + 512, 256>>>(q, k, v, ln_g, ln_b, W_in, W_out);
    gemm_bf3<<<dim3(4, 96), 256, GEMM_SMEM>>>(Ahi, Alo, Bhi, Blo, f);
    macc<<<NPAIR * SPLITS, 256>>>();
    apply_k<<<NPAIR * 8, 256, APPLY_SMEM>>>(cov_w, var_w);
    gemm_bf3_m64<<<dim3(4, 64), 256, GEMM64_SMEM>>>(ghi, glo, Bhi + DD * DD, Blo + DD * DD,
                                                    out, b_out);
}

// round 16
// speedup vs baseline: 1.1806x; 1.0283x over previous
#include <cuda_runtime.h>
#include <cuda_bf16.h>
#include <cstdint>

// Problem constants: B=4, S=1024, D=512, H=8, DH=64
#define RQ   4096
#define R3   12288
#define DD   512
#define NPAIR 32
#define SPLITS 4
#define LN_EPS 1e-5f

// ---------------- scratch ----------------
__device__ float         g_f[3 * RQ * DD];        // fp32 f_q|f_k|f_v
__device__ __nv_bfloat16 g_Ahi[R3 * DD];
__device__ __nv_bfloat16 g_Alo[R3 * DD];
__device__ __nv_bfloat16 g_Bhi[2 * DD * DD];      // W_in^T | W_out^T (hi)
__device__ __nv_bfloat16 g_Blo[2 * DD * DD];
__device__ __nv_bfloat16 g_ghi[RQ * DD];
__device__ __nv_bfloat16 g_glo[RQ * DD];
__device__ float g_hmu[2 * NPAIR * 1024];
__device__ float g_hinvn[2 * NPAIR * 1024];
__device__ float g_hvar[2 * NPAIR * 1024];
__device__ float g_Mpart[NPAIR * SPLITS * 2 * 4096];
__device__ float g_rpart[NPAIR * SPLITS * 64];

// ---------------- helpers ----------------
__device__ __forceinline__ uint32_t smem_u32(const void* p) {
    uint32_t a;
    asm("{ .reg .u64 t; cvta.to.shared.u64 t, %1; cvt.u32.u64 %0, t; }" : "=r"(a) : "l"(p));
    return a;
}
__device__ __forceinline__ void cp16(uint32_t dst, const void* src) {
    asm volatile("cp.async.cg.shared.global [%0], [%1], 16;" :: "r"(dst), "l"(src));
}
__device__ __forceinline__ void cp_commit() {
    asm volatile("cp.async.commit_group;");
}
__device__ __forceinline__ void ldsm4(uint32_t& r0, uint32_t& r1, uint32_t& r2, uint32_t& r3,
                                      uint32_t addr) {
    asm volatile("ldmatrix.sync.aligned.m8n8.x4.shared.b16 {%0,%1,%2,%3}, [%4];"
                 : "=r"(r0), "=r"(r1), "=r"(r2), "=r"(r3) : "r"(addr));
}
__device__ __forceinline__ void mma16816(float& c0, float& c1, float& c2, float& c3,
                                         uint32_t a0, uint32_t a1, uint32_t a2, uint32_t a3,
                                         uint32_t b0, uint32_t b1) {
    asm volatile(
        "mma.sync.aligned.m16n8k16.row.col.f32.bf16.bf16.f32 "
        "{%0,%1,%2,%3}, {%4,%5,%6,%7}, {%8,%9}, {%0,%1,%2,%3};"
        : "+f"(c0), "+f"(c1), "+f"(c2), "+f"(c3)
        : "r"(a0), "r"(a1), "r"(a2), "r"(a3), "r"(b0), "r"(b1));
}
__device__ __forceinline__ uint32_t pack_hi2(float x, float y) {
    __nv_bfloat162 t = __floats2bfloat162_rn(x, y);
    return *(uint32_t*)&t;
}
__device__ __forceinline__ uint32_t pack_lo2(float x, float y, uint32_t hi) {
    __nv_bfloat162 h = *(__nv_bfloat162*)&hi;
    __nv_bfloat162 t = __floats2bfloat162_rn(x - __bfloat162float(h.x),
                                             y - __bfloat162float(h.y));
    return *(uint32_t*)&t;
}

// ---------------- 1) merged prep: LN+split | W transpose+split ----------------
__global__ void __launch_bounds__(256) prep(
    const float* __restrict__ q, const float* __restrict__ k,
    const float* __restrict__ v, const float* __restrict__ lng,
    const float* __restrict__ lnb, const float* __restrict__ Win,
    const float* __restrict__ Wout)
{
    __shared__ float ts[32][33];
    if (blockIdx.x < 1536) {
        int gw   = blockIdx.x * 8 + (threadIdx.x >> 5);
        int lane = threadIdx.x & 31;
        const float* src = (gw < RQ) ? q : (gw < 2 * RQ ? k : v);
        int row = gw & (RQ - 1);
        const float4* p = (const float4*)(src + (size_t)row * DD);
        float4 x[4];
        float s = 0.f, ss = 0.f;
#pragma unroll
        for (int i = 0; i < 4; i++) {
            x[i] = p[lane + i * 32];
            s  += x[i].x + x[i].y + x[i].z + x[i].w;
            ss += x[i].x * x[i].x + x[i].y * x[i].y + x[i].z * x[i].z + x[i].w * x[i].w;
        }
#pragma unroll
        for (int o = 16; o; o >>= 1) {
            s  += __shfl_xor_sync(0xffffffffu, s, o);
            ss += __shfl_xor_sync(0xffffffffu, ss, o);
        }
        float mu = s * (1.f / 512.f);
        float rs = rsqrtf(ss * (1.f / 512.f) - mu * mu + LN_EPS);
#pragma unroll
        for (int i = 0; i < 4; i++) {
            float4 gg = ((const float4*)lng)[lane + i * 32];
            float4 bb = ((const float4*)lnb)[lane + i * 32];
            float y0 = (x[i].x - mu) * rs * gg.x + bb.x;
            float y1 = (x[i].y - mu) * rs * gg.y + bb.y;
            float y2 = (x[i].z - mu) * rs * gg.z + bb.z;
            float y3 = (x[i].w - mu) * rs * gg.w + bb.w;
            uint32_t h01 = pack_hi2(y0, y1);
            uint32_t h23 = pack_hi2(y2, y3);
            uint32_t l01 = pack_lo2(y0, y1, h01);
            uint32_t l23 = pack_lo2(y2, y3, h23);
            size_t off = (size_t)gw * DD + 4 * (lane + 32 * i);
            *(uint2*)&g_Ahi[off] = make_uint2(h01, h23);
            *(uint2*)&g_Alo[off] = make_uint2(l01, l23);
        }
    } else {
        int bx = blockIdx.x - 1536;
        int bz = bx >> 8; bx &= 255;
        const float* W = bz ? Wout : Win;
        size_t base = (size_t)bz * DD * DD;
        int k0 = (bx >> 4) * 32, n0 = (bx & 15) * 32;
        int tx = threadIdx.x & 31, ty = threadIdx.x >> 5;
#pragma unroll
        for (int i = 0; i < 4; i++)
            ts[ty + 8 * i][tx] = W[(size_t)(k0 + ty + 8 * i) * DD + n0 + tx];
        __syncthreads();
#pragma unroll
        for (int i = 0; i < 4; i++) {
            int n = n0 + ty + 8 * i, kk = k0 + tx;
            float val = ts[tx][ty + 8 * i];
            __nv_bfloat16 h = __float2bfloat16_rn(val);
            __nv_bfloat16 l = __float2bfloat16_rn(val - __bfloat162float(h));
            g_Bhi[base + (size_t)n * DD + kk] = h;
            g_Blo[base + (size_t)n * DD + kk] = l;
        }
    }
}

// ---------------- 2) HMMA GEMM, bf16x3 (GEMM1) ----------------
#define RS 40
#define TILE_B (128 * RS * 2)
#define BUF_B  (4 * TILE_B)
#define GEMM_SMEM (2 * BUF_B)

__global__ void __launch_bounds__(256, 2) gemm_bf3(
    const __nv_bfloat16* __restrict__ Ahi, const __nv_bfloat16* __restrict__ Alo,
    const __nv_bfloat16* __restrict__ Bhi, const __nv_bfloat16* __restrict__ Blo,
    float* __restrict__ C)
{
    extern __shared__ char smem[];
    uint32_t sb = smem_u32(smem);
    int t = threadIdx.x, wid = t >> 5, lane = t & 31;
    int n0 = blockIdx.x * 128, m0 = blockIdx.y * 128;
    int wm = wid >> 2, wn = wid & 3;

    float acc[4][4][4];
#pragma unroll
    for (int i = 0; i < 4; i++)
#pragma unroll
        for (int j = 0; j < 4; j++)
#pragma unroll
            for (int r = 0; r < 4; r++) acc[i][j][r] = 0.f;

    int r0l = t >> 2, seg = t & 3;

    auto issue = [&](int c, int buf) {
        int k0 = c * 32;
        uint32_t d0 = sb + buf * BUF_B;
#pragma unroll
        for (int i = 0; i < 2; i++) {
            int row = r0l + i * 64;
            uint32_t doff = (row * RS + seg * 8) * 2;
            size_t ga = (size_t)(m0 + row) * DD + k0 + seg * 8;
            size_t gb = (size_t)(n0 + row) * DD + k0 + seg * 8;
            cp16(d0 + doff,              Ahi + ga);
            cp16(d0 + TILE_B + doff,     Alo + ga);
            cp16(d0 + 2 * TILE_B + doff, Bhi + gb);
            cp16(d0 + 3 * TILE_B + doff, Blo + gb);
        }
        cp_commit();
    };

    issue(0, 0);
    int g = lane >> 3, rl = lane & 7;

    for (int c = 0; c < 16; c++) {
        int buf = c & 1;
        if (c < 15) issue(c + 1, buf ^ 1);
        if (c < 15) asm volatile("cp.async.wait_group 1;");
        else        asm volatile("cp.async.wait_group 0;");
        __syncthreads();

        uint32_t aBase = sb + buf * BUF_B;
        uint32_t bBase = aBase + 2 * TILE_B;
#pragma unroll
        for (int h = 0; h < 2; h++) {
            uint32_t aH[4][4], aL[4][4];
#pragma unroll
            for (int it = 0; it < 4; it++) {
                int row = wm * 64 + it * 16 + rl + (g & 1) * 8;
                int kc  = h * 16 + (g & 2) * 4;
                uint32_t ad = aBase + (row * RS + kc) * 2;
                ldsm4(aH[it][0], aH[it][1], aH[it][2], aH[it][3], ad);
                ldsm4(aL[it][0], aL[it][1], aL[it][2], aL[it][3], ad + TILE_B);
            }
            uint32_t bH[4][2], bL[4][2];
#pragma unroll
            for (int jp = 0; jp < 2; jp++) {
                int row = wn * 32 + jp * 16 + rl + (g >> 1) * 8;
                int kc  = h * 16 + (g & 1) * 8;
                uint32_t bd = bBase + (row * RS + kc) * 2;
                ldsm4(bH[2 * jp][0], bH[2 * jp][1], bH[2 * jp + 1][0], bH[2 * jp + 1][1], bd);
                ldsm4(bL[2 * jp][0], bL[2 * jp][1], bL[2 * jp + 1][0], bL[2 * jp + 1][1],
                      bd + TILE_B);
            }
#pragma unroll
            for (int it = 0; it < 4; it++)
#pragma unroll
                for (int jt = 0; jt < 4; jt++) {
                    mma16816(acc[it][jt][0], acc[it][jt][1], acc[it][jt][2], acc[it][jt][3],
                             aH[it][0], aH[it][1], aH[it][2], aH[it][3],
                             bH[jt][0], bH[jt][1]);
                    mma16816(acc[it][jt][0], acc[it][jt][1], acc[it][jt][2], acc[it][jt][3],
                             aH[it][0], aH[it][1], aH[it][2], aH[it][3],
                             bL[jt][0], bL[jt][1]);
                    mma16816(acc[it][jt][0], acc[it][jt][1], acc[it][jt][2], acc[it][jt][3],
                             aL[it][0], aL[it][1], aL[it][2], aL[it][3],
                             bH[jt][0], bH[jt][1]);
                }
        }
        __syncthreads();
    }

    int rr = lane >> 2, cc = 2 * (lane & 3);
#pragma unroll
    for (int it = 0; it < 4; it++) {
        int row = m0 + wm * 64 + it * 16 + rr;
#pragma unroll
        for (int jt = 0; jt < 4; jt++) {
            int col = n0 + wn * 32 + jt * 8 + cc;
            *(float2*)&C[(size_t)row * DD + col] =
                make_float2(acc[it][jt][0], acc[it][jt][1]);
            *(float2*)&C[(size_t)(row + 8) * DD + col] =
                make_float2(acc[it][jt][2], acc[it][jt][3]);
        }
    }

    if (m0 < 2 * RQ) {
        float* sred = (float*)smem;
#pragma unroll
        for (int it = 0; it < 4; it++) {
#pragma unroll
            for (int sub = 0; sub < 2; sub++) {
                float s = 0.f, ss = 0.f;
#pragma unroll
                for (int jt = 0; jt < 4; jt++) {
                    float v0 = acc[it][jt][2 * sub], v1 = acc[it][jt][2 * sub + 1];
                    s  += v0 + v1;
                    ss += v0 * v0 + v1 * v1;
                }
#pragma unroll
                for (int o = 1; o <= 2; o <<= 1) {
                    s  += __shfl_xor_sync(0xffffffffu, s, o);
                    ss += __shfl_xor_sync(0xffffffffu, ss, o);
                }
                if ((lane & 3) == 0) {
                    int lr = wm * 64 + it * 16 + rr + sub * 8;
                    sred[(wn * 128 + lr) * 2 + 0] = s;
                    sred[(wn * 128 + lr) * 2 + 1] = ss;
                }
            }
        }
        __syncthreads();
        int hp = t >> 7, lr = t & 127;
        float s  = sred[((2 * hp) * 128 + lr) * 2 + 0] +
                   sred[((2 * hp + 1) * 128 + lr) * 2 + 0];
        float ss = sred[((2 * hp) * 128 + lr) * 2 + 1] +
                   sred[((2 * hp + 1) * 128 + lr) * 2 + 1];
        int grow = m0 + lr;
        int tensor = grow >> 12;
        int b = (grow >> 10) & 3, m = grow & 1023;
        int h = (n0 >> 6) + hp;
        int idx = tensor * 32768 + (h * 4 + b) * 1024 + m;
        g_hmu[idx]   = s * (1.f / 64.f);
        g_hinvn[idx] = rsqrtf(ss);
        g_hvar[idx]  = (ss - s * s * (1.f / 64.f)) * (1.f / 63.f);
    }
}

// ---------------- 2b) GEMM2: CTA tile 64x128 ----------------
#define A64_B (64 * RS * 2)
#define BUF64 (2 * A64_B + 2 * TILE_B)
#define GEMM64_SMEM (2 * BUF64)

__global__ void __launch_bounds__(256, 2) gemm_bf3_m64(
    const __nv_bfloat16* __restrict__ Ahi, const __nv_bfloat16* __restrict__ Alo,
    const __nv_bfloat16* __restrict__ Bhi, const __nv_bfloat16* __restrict__ Blo,
    float* __restrict__ C, const float* __restrict__ bias)
{
    extern __shared__ char smem[];
    uint32_t sb = smem_u32(smem);
    int t = threadIdx.x, wid = t >> 5, lane = t & 31;
    int n0 = blockIdx.x * 128, m0 = blockIdx.y * 64;
    int wm = wid >> 2, wn = wid & 3;

    float acc[2][4][4];
#pragma unroll
    for (int i = 0; i < 2; i++)
#pragma unroll
        for (int j = 0; j < 4; j++)
#pragma unroll
            for (int r = 0; r < 4; r++) acc[i][j][r] = 0.f;

    auto issue = [&](int c, int buf) {
        int k0 = c * 32;
        uint32_t d0 = sb + buf * BUF64;
        {
            int row = t >> 2, seg = t & 3;
            uint32_t doff = (row * RS + seg * 8) * 2;
            size_t ga = (size_t)(m0 + row) * DD + k0 + seg * 8;
            cp16(d0 + doff,         Ahi + ga);
            cp16(d0 + A64_B + doff, Alo + ga);
        }
#pragma unroll
        for (int i = 0; i < 2; i++) {
            int u = t + i * 256;
            int row = u >> 2, seg = u & 3;
            uint32_t doff = (row * RS + seg * 8) * 2;
            size_t gb = (size_t)(n0 + row) * DD + k0 + seg * 8;
            cp16(d0 + 2 * A64_B + doff,          Bhi + gb);
            cp16(d0 + 2 * A64_B + TILE_B + doff, Blo + gb);
        }
        cp_commit();
    };

    issue(0, 0);
    int g = lane >> 3, rl = lane & 7;

    for (int c = 0; c < 16; c++) {
        int buf = c & 1;
        if (c < 15) issue(c + 1, buf ^ 1);
        if (c < 15) asm volatile("cp.async.wait_group 1;");
        else        asm volatile("cp.async.wait_group 0;");
        __syncthreads();

        uint32_t aBase = sb + buf * BUF64;
        uint32_t bBase = aBase + 2 * A64_B;
#pragma unroll
        for (int h = 0; h < 2; h++) {
            uint32_t aH[2][4], aL[2][4];
#pragma unroll
            for (int it = 0; it < 2; it++) {
                int row = wm * 32 + it * 16 + rl + (g & 1) * 8;
                int kc  = h * 16 + (g & 2) * 4;
                uint32_t ad = aBase + (row * RS + kc) * 2;
                ldsm4(aH[it][0], aH[it][1], aH[it][2], aH[it][3], ad);
                ldsm4(aL[it][0], aL[it][1], aL[it][2], aL[it][3], ad + A64_B);
            }
            uint32_t bH[4][2], bL[4][2];
#pragma unroll
            for (int jp = 0; jp < 2; jp++) {
                int row = wn * 32 + jp * 16 + rl + (g >> 1) * 8;
                int kc  = h * 16 + (g & 1) * 8;
                uint32_t bd = bBase + (row * RS + kc) * 2;
                ldsm4(bH[2 * jp][0], bH[2 * jp][1], bH[2 * jp + 1][0], bH[2 * jp + 1][1], bd);
                ldsm4(bL[2 * jp][0], bL[2 * jp][1], bL[2 * jp + 1][0], bL[2 * jp + 1][1],
                      bd + TILE_B);
            }
#pragma unroll
            for (int it = 0; it < 2; it++)
#pragma unroll
                for (int jt = 0; jt < 4; jt++) {
                    mma16816(acc[it][jt][0], acc[it][jt][1], acc[it][jt][2], acc[it][jt][3],
                             aH[it][0], aH[it][1], aH[it][2], aH[it][3],
                             bH[jt][0], bH[jt][1]);
                    mma16816(acc[it][jt][0], acc[it][jt][1], acc[it][jt][2], acc[it][jt][3],
                             aH[it][0], aH[it][1], aH[it][2], aH[it][3],
                             bL[jt][0], bL[jt][1]);
                    mma16816(acc[it][jt][0], acc[it][jt][1], acc[it][jt][2], acc[it][jt][3],
                             aL[it][0], aL[it][1], aL[it][2], aL[it][3],
                             bH[jt][0], bH[jt][1]);
                }
        }
        __syncthreads();
    }

    int rr = lane >> 2, cc = 2 * (lane & 3);
#pragma unroll
    for (int it = 0; it < 2; it++) {
        int row = m0 + wm * 32 + it * 16 + rr;
#pragma unroll
        for (int jt = 0; jt < 4; jt++) {
            int col = n0 + wn * 32 + jt * 8 + cc;
            float2 bb = *(const float2*)&bias[col];
            *(float2*)&C[(size_t)row * DD + col] =
                make_float2(acc[it][jt][0] + bb.x, acc[it][jt][1] + bb.y);
            *(float2*)&C[(size_t)(row + 8) * DD + col] =
                make_float2(acc[it][jt][2] + bb.x, acc[it][jt][3] + bb.y);
        }
    }
}

// ---------------- 3) G/H/r partials: 4 splits x 256 rows, cp.async ring ----------------
__global__ void __launch_bounds__(256, 4) macc()
{
    __shared__ float Ks[2][32][64];
    __shared__ float Vs[2][32][64];
    __shared__ float sikn[256], skv[256];
    int t = threadIdx.x;
    int pair  = blockIdx.x >> 2;
    int split = blockIdx.x & 3;
    int h = pair >> 2, b = pair & 3;
    const float* fk = g_f + (size_t)RQ * DD     + (size_t)(b * 1024) * DD + h * 64;
    const float* fv = g_f + (size_t)2 * RQ * DD + (size_t)(b * 1024) * DD + h * 64;
    int tx = t & 15, ty = t >> 4;
    int d0 = ty * 4, e0 = tx * 4;
    float G[4][4] = {}, Hm[4][4] = {}, ra[4] = {};
    int mbase0 = split * 256;
    uint32_t sK = smem_u32(Ks), sV = smem_u32(Vs);

    auto issue = [&](int c) {
        int mbase = mbase0 + c * 32;
        uint32_t bufo = (uint32_t)(c & 1) * (32 * 64 * 4);
#pragma unroll
        for (int i = 0; i < 2; i++) {
            int u = t + i * 256;
            int rr = u >> 4, c4 = (u & 15) * 4;
            uint32_t off = bufo + (rr * 64 + c4) * 4;
            cp16(sK + off, fk + (size_t)(mbase + rr) * DD + c4);
            cp16(sV + off, fv + (size_t)(mbase + rr) * DD + c4);
        }
        cp_commit();
    };

    issue(0);
    {
        int idx = 32768 + pair * 1024 + mbase0 + t;
        sikn[t] = g_hinvn[idx];
        skv[t]  = g_hvar[idx];
    }

    for (int c = 0; c < 8; c++) {
        if (c < 7) issue(c + 1);
        if (c < 7) asm volatile("cp.async.wait_group 1;");
        else       asm volatile("cp.async.wait_group 0;");
        __syncthreads();
        int buf = c & 1;
#pragma unroll 8
        for (int mm = 0; mm < 32; mm++) {
            float ikn = sikn[c * 32 + mm];
            float4 kk4 = *(float4*)&Ks[buf][mm][d0];
            float4 vv4 = *(float4*)&Vs[buf][mm][e0];
            float kk[4] = {kk4.x, kk4.y, kk4.z, kk4.w};
            float vv[4] = {vv4.x, vv4.y, vv4.z, vv4.w};
            float vn[4] = {vv4.x * ikn, vv4.y * ikn, vv4.z * ikn, vv4.w * ikn};
#pragma unroll
            for (int i = 0; i < 4; i++)
#pragma unroll
                for (int j = 0; j < 4; j++) {
                    G[i][j]  += kk[i] * vv[j];
                    Hm[i][j] += kk[i] * vn[j];
                }
        }
        if (ty == 0) {
#pragma unroll 8
            for (int mm = 0; mm < 32; mm++) {
                float kvv = skv[c * 32 + mm];
#pragma unroll
                for (int j = 0; j < 4; j++) ra[j] += kvv * Vs[buf][mm][e0 + j];
            }
        }
        __syncthreads();
    }
    float* mp = g_Mpart + (size_t)blockIdx.x * 8192;
#pragma unroll
    for (int i = 0; i < 4; i++)
#pragma unroll
        for (int j = 0; j < 4; j++) {
            mp[(d0 + i) * 64 + e0 + j]        = G[i][j];
            mp[4096 + (d0 + i) * 64 + e0 + j] = Hm[i][j];
        }
    if (ty == 0)
#pragma unroll
        for (int j = 0; j < 4; j++) g_rpart[blockIdx.x * 64 + e0 + j] = ra[j];
}

// ---------------- 4) apply v5.1: HMMA bf16x3, vectorized conversion ----------------
#define MB_S 72
#define APPLY_SMEM (32768 + 2 * 128 * MB_S * 2 + 4096)

__global__ void __launch_bounds__(256) apply_k(const float* __restrict__ cov_w,
                                               const float* __restrict__ var_w)
{
    extern __shared__ float sm[];
    float* Ms = sm;                                      // 8192 fp32: G | H
    __nv_bfloat16* Mbh = (__nv_bfloat16*)(sm + 8192);    // [128 e'][MB_S]
    __nv_bfloat16* Mbl = Mbh + 128 * MB_S;
    float* sbeta = (float*)(Mbl + 128 * MB_S);           // 128
    float* sgam  = sbeta + 128;                          // 128
    float* smual = sgam + 128;                           // 128
    float* srs   = smual + 128;                          // 64
    float* scs1  = srs + 64;                             // 64
    float* spart = scs1 + 64;                            // 128

    int t = threadIdx.x, wid = t >> 5, lane = t & 31;
    int pair  = blockIdx.x >> 3;
    int ntile = blockIdx.x & 7;
    int h = pair >> 2, b = pair & 3;
    float cw = cov_w[0], vw = var_w[0];
    float w3 = 1.f - cw - vw;
    float alpha = cw * (1.f / 64.f);
    int n0 = ntile * 128;

    // 1) fused reduction of 4 split partials -> Ms
    const float4* mp0 = (const float4*)(g_Mpart + (size_t)(pair * SPLITS) * 8192);
#pragma unroll
    for (int i = 0; i < 8; i++) {
        int fi = t + i * 256;
        float4 a0 = __ldcg(mp0 + fi);
        float4 a1 = __ldcg(mp0 + 2048 + fi);
        float4 a2 = __ldcg(mp0 + 4096 + fi);
        float4 a3 = __ldcg(mp0 + 6144 + fi);
        float4 o;
        o.x = ((a0.x + a1.x) + a2.x) + a3.x;
        o.y = ((a0.y + a1.y) + a2.y) + a3.y;
        o.z = ((a0.z + a1.z) + a2.z) + a3.z;
        o.w = ((a0.w + a1.w) + a2.w) + a3.w;
        ((float4*)Ms)[fi] = o;
    }
    if (t < 128) {
        int idx = pair * 1024 + n0 + t;
        float mu = g_hmu[idx], invn = g_hinvn[idx], var = g_hvar[idx];
        sbeta[t] = w3 * invn;
        sgam[t]  = vw * (1.f / 64.f) * var;
        smual[t] = alpha * mu;
    }
    if (t < 64) {
        float r = 0.f;
#pragma unroll
        for (int sp = 0; sp < SPLITS; sp++)
            r += __ldcg(&g_rpart[(pair * SPLITS + sp) * 64 + t]);
        srs[t] = r;
    }
    __syncthreads();

    // 2) convert Ms -> Mb transposed (conflict-free col reads, 16B stores) + scs1
    {
        int ep  = t & 127;           // 0..127: G cols 0-63, H cols 64-127
        int dd0 = (t >> 7) * 32;     // d-half
        int e = ep & 63, half = ep >> 6;
        const float* msrc = Ms + half * 4096 + e;
        __nv_bfloat16 hbuf[32], lbuf[32];
        float s = 0.f;
#pragma unroll
        for (int d = 0; d < 32; d++) {
            float vv = msrc[(dd0 + d) * 64];
            __nv_bfloat16 hh = __float2bfloat16_rn(vv);
            hbuf[d] = hh;
            lbuf[d] = __float2bfloat16_rn(vv - __bfloat162float(hh));
            s += vv;
        }
#pragma unroll
        for (int i = 0; i < 4; i++) {
            *(uint4*)&Mbh[ep * MB_S + dd0 + i * 8] = *(uint4*)&hbuf[i * 8];
            *(uint4*)&Mbl[ep * MB_S + dd0 + i * 8] = *(uint4*)&lbuf[i * 8];
        }
        if (half == 0) spart[(t >> 7) * 64 + e] = s;
    }
    __syncthreads();
    if (t < 64) scs1[t] = spart[t] + spart[64 + t];

    // 3) A-fragment preload from gmem fp32 (warp owns 16 rows)
    int r = lane >> 2, c0b = (lane & 3) * 2;
    const float* qrow0 = g_f + (size_t)(b * 1024 + n0 + wid * 16 + r) * DD + h * 64;
    const float* qrow8 = qrow0 + 8 * DD;
    uint32_t aH[4][4], aL[4][4];
#pragma unroll
    for (int ch = 0; ch < 4; ch++) {
        int c0 = c0b + ch * 16;
#pragma unroll
        for (int p = 0; p < 4; p++) {
            const float* src = ((p & 1) ? qrow8 : qrow0) + c0 + (p >> 1) * 8;
            float2 v = *(const float2*)src;
            aH[ch][p] = pack_hi2(v.x, v.y);
            aL[ch][p] = pack_lo2(v.x, v.y, aH[ch][p]);
        }
    }

    // 4) mainloop: warp tile 16 rows x 128 cols, K=64
    float acc[16][4];
#pragma unroll
    for (int j = 0; j < 16; j++)
#pragma unroll
        for (int x = 0; x < 4; x++) acc[j][x] = 0.f;

    int g = lane >> 3, rl = lane & 7;
    uint32_t mbh = smem_u32(Mbh), mbl = smem_u32(Mbl);
#pragma unroll
    for (int ch = 0; ch < 4; ch++) {
        int kc = ch * 16 + (g & 1) * 8;
#pragma unroll
        for (int jp = 0; jp < 8; jp++) {
            int brow = jp * 16 + rl + (g >> 1) * 8;
            uint32_t boff = (brow * MB_S + kc) * 2;
            uint32_t bH[2][2], bL[2][2];
            ldsm4(bH[0][0], bH[0][1], bH[1][0], bH[1][1], mbh + boff);
            ldsm4(bL[0][0], bL[0][1], bL[1][0], bL[1][1], mbl + boff);
#pragma unroll
            for (int j2 = 0; j2 < 2; j2++) {
                int jt = jp * 2 + j2;
                mma16816(acc[jt][0], acc[jt][1], acc[jt][2], acc[jt][3],
                         aH[ch][0], aH[ch][1], aH[ch][2], aH[ch][3],
                         bH[j2][0], bH[j2][1]);
                mma16816(acc[jt][0], acc[jt][1], acc[jt][2], acc[jt][3],
                         aH[ch][0], aH[ch][1], aH[ch][2], aH[ch][3],
                         bL[j2][0], bL[j2][1]);
                mma16816(acc[jt][0], acc[jt][1], acc[jt][2], acc[jt][3],
                         aL[ch][0], aL[ch][1], aL[ch][2], aL[ch][3],
                         bH[j2][0], bH[j2][1]);
            }
        }
    }
    __syncthreads();   // scs1 visibility

    // 5) epilogue: combine T1 (jt 0-7) and T2 (jt 8-15), emit bf16 hi/lo
#pragma unroll
    for (int jt = 0; jt < 8; jt++) {
        int e0v = jt * 8 + c0b;
        float cs0 = scs1[e0v], cs1v = scs1[e0v + 1];
        float rr0 = srs[e0v],  rr1 = srs[e0v + 1];
#pragma unroll
        for (int rr2 = 0; rr2 < 2; rr2++) {
            int lrow = wid * 16 + r + rr2 * 8;
            float T1a = acc[jt][rr2 * 2],     T1b = acc[jt][rr2 * 2 + 1];
            float T2a = acc[jt + 8][rr2 * 2], T2b = acc[jt + 8][rr2 * 2 + 1];
            float beta = sbeta[lrow], gamma = sgam[lrow], mal = smual[lrow];
            float o0 = alpha * T1a - mal * cs0 + beta * T2a + gamma * rr0;
            float o1 = alpha * T1b - mal * cs1v + beta * T2b + gamma * rr1;
            uint32_t hv = pack_hi2(o0, o1);
            uint32_t lv = pack_lo2(o0, o1, hv);
            size_t off = (size_t)(b * 1024 + n0 + lrow) * DD + h * 64 + e0v;
            *(uint32_t*)&g_ghi[off] = hv;
            *(uint32_t*)&g_glo[off] = lv;
        }
    }
}

// ---------------- launch ----------------
extern "C" void kernel_launch(void* const* d_in, const int* in_sizes, int n_in,
                              void* d_out, int out_size)
{
    const float* q     = (const float*)d_in[0];
    const float* k     = (const float*)d_in[1];
    const float* v     = (const float*)d_in[2];
    const float* ln_g  = (const float*)d_in[3];
    const float* ln_b  = (const float*)d_in[4];
    const float* W_in  = (const float*)d_in[5];
    const float* W_out = (const float*)d_in[6];
    const float* b_out = (const float*)d_in[7];
    const float* cov_w = (const float*)d_in[8];
    const float* var_w = (const float*)d_in[9];
    float* out = (float*)d_out;

    cudaFuncSetAttribute(gemm_bf3, cudaFuncAttributeMaxDynamicSharedMemorySize, GEMM_SMEM);
    cudaFuncSetAttribute(gemm_bf3_m64, cudaFuncAttributeMaxDynamicSharedMemorySize, GEMM64_SMEM);
    cudaFuncSetAttribute(apply_k, cudaFuncAttributeMaxDynamicSharedMemorySize, APPLY_SMEM);

    __nv_bfloat16 *Ahi, *Alo, *Bhi, *Blo, *ghi, *glo;
    float* f;
    cudaGetSymbolAddress((void**)&Ahi, g_Ahi);
    cudaGetSymbolAddress((void**)&Alo, g_Alo);
    cudaGetSymbolAddress((void**)&Bhi, g_Bhi);
    cudaGetSymbolAddress((void**)&Blo, g_Blo);
    cudaGetSymbolAddress((void**)&ghi, g_ghi);
    cudaGetSymbolAddress((void**)&glo, g_glo);
    cudaGetSymbolAddress((void**)&f,   g_f);

    prep<<<1536 + 512, 256>>>(q, k, v, ln_g, ln_b, W_in, W_out);
    gemm_bf3<<<dim3(4, 96), 256, GEMM_SMEM>>>(Ahi, Alo, Bhi, Blo, f);
    macc<<<NPAIR * SPLITS, 256>>>();
    apply_k<<<NPAIR * 8, 256, APPLY_SMEM>>>(cov_w, var_w);
    gemm_bf3_m64<<<dim3(4, 64), 256, GEMM64_SMEM>>>(ghi, glo, Bhi + DD * DD, Blo + DD * DD,
                                                    out, b_out);
}